// round 3
// baseline (speedup 1.0000x reference)
#include <cuda_runtime.h>
#include <cuda_fp16.h>
#include <cstdint>

#define DINL __device__ __forceinline__

// ---------------- problem sizes ----------------
static constexpr int M_TOTAL = 8 * 4096;   // 32768 rows
static constexpr int NK      = 1024;       // N (output cols) == K (window)
static constexpr int BM = 128;
static constexpr int BN = 128;
static constexpr int BK = 64;              // halfs per chunk (128B rows)
static constexpr int NCHUNK = NK / BK;     // 16
static constexpr int STAGES = 3;
static constexpr int THREADS = 256;

// ---------------- smem layout ----------------
static constexpr uint32_t OFF_AR = 0;                 // xr tile 128x128B
static constexpr uint32_t OFF_AI = 16384;             // xi tile
static constexpr uint32_t OFF_BR = 32768;             // wr tile
static constexpr uint32_t OFF_BI = 49152;             // wi tile
static constexpr uint32_t STAGE  = 65536;             // 64KB per stage
static constexpr uint32_t SM_BIAS = STAGES * STAGE;   // 196608
static constexpr uint32_t SMEM_TOTAL = SM_BIAS + 1024;

// ---------------- fp16 scratch (device globals) ----------------
__device__ __align__(128) __half g_xr_h[33554432];
__device__ __align__(128) __half g_xi_h[33554432];
__device__ __align__(128) __half g_wr_h[1048576];
__device__ __align__(128) __half g_wi_h[1048576];

// ---------------- PTX helpers ----------------
DINL uint32_t swz(uint32_t o) { return o ^ ((o >> 3) & 0x70); }   // SW128

DINL void cp16(uint32_t dst, const void* src) {
    asm volatile("cp.async.cg.shared.global [%0], [%1], 16;\n" :: "r"(dst), "l"(src));
}
DINL void cp_commit() { asm volatile("cp.async.commit_group;\n" ::: "memory"); }
template <int N> DINL void cp_wait() {
    asm volatile("cp.async.wait_group %0;\n" :: "n"(N) : "memory");
}

DINL void ldsm4(uint32_t* r, uint32_t a) {
    asm volatile("ldmatrix.sync.aligned.m8n8.x4.shared.b16 {%0,%1,%2,%3}, [%4];\n"
                 : "=r"(r[0]), "=r"(r[1]), "=r"(r[2]), "=r"(r[3]) : "r"(a));
}

DINL void mma16816(float* d, const uint32_t* a, uint32_t b0, uint32_t b1) {
    asm volatile(
        "mma.sync.aligned.m16n8k16.row.col.f32.f16.f16.f32 "
        "{%0,%1,%2,%3}, {%4,%5,%6,%7}, {%8,%9}, {%0,%1,%2,%3};\n"
        : "+f"(d[0]), "+f"(d[1]), "+f"(d[2]), "+f"(d[3])
        : "r"(a[0]), "r"(a[1]), "r"(a[2]), "r"(a[3]), "r"(b0), "r"(b1));
}

// ---------------- conversion kernels ----------------
DINL uint4 pack8(float4 a, float4 b) {
    __half2 h0 = __float22half2_rn(make_float2(a.x, a.y));
    __half2 h1 = __float22half2_rn(make_float2(a.z, a.w));
    __half2 h2 = __float22half2_rn(make_float2(b.x, b.y));
    __half2 h3 = __float22half2_rn(make_float2(b.z, b.w));
    uint4 u;
    u.x = *(uint32_t*)&h0; u.y = *(uint32_t*)&h1;
    u.z = *(uint32_t*)&h2; u.w = *(uint32_t*)&h3;
    return u;
}

__global__ void __launch_bounds__(256) convert_x_kernel(const float4* __restrict__ xr,
                                                        const float4* __restrict__ xi) {
    size_t t = (size_t)blockIdx.x * 256 + threadIdx.x;   // 8 floats each
    float4 a = xr[2 * t], b = xr[2 * t + 1];
    *(uint4*)(g_xr_h + t * 8) = pack8(a, b);
    float4 c = xi[2 * t], d = xi[2 * t + 1];
    *(uint4*)(g_xi_h + t * 8) = pack8(c, d);
}

__global__ void __launch_bounds__(256) convert_w_kernel(const float4* __restrict__ wr,
                                                        const float4* __restrict__ wi) {
    size_t t = (size_t)blockIdx.x * 256 + threadIdx.x;
    float4 a = wr[2 * t], b = wr[2 * t + 1];
    *(uint4*)(g_wr_h + t * 8) = pack8(a, b);
    float4 c = wi[2 * t], d = wi[2 * t + 1];
    *(uint4*)(g_wi_h + t * 8) = pack8(c, d);
}

// ---------------- chunk loader: 16 cp.async of 16B per thread ----------------
DINL void load_chunk(uint32_t st, int m0, int n0, int kc, int tid) {
    const int c0 = kc * BK;
#pragma unroll
    for (int it = 0; it < 4; ++it) {
        int u = tid + it * 256;                 // 0..1023
        int r = u >> 3, c = u & 7;
        uint32_t so = swz((uint32_t)((r << 7) + (c << 4)));
        size_t acol = (size_t)c0 + (c << 3);
        cp16(st + OFF_AR + so, g_xr_h + (((size_t)(m0 + r)) << 10) + acol);
        cp16(st + OFF_AI + so, g_xi_h + (((size_t)(m0 + r)) << 10) + acol);
        size_t go = (((size_t)(n0 + r)) << 10) + acol;
        cp16(st + OFF_BR + so, g_wr_h + go);
        cp16(st + OFF_BI + so, g_wi_h + go);
    }
}

// ---------------- main GEMM kernel ----------------
__global__ void __launch_bounds__(THREADS, 1)
dft_gemm_kernel(const float* __restrict__ b_real, const float* __restrict__ b_imag,
                float* __restrict__ out_real, float* __restrict__ out_imag) {
    extern __shared__ __align__(1024) char sm[];
    uint32_t sb = (uint32_t)__cvta_generic_to_shared(sm);
    const int tid = threadIdx.x, wid = tid >> 5, lid = tid & 31;
    const int n0 = blockIdx.x * BN;
    const int m0 = blockIdx.y * BM;
    const int wm = (wid >> 2) * 64;            // warp m offset (0 / 64)
    const int wn = (wid & 3) * 32;             // warp n offset

    // bias staging: bm = br - bi (real), bp = br + bi (imag)
    if (tid < 128) {
        float a = b_real[n0 + tid], b = b_imag[n0 + tid];
        ((float*)(sm + SM_BIAS))[tid]       = a - b;
        ((float*)(sm + SM_BIAS + 512))[tid] = a + b;
    }

    // pipeline prologue: chunks 0,1
    load_chunk(sb + 0 * STAGE, m0, n0, 0, tid); cp_commit();
    load_chunk(sb + 1 * STAGE, m0, n0, 1, tid); cp_commit();

    float accR[4][4][4], accI[4][4][4];
#pragma unroll
    for (int a = 0; a < 4; ++a)
#pragma unroll
        for (int b = 0; b < 4; ++b)
#pragma unroll
            for (int c = 0; c < 4; ++c) { accR[a][b][c] = 0.f; accI[a][b][c] = 0.f; }

    const int lrow = lid & 15;                 // ldmatrix row-within-16
    const int lcb  = (lid >> 4) << 4;          // ldmatrix 16B col select

    for (int i = 0; i < NCHUNK; ++i) {
        cp_wait<STAGES - 2>();                 // chunk i resident
        __syncthreads();
        if (i + 2 < NCHUNK)
            load_chunk(sb + ((i + 2) % STAGES) * STAGE, m0, n0, i + 2, tid);
        cp_commit();

        const uint32_t st = sb + (i % STAGES) * STAGE;
#pragma unroll
        for (int kk = 0; kk < 4; ++kk) {
            const uint32_t colb = (uint32_t)(kk * 32 + lcb);
            uint32_t Axr[4][4], Axi[4][4];
#pragma unroll
            for (int mt = 0; mt < 4; ++mt) {
                uint32_t ro = (uint32_t)((wm + mt * 16 + lrow) << 7) + colb;
                ldsm4(Axr[mt], st + OFF_AR + swz(ro));
                ldsm4(Axi[mt], st + OFF_AI + swz(ro));
            }
            // B regs from ldmatrix.x4: {n0-7/k0-7, n8-15/k0-7, n0-7/k8-15, n8-15/k8-15}
            // Permute 1<->2 so pairs for a given n-octet are contiguous:
            //   [0]={n0-7,k0-7} [1]={n0-7,k8-15} [2]={n8-15,k0-7} [3]={n8-15,k8-15}
            uint32_t Bwr[2][4], Bwi[2][4], Bwn[2][4];
#pragma unroll
            for (int bt = 0; bt < 2; ++bt) {
                uint32_t t4[4];
                uint32_t ro = (uint32_t)((wn + bt * 16 + lrow) << 7) + colb;
                ldsm4(t4, st + OFF_BR + swz(ro));
                Bwr[bt][0] = t4[0]; Bwr[bt][1] = t4[2]; Bwr[bt][2] = t4[1]; Bwr[bt][3] = t4[3];
                ldsm4(t4, st + OFF_BI + swz(ro));
                Bwi[bt][0] = t4[0]; Bwi[bt][1] = t4[2]; Bwi[bt][2] = t4[1]; Bwi[bt][3] = t4[3];
#pragma unroll
                for (int j = 0; j < 4; ++j) Bwn[bt][j] = Bwi[bt][j] ^ 0x80008000u;
            }
#pragma unroll
            for (int mt = 0; mt < 4; ++mt)
#pragma unroll
                for (int nt = 0; nt < 4; ++nt) {
                    const int hb = nt >> 1, ob = (nt & 1) * 2;
                    mma16816(accR[mt][nt], Axr[mt], Bwr[hb][ob], Bwr[hb][ob + 1]); // xr*wr
                    mma16816(accR[mt][nt], Axi[mt], Bwn[hb][ob], Bwn[hb][ob + 1]); // xi*(-wi)
                    mma16816(accI[mt][nt], Axr[mt], Bwi[hb][ob], Bwi[hb][ob + 1]); // xr*wi
                    mma16816(accI[mt][nt], Axi[mt], Bwr[hb][ob], Bwr[hb][ob + 1]); // xi*wr
                }
        }
    }

    // epilogue: fused bias, direct float2 stores
    const float* bm = (const float*)(sm + SM_BIAS);
    const float* bp = (const float*)(sm + SM_BIAS + 512);
    const int gr = lid >> 2, gc = (lid & 3) * 2;
#pragma unroll
    for (int mt = 0; mt < 4; ++mt) {
        size_t row = (size_t)(m0 + wm + mt * 16 + gr);
#pragma unroll
        for (int nt = 0; nt < 4; ++nt) {
            int col = wn + nt * 8 + gc;
            float bm0 = bm[col], bm1 = bm[col + 1];
            float bp0 = bp[col], bp1 = bp[col + 1];
            float* pr0 = out_real + (row << 10) + n0 + col;
            float* pi0 = out_imag + (row << 10) + n0 + col;
            float2 v;
            v.x = accR[mt][nt][0] + bm0; v.y = accR[mt][nt][1] + bm1;
            *(float2*)pr0 = v;
            v.x = accR[mt][nt][2] + bm0; v.y = accR[mt][nt][3] + bm1;
            *(float2*)(pr0 + (8 << 10)) = v;
            v.x = accI[mt][nt][0] + bp0; v.y = accI[mt][nt][1] + bp1;
            *(float2*)pi0 = v;
            v.x = accI[mt][nt][2] + bp0; v.y = accI[mt][nt][3] + bp1;
            *(float2*)(pi0 + (8 << 10)) = v;
        }
    }
}

// ---------------- launch ----------------
extern "C" void kernel_launch(void* const* d_in, const int* in_sizes, int n_in,
                              void* d_out, int out_size) {
    (void)in_sizes; (void)n_in; (void)out_size;
    const float4* xr = (const float4*)d_in[0];
    const float4* xi = (const float4*)d_in[1];
    const float4* wr = (const float4*)d_in[2];
    const float4* wi = (const float4*)d_in[3];
    const float*  br = (const float*)d_in[4];
    const float*  bi = (const float*)d_in[5];
    float* out_real = (float*)d_out;
    float* out_imag = out_real + (size_t)M_TOTAL * NK;   // real first, then imag

    convert_x_kernel<<<16384, 256>>>(xr, xi);
    convert_w_kernel<<<512, 256>>>(wr, wi);

    cudaFuncSetAttribute(dft_gemm_kernel,
                         cudaFuncAttributeMaxDynamicSharedMemorySize, SMEM_TOTAL);
    dim3 grid(NK / BN, M_TOTAL / BM);   // (8, 256)
    dft_gemm_kernel<<<grid, THREADS, SMEM_TOTAL>>>(br, bi, out_real, out_imag);
}

// round 4
// speedup vs baseline: 1.4424x; 1.4424x over previous
#include <cuda_runtime.h>
#include <cuda_fp16.h>
#include <cstdint>

#define DINL __device__ __forceinline__

// ---------------- problem sizes ----------------
static constexpr int M_TOTAL = 8 * 4096;   // 32768 rows
static constexpr int NK      = 1024;       // window == full output cols
static constexpr int BM = 128;             // rows per CTA
static constexpr int BN = 64;              // direct k-cols per CTA (k in [0,512))
static constexpr int BK = 64;              // halfs per chunk
static constexpr int NCHUNK = NK / BK;     // 16
static constexpr int STAGES = 4;
static constexpr int THREADS = 256;

// ---------------- smem layout ----------------
static constexpr uint32_t OFF_AR = 0;                  // xr tile 128x128B = 16KB
static constexpr uint32_t OFF_AI = 16384;              // xi tile
static constexpr uint32_t OFF_BR = 32768;              // wr tile 64x128B = 8KB
static constexpr uint32_t OFF_BI = 40960;              // wi tile
static constexpr uint32_t STAGE  = 49152;              // 48KB per stage
static constexpr uint32_t SM_BIAS = STAGES * STAGE;    // 196608
static constexpr uint32_t SMEM_TOTAL = SM_BIAS + 1024;

// ---------------- fp16 scratch ----------------
__device__ __align__(128) __half g_xr_h[33554432];
__device__ __align__(128) __half g_xi_h[33554432];
__device__ __align__(128) __half g_wr_h[1048576];
__device__ __align__(128) __half g_wi_h[1048576];

// ---------------- PTX helpers ----------------
DINL uint32_t swz(uint32_t o) { return o ^ ((o >> 3) & 0x70); }

DINL void cp16(uint32_t dst, const void* src) {
    asm volatile("cp.async.cg.shared.global [%0], [%1], 16;\n" :: "r"(dst), "l"(src));
}
DINL void cp_commit() { asm volatile("cp.async.commit_group;\n" ::: "memory"); }
template <int N> DINL void cp_wait() {
    asm volatile("cp.async.wait_group %0;\n" :: "n"(N) : "memory");
}

DINL void ldsm4(uint32_t* r, uint32_t a) {
    asm volatile("ldmatrix.sync.aligned.m8n8.x4.shared.b16 {%0,%1,%2,%3}, [%4];\n"
                 : "=r"(r[0]), "=r"(r[1]), "=r"(r[2]), "=r"(r[3]) : "r"(a));
}

DINL void mma16816(float* d, const uint32_t* a, uint32_t b0, uint32_t b1) {
    asm volatile(
        "mma.sync.aligned.m16n8k16.row.col.f32.f16.f16.f32 "
        "{%0,%1,%2,%3}, {%4,%5,%6,%7}, {%8,%9}, {%0,%1,%2,%3};\n"
        : "+f"(d[0]), "+f"(d[1]), "+f"(d[2]), "+f"(d[3])
        : "r"(a[0]), "r"(a[1]), "r"(a[2]), "r"(a[3]), "r"(b0), "r"(b1));
}

// ---------------- conversion kernels ----------------
DINL uint4 pack8(float4 a, float4 b) {
    __half2 h0 = __float22half2_rn(make_float2(a.x, a.y));
    __half2 h1 = __float22half2_rn(make_float2(a.z, a.w));
    __half2 h2 = __float22half2_rn(make_float2(b.x, b.y));
    __half2 h3 = __float22half2_rn(make_float2(b.z, b.w));
    uint4 u;
    u.x = *(uint32_t*)&h0; u.y = *(uint32_t*)&h1;
    u.z = *(uint32_t*)&h2; u.w = *(uint32_t*)&h3;
    return u;
}

__global__ void __launch_bounds__(256) convert_x_kernel(const float4* __restrict__ xr,
                                                        const float4* __restrict__ xi) {
    size_t t = (size_t)blockIdx.x * 256 + threadIdx.x;
    float4 a = xr[2 * t], b = xr[2 * t + 1];
    *(uint4*)(g_xr_h + t * 8) = pack8(a, b);
    float4 c = xi[2 * t], d = xi[2 * t + 1];
    *(uint4*)(g_xi_h + t * 8) = pack8(c, d);
}

__global__ void __launch_bounds__(256) convert_w_kernel(const float4* __restrict__ wr,
                                                        const float4* __restrict__ wi) {
    size_t t = (size_t)blockIdx.x * 256 + threadIdx.x;
    float4 a = wr[2 * t], b = wr[2 * t + 1];
    *(uint4*)(g_wr_h + t * 8) = pack8(a, b);
    float4 c = wi[2 * t], d = wi[2 * t + 1];
    *(uint4*)(g_wi_h + t * 8) = pack8(c, d);
}

// ---------------- column 512: w = (-1)^n, wi = 0 ----------------
__global__ void __launch_bounds__(256) col512_kernel(const float* __restrict__ b_real,
                                                     const float* __restrict__ b_imag,
                                                     float* __restrict__ out_real,
                                                     float* __restrict__ out_imag) {
    int row = blockIdx.x * 8 + (threadIdx.x >> 5);     // one warp per row
    int lane = threadIdx.x & 31;
    const uint4* pr = (const uint4*)(g_xr_h + ((size_t)row << 10));
    const uint4* pi = (const uint4*)(g_xi_h + ((size_t)row << 10));
    float sr = 0.f, si = 0.f;
#pragma unroll
    for (int t = 0; t < 4; ++t) {
        uint4 v = pr[lane + 32 * t];                   // 8 halfs, starts at n % 8 == 0
        const __half2* h = (const __half2*)&v;
#pragma unroll
        for (int j = 0; j < 4; ++j) { float2 f = __half22float2(h[j]); sr += f.x - f.y; }
        uint4 w = pi[lane + 32 * t];
        const __half2* g = (const __half2*)&w;
#pragma unroll
        for (int j = 0; j < 4; ++j) { float2 f = __half22float2(g[j]); si += f.x - f.y; }
    }
#pragma unroll
    for (int s = 16; s > 0; s >>= 1) {
        sr += __shfl_xor_sync(0xFFFFFFFFu, sr, s);
        si += __shfl_xor_sync(0xFFFFFFFFu, si, s);
    }
    if (lane == 0) {
        float br = b_real[512], bi = b_imag[512];
        out_real[((size_t)row << 10) + 512] = sr + (br - bi);
        out_imag[((size_t)row << 10) + 512] = si + (br + bi);
    }
}

// ---------------- chunk loader: 12 cp.async of 16B per thread ----------------
DINL void load_chunk(uint32_t st, int m0, int n0, int kc, int tid) {
    const int c0 = kc * BK;
#pragma unroll
    for (int it = 0; it < 4; ++it) {                   // A: 128 rows x 8 x 16B
        int u = tid + it * 256;
        int r = u >> 3, c = u & 7;
        uint32_t so = swz((uint32_t)((r << 7) + (c << 4)));
        size_t acol = (size_t)c0 + (c << 3);
        cp16(st + OFF_AR + so, g_xr_h + (((size_t)(m0 + r)) << 10) + acol);
        cp16(st + OFF_AI + so, g_xi_h + (((size_t)(m0 + r)) << 10) + acol);
    }
#pragma unroll
    for (int it = 0; it < 2; ++it) {                   // B: 64 rows x 8 x 16B
        int u = tid + it * 256;
        int r = u >> 3, c = u & 7;
        uint32_t so = swz((uint32_t)((r << 7) + (c << 4)));
        size_t go = (((size_t)(n0 + r)) << 10) + c0 + (c << 3);
        cp16(st + OFF_BR + so, g_wr_h + go);
        cp16(st + OFF_BI + so, g_wi_h + go);
    }
}

// ---------------- main GEMM kernel (symmetric: k and 1024-k per tile) ----------
__global__ void __launch_bounds__(THREADS, 1)
dft_gemm_kernel(const float* __restrict__ b_real, const float* __restrict__ b_imag,
                float* __restrict__ out_real, float* __restrict__ out_imag) {
    extern __shared__ __align__(1024) char sm[];
    uint32_t sb = (uint32_t)__cvta_generic_to_shared(sm);
    const int tid = threadIdx.x, wid = tid >> 5, lid = tid & 31;
    const int n0 = blockIdx.x * BN;                    // k-tile base, in [0, 512)
    const int m0 = blockIdx.y * BM;
    const int wm = (wid >> 2) * 64;                    // 2 m-warps
    const int wn = (wid & 3) * 16;                     // 4 n-warps

    // bias staging: direct (cols n0+j) and mirror (cols (1024-n0-j)%1024)
    float* bmD = (float*)(sm + SM_BIAS);
    float* bpD = bmD + 64;
    float* bmM = bmD + 128;
    float* bpM = bmD + 192;
    if (tid < 64) {
        float a = b_real[n0 + tid], b = b_imag[n0 + tid];
        bmD[tid] = a - b; bpD[tid] = a + b;
        int jm = (1024 - n0 - tid) & 1023;
        float am = b_real[jm], bm2 = b_imag[jm];
        bmM[tid] = am - bm2; bpM[tid] = am + bm2;
    }

    // pipeline prologue: chunks 0..2
    load_chunk(sb + 0 * STAGE, m0, n0, 0, tid); cp_commit();
    load_chunk(sb + 1 * STAGE, m0, n0, 1, tid); cp_commit();
    load_chunk(sb + 2 * STAGE, m0, n0, 2, tid); cp_commit();

    // P1=xr@wr  P2=xi@wi  P3=xr@wi  P4=xi@wr
    float P1[4][2][4], P2[4][2][4], P3[4][2][4], P4[4][2][4];
#pragma unroll
    for (int a = 0; a < 4; ++a)
#pragma unroll
        for (int b = 0; b < 2; ++b)
#pragma unroll
            for (int c = 0; c < 4; ++c) {
                P1[a][b][c] = 0.f; P2[a][b][c] = 0.f;
                P3[a][b][c] = 0.f; P4[a][b][c] = 0.f;
            }

    const int lrow = lid & 15;
    const int lcb  = (lid >> 4) << 4;

    for (int i = 0; i < NCHUNK; ++i) {
        cp_wait<STAGES - 2>();
        __syncthreads();
        if (i + 3 < NCHUNK)
            load_chunk(sb + ((i + 3) & 3) * STAGE, m0, n0, i + 3, tid);
        cp_commit();

        const uint32_t st = sb + (i & 3) * STAGE;
#pragma unroll
        for (int kk = 0; kk < 4; ++kk) {
            const uint32_t colb = (uint32_t)(kk * 32 + lcb);
            uint32_t Axr[4][4], Axi[4][4];
#pragma unroll
            for (int mt = 0; mt < 4; ++mt) {
                uint32_t ro = (uint32_t)((wm + mt * 16 + lrow) << 7) + colb;
                ldsm4(Axr[mt], st + OFF_AR + swz(ro));
                ldsm4(Axi[mt], st + OFF_AI + swz(ro));
            }
            // B regs permuted so n-octet pairs are contiguous:
            // [0]={n0-7,k0-7} [1]={n0-7,k8-15} [2]={n8-15,k0-7} [3]={n8-15,k8-15}
            uint32_t Bwr[4], Bwi[4], t4[4];
            {
                uint32_t ro = (uint32_t)((wn + lrow) << 7) + colb;
                ldsm4(t4, st + OFF_BR + swz(ro));
                Bwr[0] = t4[0]; Bwr[1] = t4[2]; Bwr[2] = t4[1]; Bwr[3] = t4[3];
                ldsm4(t4, st + OFF_BI + swz(ro));
                Bwi[0] = t4[0]; Bwi[1] = t4[2]; Bwi[2] = t4[1]; Bwi[3] = t4[3];
            }
#pragma unroll
            for (int mt = 0; mt < 4; ++mt)
#pragma unroll
                for (int nt = 0; nt < 2; ++nt) {
                    const int ob = nt * 2;
                    mma16816(P1[mt][nt], Axr[mt], Bwr[ob], Bwr[ob + 1]);
                    mma16816(P2[mt][nt], Axi[mt], Bwi[ob], Bwi[ob + 1]);
                    mma16816(P3[mt][nt], Axr[mt], Bwi[ob], Bwi[ob + 1]);
                    mma16816(P4[mt][nt], Axi[mt], Bwr[ob], Bwr[ob + 1]);
                }
        }
    }

    // epilogue: direct cols k = n0+jl (float2), mirror cols 1024-k (scalar)
    const int gr = lid >> 2, gc = (lid & 3) * 2;
#pragma unroll
    for (int mt = 0; mt < 4; ++mt) {
#pragma unroll
        for (int nt = 0; nt < 2; ++nt) {
            const int jl = wn + nt * 8 + gc;           // local col 0..63
            const int c  = n0 + jl;                    // global k (even)
            const int mc = 1024 - c;                   // mirror of c
            float bmD0 = bmD[jl], bmD1 = bmD[jl + 1];
            float bpD0 = bpD[jl], bpD1 = bpD[jl + 1];
            float bmM0 = bmM[jl], bmM1 = bmM[jl + 1];
            float bpM0 = bpM[jl], bpM1 = bpM[jl + 1];
#pragma unroll
            for (int rg = 0; rg < 2; ++rg) {
                const int e0 = rg * 2, e1 = rg * 2 + 1;
                size_t row = (size_t)(m0 + wm + mt * 16 + gr + rg * 8);
                float* pr = out_real + (row << 10);
                float* pi = out_imag + (row << 10);
                float p1a = P1[mt][nt][e0], p1b = P1[mt][nt][e1];
                float p2a = P2[mt][nt][e0], p2b = P2[mt][nt][e1];
                float p3a = P3[mt][nt][e0], p3b = P3[mt][nt][e1];
                float p4a = P4[mt][nt][e0], p4b = P4[mt][nt][e1];
                float2 v;
                v.x = p1a - p2a + bmD0; v.y = p1b - p2b + bmD1;
                *(float2*)(pr + c) = v;                              // real direct
                v.x = p3a + p4a + bpD0; v.y = p3b + p4b + bpD1;
                *(float2*)(pi + c) = v;                              // imag direct
                pr[mc - 1] = p1b + p2b + bmM1;                       // real mirror k+1
                pi[mc - 1] = p4b - p3b + bpM1;                       // imag mirror k+1
                if (c != 0) {
                    pr[mc] = p1a + p2a + bmM0;                       // real mirror k
                    pi[mc] = p4a - p3a + bpM0;                       // imag mirror k
                }
            }
        }
    }
}

// ---------------- launch ----------------
extern "C" void kernel_launch(void* const* d_in, const int* in_sizes, int n_in,
                              void* d_out, int out_size) {
    (void)in_sizes; (void)n_in; (void)out_size;
    const float4* xr = (const float4*)d_in[0];
    const float4* xi = (const float4*)d_in[1];
    const float4* wr = (const float4*)d_in[2];
    const float4* wi = (const float4*)d_in[3];
    const float*  br = (const float*)d_in[4];
    const float*  bi = (const float*)d_in[5];
    float* out_real = (float*)d_out;
    float* out_imag = out_real + (size_t)M_TOTAL * NK;

    convert_x_kernel<<<16384, 256>>>(xr, xi);
    convert_w_kernel<<<512, 256>>>(wr, wi);
    col512_kernel<<<4096, 256>>>(br, bi, out_real, out_imag);

    cudaFuncSetAttribute(dft_gemm_kernel,
                         cudaFuncAttributeMaxDynamicSharedMemorySize, SMEM_TOTAL);
    dim3 grid(512 / BN, M_TOTAL / BM);   // (8, 256): k-tiles 0..511
    dft_gemm_kernel<<<grid, THREADS, SMEM_TOTAL>>>(br, bi, out_real, out_imag);
}

// round 5
// speedup vs baseline: 2.1113x; 1.4637x over previous
#include <cuda_runtime.h>
#include <cuda_fp16.h>
#include <cstdint>

#define DINL __device__ __forceinline__

// ---------------- problem sizes ----------------
static constexpr int M_SIG  = 32768;       // independent signals (8*4096)
static constexpr int MR     = 65536;       // scratch rows: even/odd interleaved
static constexpr int KH     = 512;         // GEMM K (half window)
static constexpr int BM = 128;             // scratch rows per CTA (64 signals)
static constexpr int BN = 64;              // direct W512 cols per CTA (of 256)
static constexpr int BK = 64;              // halfs per chunk (128B rows)
static constexpr int NCHUNK = KH / BK;     // 8
static constexpr int STAGES = 4;
static constexpr int THREADS = 256;

// ---------------- smem layout ----------------
static constexpr uint32_t OFF_AR = 0;                 // xr tile 128x128B = 16KB
static constexpr uint32_t OFF_AI = 16384;
static constexpr uint32_t OFF_BR = 32768;             // wr tile 64x128B = 8KB
static constexpr uint32_t OFF_BI = 40960;
static constexpr uint32_t STAGE  = 49152;             // 48KB
static constexpr uint32_t SM_TAB = STAGES * STAGE;    // 196608: bias+twiddle tables
static constexpr uint32_t SMEM_TOTAL = SM_TAB + 3072;

// ---------------- fp16 scratch ----------------
// row 2s = even samples of signal s (512 halfs), row 2s+1 = odd samples
__device__ __align__(128) __half g_xr_h[33554432];
__device__ __align__(128) __half g_xi_h[33554432];
// W512 rows 0..255 (k-major, 512 halfs per row): W512[k][t] = w1024[2k][t]
__device__ __align__(128) __half g_wr_h[131072];
__device__ __align__(128) __half g_wi_h[131072];

// ---------------- PTX helpers ----------------
DINL uint32_t swz(uint32_t o) { return o ^ ((o >> 3) & 0x70); }

DINL void cp16(uint32_t dst, const void* src) {
    asm volatile("cp.async.cg.shared.global [%0], [%1], 16;\n" :: "r"(dst), "l"(src));
}
DINL void cp_commit() { asm volatile("cp.async.commit_group;\n" ::: "memory"); }
template <int N> DINL void cp_wait() {
    asm volatile("cp.async.wait_group %0;\n" :: "n"(N) : "memory");
}

DINL void ldsm4(uint32_t* r, uint32_t a) {
    asm volatile("ldmatrix.sync.aligned.m8n8.x4.shared.b16 {%0,%1,%2,%3}, [%4];\n"
                 : "=r"(r[0]), "=r"(r[1]), "=r"(r[2]), "=r"(r[3]) : "r"(a));
}

DINL void mma16816(float* d, const uint32_t* a, uint32_t b0, uint32_t b1) {
    asm volatile(
        "mma.sync.aligned.m16n8k16.row.col.f32.f16.f16.f32 "
        "{%0,%1,%2,%3}, {%4,%5,%6,%7}, {%8,%9}, {%0,%1,%2,%3};\n"
        : "+f"(d[0]), "+f"(d[1]), "+f"(d[2]), "+f"(d[3])
        : "r"(a[0]), "r"(a[1]), "r"(a[2]), "r"(a[3]), "r"(b0), "r"(b1));
}

// ---------------- conversion kernels ----------------
DINL uint32_t h2u(float a, float b) {
    __half2 h = __floats2half2_rn(a, b);
    return *(uint32_t*)&h;
}

DINL uint4 pack8(float4 a, float4 b) {
    uint4 u;
    u.x = h2u(a.x, a.y); u.y = h2u(a.z, a.w);
    u.z = h2u(b.x, b.y); u.w = h2u(b.z, b.w);
    return u;
}

// deinterleave even/odd samples into fp16 scratch rows 2m / 2m+1
__global__ void __launch_bounds__(256) convert_x_kernel(const float4* __restrict__ xr,
                                                        const float4* __restrict__ xi) {
    size_t gid = (size_t)blockIdx.x * 256 + threadIdx.x;   // 2M threads
    size_t m = gid >> 6;                                   // signal
    int j = (int)(gid & 63);                               // 16-sample group
    {
        const float4* p = xr + (m << 8) + (j << 2);
        float4 f0 = p[0], f1 = p[1], f2 = p[2], f3 = p[3];
        uint4 ev, od;
        ev.x = h2u(f0.x, f0.z); ev.y = h2u(f1.x, f1.z);
        ev.z = h2u(f2.x, f2.z); ev.w = h2u(f3.x, f3.z);
        od.x = h2u(f0.y, f0.w); od.y = h2u(f1.y, f1.w);
        od.z = h2u(f2.y, f2.w); od.w = h2u(f3.y, f3.w);
        *(uint4*)(g_xr_h + ((m * 2) << 9) + (j << 3)) = ev;
        *(uint4*)(g_xr_h + ((m * 2 + 1) << 9) + (j << 3)) = od;
    }
    {
        const float4* p = xi + (m << 8) + (j << 2);
        float4 f0 = p[0], f1 = p[1], f2 = p[2], f3 = p[3];
        uint4 ev, od;
        ev.x = h2u(f0.x, f0.z); ev.y = h2u(f1.x, f1.z);
        ev.z = h2u(f2.x, f2.z); ev.w = h2u(f3.x, f3.z);
        od.x = h2u(f0.y, f0.w); od.y = h2u(f1.y, f1.w);
        od.z = h2u(f2.y, f2.w); od.w = h2u(f3.y, f3.w);
        *(uint4*)(g_xi_h + ((m * 2) << 9) + (j << 3)) = ev;
        *(uint4*)(g_xi_h + ((m * 2 + 1) << 9) + (j << 3)) = od;
    }
}

// W512 rows 0..255: copy even rows of w1024, fp32->fp16
__global__ void __launch_bounds__(256) convert_w_kernel(const float4* __restrict__ wr,
                                                        const float4* __restrict__ wi) {
    size_t gid = (size_t)blockIdx.x * 256 + threadIdx.x;   // 16384 threads
    size_t k = gid >> 6;                                   // W512 row
    int j = (int)(gid & 63);
    size_t src = ((k * 2) << 8) + (j << 1);                // float4 idx into row 2k
    float4 a = wr[src], b = wr[src + 1];
    *(uint4*)(g_wr_h + (k << 9) + (j << 3)) = pack8(a, b);
    float4 c = wi[src], d = wi[src + 1];
    *(uint4*)(g_wi_h + (k << 9) + (j << 3)) = pack8(c, d);
}

// ---------------- col 256 / 768: W512[256][t] = (-1)^t, twiddle w^256 = -i ----
DINL float altsum(uint4 v) {
    const __half2* h = (const __half2*)&v;
    float s = 0.f;
#pragma unroll
    for (int j = 0; j < 4; ++j) { float2 f = __half22float2(h[j]); s += f.x - f.y; }
    return s;
}

__global__ void __launch_bounds__(256) col256_kernel(const float* __restrict__ b_real,
                                                     const float* __restrict__ b_imag,
                                                     float* __restrict__ out_real,
                                                     float* __restrict__ out_imag) {
    int s = blockIdx.x * 8 + (threadIdx.x >> 5);           // one warp per signal
    int lane = threadIdx.x & 31;
    const uint4* er = (const uint4*)(g_xr_h + ((size_t)(2 * s) << 9));
    const uint4* od = (const uint4*)(g_xr_h + ((size_t)(2 * s + 1) << 9));
    const uint4* ei = (const uint4*)(g_xi_h + ((size_t)(2 * s) << 9));
    const uint4* oi = (const uint4*)(g_xi_h + ((size_t)(2 * s + 1) << 9));
    float Er = 0.f, Ei = 0.f, Or = 0.f, Oi = 0.f;
#pragma unroll
    for (int t = 0; t < 2; ++t) {
        int idx = lane + 32 * t;
        Er += altsum(er[idx]); Or += altsum(od[idx]);
        Ei += altsum(ei[idx]); Oi += altsum(oi[idx]);
    }
#pragma unroll
    for (int sh = 16; sh > 0; sh >>= 1) {
        Er += __shfl_xor_sync(0xFFFFFFFFu, Er, sh);
        Ei += __shfl_xor_sync(0xFFFFFFFFu, Ei, sh);
        Or += __shfl_xor_sync(0xFFFFFFFFu, Or, sh);
        Oi += __shfl_xor_sync(0xFFFFFFFFu, Oi, sh);
    }
    if (lane == 0) {
        float b2r = b_real[256], b2i = b_imag[256];
        float b7r = b_real[768], b7i = b_imag[768];
        size_t o = ((size_t)s << 10);
        // X[256] = E - i*O ; X[768] = E + i*O
        out_real[o + 256] = Er + Oi + (b2r - b2i);
        out_imag[o + 256] = Ei - Or + (b2r + b2i);
        out_real[o + 768] = Er - Oi + (b7r - b7i);
        out_imag[o + 768] = Ei + Or + (b7r + b7i);
    }
}

// ---------------- chunk loader ----------------
DINL void load_chunk(uint32_t st, int m0, int n0, int kc, int tid) {
    const int c0 = kc * BK;
#pragma unroll
    for (int it = 0; it < 4; ++it) {                   // A: 128 rows x 8 x 16B
        int u = tid + it * 256;
        int r = u >> 3, c = u & 7;
        uint32_t so = swz((uint32_t)((r << 7) + (c << 4)));
        size_t off = (((size_t)(m0 + r)) << 9) + c0 + (c << 3);
        cp16(st + OFF_AR + so, g_xr_h + off);
        cp16(st + OFF_AI + so, g_xi_h + off);
    }
#pragma unroll
    for (int it = 0; it < 2; ++it) {                   // B: 64 rows x 8 x 16B
        int u = tid + it * 256;
        int r = u >> 3, c = u & 7;
        uint32_t so = swz((uint32_t)((r << 7) + (c << 4)));
        size_t go = (((size_t)(n0 + r)) << 9) + c0 + (c << 3);
        cp16(st + OFF_BR + so, g_wr_h + go);
        cp16(st + OFF_BI + so, g_wi_h + go);
    }
}

// ---------------- main GEMM kernel (radix-2 fused) ----------------
__global__ void __launch_bounds__(THREADS, 1)
dft_gemm_kernel(const float* __restrict__ b_real, const float* __restrict__ b_imag,
                const float* __restrict__ w_real, const float* __restrict__ w_imag,
                float* __restrict__ out_real, float* __restrict__ out_imag) {
    extern __shared__ __align__(1024) char sm[];
    uint32_t sb = (uint32_t)__cvta_generic_to_shared(sm);
    const int tid = threadIdx.x, wid = tid >> 5, lid = tid & 31;
    const int n0 = blockIdx.x * BN;                    // W512 col tile base, in [0,256)
    const int m0 = blockIdx.y * BM;                    // scratch row base
    const int wm = (wid >> 2) * 64;
    const int wn = (wid & 3) * 16;

    // stage bias + twiddle tables
    float* TB = (float*)(sm + SM_TAB);
    if (tid < 64) {
        int c = n0 + tid, mc = 512 - c, mc2 = (mc + 512) & 1023;
        float a, b;
        a = b_real[c];        b = b_imag[c];        TB[tid] = a - b;       TB[64 + tid] = a + b;
        a = b_real[c + 512];  b = b_imag[c + 512];  TB[128 + tid] = a - b; TB[192 + tid] = a + b;
        a = b_real[mc];       b = b_imag[mc];       TB[256 + tid] = a - b; TB[320 + tid] = a + b;
        a = b_real[mc2];      b = b_imag[mc2];      TB[384 + tid] = a - b; TB[448 + tid] = a + b;
        TB[512 + tid] = w_real[((size_t)c << 10) + 1];    // w^c
        TB[576 + tid] = w_imag[((size_t)c << 10) + 1];
        TB[640 + tid] = w_real[((size_t)mc << 10) + 1];   // w^(512-c)
        TB[704 + tid] = w_imag[((size_t)mc << 10) + 1];
    }

    // pipeline prologue
    load_chunk(sb + 0 * STAGE, m0, n0, 0, tid); cp_commit();
    load_chunk(sb + 1 * STAGE, m0, n0, 1, tid); cp_commit();
    load_chunk(sb + 2 * STAGE, m0, n0, 2, tid); cp_commit();

    // P1=x?@Wr(xr), P2=xi@Wi, P3=xr@Wi, P4=xi@Wr (per scratch row: E or O rows)
    float P1[4][2][4], P2[4][2][4], P3[4][2][4], P4[4][2][4];
#pragma unroll
    for (int a = 0; a < 4; ++a)
#pragma unroll
        for (int b = 0; b < 2; ++b)
#pragma unroll
            for (int c = 0; c < 4; ++c) {
                P1[a][b][c] = 0.f; P2[a][b][c] = 0.f;
                P3[a][b][c] = 0.f; P4[a][b][c] = 0.f;
            }

    const int lrow = lid & 15;
    const int lcb  = (lid >> 4) << 4;

    for (int i = 0; i < NCHUNK; ++i) {
        cp_wait<STAGES - 2>();
        __syncthreads();
        if (i + 3 < NCHUNK)
            load_chunk(sb + ((i + 3) & 3) * STAGE, m0, n0, i + 3, tid);
        cp_commit();

        const uint32_t st = sb + (i & 3) * STAGE;
#pragma unroll
        for (int kk = 0; kk < 4; ++kk) {
            const uint32_t colb = (uint32_t)(kk * 32 + lcb);
            uint32_t Axr[4][4], Axi[4][4];
#pragma unroll
            for (int mt = 0; mt < 4; ++mt) {
                uint32_t ro = (uint32_t)((wm + mt * 16 + lrow) << 7) + colb;
                ldsm4(Axr[mt], st + OFF_AR + swz(ro));
                ldsm4(Axi[mt], st + OFF_AI + swz(ro));
            }
            uint32_t Bwr[4], Bwi[4], t4[4];
            {
                uint32_t ro = (uint32_t)((wn + lrow) << 7) + colb;
                ldsm4(t4, st + OFF_BR + swz(ro));
                Bwr[0] = t4[0]; Bwr[1] = t4[2]; Bwr[2] = t4[1]; Bwr[3] = t4[3];
                ldsm4(t4, st + OFF_BI + swz(ro));
                Bwi[0] = t4[0]; Bwi[1] = t4[2]; Bwi[2] = t4[1]; Bwi[3] = t4[3];
            }
#pragma unroll
            for (int mt = 0; mt < 4; ++mt)
#pragma unroll
                for (int nt = 0; nt < 2; ++nt) {
                    const int ob = nt * 2;
                    mma16816(P1[mt][nt], Axr[mt], Bwr[ob], Bwr[ob + 1]);
                    mma16816(P2[mt][nt], Axi[mt], Bwi[ob], Bwi[ob + 1]);
                    mma16816(P3[mt][nt], Axr[mt], Bwi[ob], Bwi[ob + 1]);
                    mma16816(P4[mt][nt], Axi[mt], Bwr[ob], Bwr[ob + 1]);
                }
        }
    }

    // ---------------- fused radix-2 epilogue ----------------
    const float* bmD = TB,        *bpD = TB + 64,  *bmD2 = TB + 128, *bpD2 = TB + 192;
    const float* bmM = TB + 256,  *bpM = TB + 320, *bmM2 = TB + 384, *bpM2 = TB + 448;
    const float* twdr = TB + 512, *twdi = TB + 576, *twmr = TB + 640, *twmi = TB + 704;
    const int gr = lid >> 2, gc = (lid & 3) * 2;
    const bool isE = (gr & 1) == 0;                    // even gr lanes hold E-rows

#pragma unroll
    for (int mt = 0; mt < 4; ++mt)
#pragma unroll
        for (int nt = 0; nt < 2; ++nt) {
            const int jl = wn + nt * 8 + gc;           // 0..62 (even)
            const int c = n0 + jl;                     // direct col, in [0,255)
            // exchange with partner lane (other parity row, same signal)
            float eP1[4], eP2[4], eP3[4], eP4[4], oP1[4], oP2[4], oP3[4], oP4[4];
#pragma unroll
            for (int q = 0; q < 4; ++q) {
                float a1 = P1[mt][nt][q], a2 = P2[mt][nt][q];
                float a3 = P3[mt][nt][q], a4 = P4[mt][nt][q];
                float b1 = __shfl_xor_sync(0xFFFFFFFFu, a1, 4);
                float b2 = __shfl_xor_sync(0xFFFFFFFFu, a2, 4);
                float b3 = __shfl_xor_sync(0xFFFFFFFFu, a3, 4);
                float b4 = __shfl_xor_sync(0xFFFFFFFFu, a4, 4);
                eP1[q] = isE ? a1 : b1; oP1[q] = isE ? b1 : a1;
                eP2[q] = isE ? a2 : b2; oP2[q] = isE ? b2 : a2;
                eP3[q] = isE ? a3 : b3; oP3[q] = isE ? b3 : a3;
                eP4[q] = isE ? a4 : b4; oP4[q] = isE ? b4 : a4;
            }
#pragma unroll
            for (int rg = 0; rg < 2; ++rg) {
                const int e0 = rg * 2, e1 = rg * 2 + 1;
                size_t s = (size_t)((m0 + wm + mt * 16 + gr) >> 1) + rg * 4;  // signal
                float* pr = out_real + (s << 10);
                float* pi = out_imag + (s << 10);
                if (isE) {
                    // direct cols c (elem e0) and c+1 (elem e1)
                    float ErA = eP1[e0] - eP2[e0], EiA = eP3[e0] + eP4[e0];
                    float OrA = oP1[e0] - oP2[e0], OiA = oP3[e0] + oP4[e0];
                    float ErB = eP1[e1] - eP2[e1], EiB = eP3[e1] + eP4[e1];
                    float OrB = oP1[e1] - oP2[e1], OiB = oP3[e1] + oP4[e1];
                    float trA = twdr[jl] * OrA - twdi[jl] * OiA;
                    float tiA = twdr[jl] * OiA + twdi[jl] * OrA;
                    float trB = twdr[jl + 1] * OrB - twdi[jl + 1] * OiB;
                    float tiB = twdr[jl + 1] * OiB + twdi[jl + 1] * OrB;
                    float2 v;
                    v.x = ErA + trA + bmD[jl]; v.y = ErB + trB + bmD[jl + 1];
                    *(float2*)(pr + c) = v;
                    v.x = EiA + tiA + bpD[jl]; v.y = EiB + tiB + bpD[jl + 1];
                    *(float2*)(pi + c) = v;
                    v.x = ErA - trA + bmD2[jl]; v.y = ErB - trB + bmD2[jl + 1];
                    *(float2*)(pr + c + 512) = v;
                    v.x = EiA - tiA + bpD2[jl]; v.y = EiB - tiB + bpD2[jl + 1];
                    *(float2*)(pi + c + 512) = v;
                } else {
                    // mirror cols 512-c (elem e0) and 511-c (elem e1)
                    float ErA = eP1[e0] + eP2[e0], EiA = eP4[e0] - eP3[e0];
                    float OrA = oP1[e0] + oP2[e0], OiA = oP4[e0] - oP3[e0];
                    float ErB = eP1[e1] + eP2[e1], EiB = eP4[e1] - eP3[e1];
                    float OrB = oP1[e1] + oP2[e1], OiB = oP4[e1] - oP3[e1];
                    float trA = twmr[jl] * OrA - twmi[jl] * OiA;
                    float tiA = twmr[jl] * OiA + twmi[jl] * OrA;
                    float trB = twmr[jl + 1] * OrB - twmi[jl + 1] * OiB;
                    float tiB = twmr[jl + 1] * OiB + twmi[jl + 1] * OrB;
                    const int mcA = 512 - c;
                    const int mcA2 = (mcA + 512) & 1023;
                    if (c != 0) {                       // c==0 cols owned by direct path
                        pr[mcA] = ErA + trA + bmM[jl];
                        pi[mcA] = EiA + tiA + bpM[jl];
                        pr[mcA2] = ErA - trA + bmM2[jl];
                        pi[mcA2] = EiA - tiA + bpM2[jl];
                    }
                    pr[mcA - 1] = ErB + trB + bmM[jl + 1];
                    pi[mcA - 1] = EiB + tiB + bpM[jl + 1];
                    pr[1023 - c] = ErB - trB + bmM2[jl + 1];
                    pi[1023 - c] = EiB - tiB + bpM2[jl + 1];
                }
            }
        }
}

// ---------------- launch ----------------
extern "C" void kernel_launch(void* const* d_in, const int* in_sizes, int n_in,
                              void* d_out, int out_size) {
    (void)in_sizes; (void)n_in; (void)out_size;
    const float4* xr = (const float4*)d_in[0];
    const float4* xi = (const float4*)d_in[1];
    const float4* wr = (const float4*)d_in[2];
    const float4* wi = (const float4*)d_in[3];
    const float*  br = (const float*)d_in[4];
    const float*  bi = (const float*)d_in[5];
    float* out_real = (float*)d_out;
    float* out_imag = out_real + (size_t)M_SIG * 1024;

    convert_x_kernel<<<8192, 256>>>(xr, xi);
    convert_w_kernel<<<64, 256>>>(wr, wi);
    col256_kernel<<<4096, 256>>>(br, bi, out_real, out_imag);

    cudaFuncSetAttribute(dft_gemm_kernel,
                         cudaFuncAttributeMaxDynamicSharedMemorySize, SMEM_TOTAL);
    dim3 grid(256 / BN, MR / BM);   // (4, 512)
    dft_gemm_kernel<<<grid, THREADS, SMEM_TOTAL>>>(br, bi,
                                                   (const float*)d_in[2],
                                                   (const float*)d_in[3],
                                                   out_real, out_imag);
}

// round 7
// speedup vs baseline: 2.1717x; 1.0286x over previous
#include <cuda_runtime.h>
#include <cuda_fp16.h>
#include <cstdint>

#define DINL __device__ __forceinline__

// ---------------- problem sizes ----------------
static constexpr int M_SIG = 32768;        // independent signals
static constexpr int MR    = 131072;       // scratch rows: 4 phases per signal
static constexpr int KQ    = 256;          // GEMM K (quarter window)
static constexpr int BM = 128;             // scratch rows per CTA (32 signals)
static constexpr int BN = 64;              // direct W256 cols per CTA (of 128)
static constexpr int BK = 64;              // halfs per chunk (128B rows)
static constexpr int NCHUNK = KQ / BK;     // 4
static constexpr int STAGES = 4;
static constexpr int THREADS = 256;

// ---------------- smem layout ----------------
static constexpr uint32_t OFF_AR = 0;                 // xr tile 128x128B = 16KB
static constexpr uint32_t OFF_AI = 16384;
static constexpr uint32_t OFF_BR = 32768;             // wr tile 64x128B = 8KB
static constexpr uint32_t OFF_BI = 40960;
static constexpr uint32_t STAGE  = 49152;             // 48KB
static constexpr uint32_t SM_TAB = STAGES * STAGE;    // 196608: twiddle/bias tables
static constexpr uint32_t SMEM_TOTAL = SM_TAB + 16384;  // 212992

// table float offsets inside TB
static constexpr int T_TWD = 0;      // [64][4][6]
static constexpr int T_TWM = 1536;   // [64][4][6]
static constexpr int T_BD  = 3072;   // [64][4][2]
static constexpr int T_BM  = 3584;   // [64][4][2]

// ---------------- fp16 scratch ----------------
// row 4s+p holds samples n == p (mod 4) of signal s: 256 halfs per row
__device__ __align__(128) __half g_xr_h[33554432];
__device__ __align__(128) __half g_xi_h[33554432];
// W256 rows 0..127 (k-major, 256 halfs per row): W256[k][t] = w1024[4k][t]
__device__ __align__(128) __half g_wr_h[32768];
__device__ __align__(128) __half g_wi_h[32768];

// ---------------- PTX helpers ----------------
DINL uint32_t swz(uint32_t o) { return o ^ ((o >> 3) & 0x70); }

DINL void cp16(uint32_t dst, const void* src) {
    asm volatile("cp.async.cg.shared.global [%0], [%1], 16;\n" :: "r"(dst), "l"(src));
}
DINL void cp_commit() { asm volatile("cp.async.commit_group;\n" ::: "memory"); }
template <int N> DINL void cp_wait() {
    asm volatile("cp.async.wait_group %0;\n" :: "n"(N) : "memory");
}

DINL void ldsm4(uint32_t* r, uint32_t a) {
    asm volatile("ldmatrix.sync.aligned.m8n8.x4.shared.b16 {%0,%1,%2,%3}, [%4];\n"
                 : "=r"(r[0]), "=r"(r[1]), "=r"(r[2]), "=r"(r[3]) : "r"(a));
}

DINL void mma16816(float* d, const uint32_t* a, uint32_t b0, uint32_t b1) {
    asm volatile(
        "mma.sync.aligned.m16n8k16.row.col.f32.f16.f16.f32 "
        "{%0,%1,%2,%3}, {%4,%5,%6,%7}, {%8,%9}, {%0,%1,%2,%3};\n"
        : "+f"(d[0]), "+f"(d[1]), "+f"(d[2]), "+f"(d[3])
        : "r"(a[0]), "r"(a[1]), "r"(a[2]), "r"(a[3]), "r"(b0), "r"(b1));
}

// ---------------- conversion ----------------
DINL uint32_t h2u(float a, float b) {
    __half2 h = __floats2half2_rn(a, b);
    return *(uint32_t*)&h;
}
DINL uint4 pack8(float4 a, float4 b) {
    uint4 u;
    u.x = h2u(a.x, a.y); u.y = h2u(a.z, a.w);
    u.z = h2u(b.x, b.y); u.w = h2u(b.z, b.w);
    return u;
}

// 4-phase deinterleave: thread handles 16 consecutive samples of one signal
__global__ void __launch_bounds__(256) convert_x_kernel(const float4* __restrict__ xr,
                                                        const float4* __restrict__ xi) {
    size_t gid = (size_t)blockIdx.x * 256 + threadIdx.x;   // 2M threads
    size_t m = gid >> 6;                                   // signal
    int j = (int)(gid & 63);                               // 16-sample group
    {
        const float4* p = xr + (m << 8) + (j << 2);
        float4 f0 = p[0], f1 = p[1], f2 = p[2], f3 = p[3];
        // f_q component [p] is sample n=16j+4q+p -> phase p, t=4j+q
        uint2 v;
        v.x = h2u(f0.x, f1.x); v.y = h2u(f2.x, f3.x);
        *(uint2*)(g_xr_h + ((m * 4 + 0) << 8) + (j << 2)) = v;
        v.x = h2u(f0.y, f1.y); v.y = h2u(f2.y, f3.y);
        *(uint2*)(g_xr_h + ((m * 4 + 1) << 8) + (j << 2)) = v;
        v.x = h2u(f0.z, f1.z); v.y = h2u(f2.z, f3.z);
        *(uint2*)(g_xr_h + ((m * 4 + 2) << 8) + (j << 2)) = v;
        v.x = h2u(f0.w, f1.w); v.y = h2u(f2.w, f3.w);
        *(uint2*)(g_xr_h + ((m * 4 + 3) << 8) + (j << 2)) = v;
    }
    {
        const float4* p = xi + (m << 8) + (j << 2);
        float4 f0 = p[0], f1 = p[1], f2 = p[2], f3 = p[3];
        uint2 v;
        v.x = h2u(f0.x, f1.x); v.y = h2u(f2.x, f3.x);
        *(uint2*)(g_xi_h + ((m * 4 + 0) << 8) + (j << 2)) = v;
        v.x = h2u(f0.y, f1.y); v.y = h2u(f2.y, f3.y);
        *(uint2*)(g_xi_h + ((m * 4 + 1) << 8) + (j << 2)) = v;
        v.x = h2u(f0.z, f1.z); v.y = h2u(f2.z, f3.z);
        *(uint2*)(g_xi_h + ((m * 4 + 2) << 8) + (j << 2)) = v;
        v.x = h2u(f0.w, f1.w); v.y = h2u(f2.w, f3.w);
        *(uint2*)(g_xi_h + ((m * 4 + 3) << 8) + (j << 2)) = v;
    }
}

// W256 rows 0..127: row k = first 256 cols of w1024 row 4k
// row 4k starts at float4 index (4k)*(1024/4) = k<<10
__global__ void __launch_bounds__(256) convert_w_kernel(const float4* __restrict__ wr,
                                                        const float4* __restrict__ wi) {
    size_t gid = (size_t)blockIdx.x * 256 + threadIdx.x;   // 4096 threads
    size_t k = gid >> 5;                                   // W256 row
    int j = (int)(gid & 31);                               // 8-half group
    size_t src = (k << 10) + (j << 1);                     // float4 idx into row 4k
    float4 a = wr[src], b = wr[src + 1];
    *(uint4*)(g_wr_h + (k << 8) + (j << 3)) = pack8(a, b);
    float4 c = wi[src], d = wi[src + 1];
    *(uint4*)(g_wi_h + (k << 8) + (j << 3)) = pack8(c, d);
}

// ---------------- special cols: km = 128 -> k in {128,384,640,896} ----------------
DINL float altsum(uint4 v) {
    const __half2* h = (const __half2*)&v;
    float s = 0.f;
#pragma unroll
    for (int j = 0; j < 4; ++j) { float2 f = __half22float2(h[j]); s += f.x - f.y; }
    return s;
}

__global__ void __launch_bounds__(256) col128_kernel(const float* __restrict__ b_real,
                                                     const float* __restrict__ b_imag,
                                                     const float* __restrict__ w_real,
                                                     const float* __restrict__ w_imag,
                                                     float* __restrict__ out_real,
                                                     float* __restrict__ out_imag) {
    int s = blockIdx.x * 8 + (threadIdx.x >> 5);       // one warp per signal
    int lane = threadIdx.x & 31;
    float g[8];                                        // G0r,G0i,G1r,G1i,G2r,G2i,G3r,G3i
#pragma unroll
    for (int p = 0; p < 4; ++p) {
        const uint4* rr = (const uint4*)(g_xr_h + ((size_t)(4 * s + p) << 8));
        const uint4* ri = (const uint4*)(g_xi_h + ((size_t)(4 * s + p) << 8));
        g[2 * p]     = altsum(rr[lane]);
        g[2 * p + 1] = altsum(ri[lane]);
    }
#pragma unroll
    for (int sh = 16; sh > 0; sh >>= 1)
#pragma unroll
        for (int v = 0; v < 8; ++v) g[v] += __shfl_xor_sync(0xFFFFFFFFu, g[v], sh);
    if (lane == 0) {
        float twr[6], twi[6];                          // rows 128,256,384,640,768,896
        const int rows[6] = {128, 256, 384, 640, 768, 896};
#pragma unroll
        for (int v = 0; v < 6; ++v) {
            twr[v] = w_real[((size_t)rows[v] << 10) + 1];
            twi[v] = w_imag[((size_t)rows[v] << 10) + 1];
        }
        size_t o = ((size_t)s << 10);
        // X[k] = G0 + w^k G1 + w^2k G2 + w^3k G3
        const int ks[4] = {128, 384, 640, 896};
        const int ia[4] = {0, 2, 3, 5};                // w^k   index
        const int ib[4] = {1, 4, 1, 4};                // w^2k  index
        const int ic[4] = {2, 0, 5, 3};                // w^3k  index
#pragma unroll
        for (int v = 0; v < 4; ++v) {
            float ar = twr[ia[v]], ai = twi[ia[v]];
            float br2 = twr[ib[v]], bi2 = twi[ib[v]];
            float cr = twr[ic[v]], ci = twi[ic[v]];
            float Xr = g[0] + ar * g[2] - ai * g[3] + br2 * g[4] - bi2 * g[5]
                            + cr * g[6] - ci * g[7];
            float Xi = g[1] + ar * g[3] + ai * g[2] + br2 * g[5] + bi2 * g[4]
                            + cr * g[7] + ci * g[6];
            int k = ks[v];
            float br = b_real[k], bi = b_imag[k];
            out_real[o + k] = Xr + (br - bi);
            out_imag[o + k] = Xi + (br + bi);
        }
    }
}

// ---------------- chunk loader ----------------
DINL void load_chunk(uint32_t st, int m0, int n0, int kc, int tid) {
    const int c0 = kc * BK;
#pragma unroll
    for (int it = 0; it < 4; ++it) {                   // A: 128 rows x 8 x 16B
        int u = tid + it * 256;
        int r = u >> 3, c = u & 7;
        uint32_t so = swz((uint32_t)((r << 7) + (c << 4)));
        size_t off = (((size_t)(m0 + r)) << 8) + c0 + (c << 3);
        cp16(st + OFF_AR + so, g_xr_h + off);
        cp16(st + OFF_AI + so, g_xi_h + off);
    }
#pragma unroll
    for (int it = 0; it < 2; ++it) {                   // B: 64 rows x 8 x 16B
        int u = tid + it * 256;
        int r = u >> 3, c = u & 7;
        uint32_t so = swz((uint32_t)((r << 7) + (c << 4)));
        size_t go = (((size_t)(n0 + r)) << 8) + c0 + (c << 3);
        cp16(st + OFF_BR + so, g_wr_h + go);
        cp16(st + OFF_BI + so, g_wi_h + go);
    }
}

// combine X = G0 + t1*G1 + t2*G2 + t3*G3 (t = [t1r,t1i,t2r,t2i,t3r,t3i])
DINL void comb4(float& Xr, float& Xi, const float* gr_, const float* gi_, const float* t) {
    Xr = gr_[0] + t[0] * gr_[1] - t[1] * gi_[1]
                + t[2] * gr_[2] - t[3] * gi_[2]
                + t[4] * gr_[3] - t[5] * gi_[3];
    Xi = gi_[0] + t[0] * gi_[1] + t[1] * gr_[1]
                + t[2] * gi_[2] + t[3] * gr_[2]
                + t[4] * gi_[3] + t[5] * gr_[3];
}

// ---------------- main GEMM kernel (radix-4 fused) ----------------
__global__ void __launch_bounds__(THREADS, 1)
dft_gemm_kernel(const float* __restrict__ b_real, const float* __restrict__ b_imag,
                const float* __restrict__ w_real, const float* __restrict__ w_imag,
                float* __restrict__ out_real, float* __restrict__ out_imag) {
    extern __shared__ __align__(1024) char sm[];
    uint32_t sb = (uint32_t)__cvta_generic_to_shared(sm);
    const int tid = threadIdx.x, wid = tid >> 5, lid = tid & 31;
    const int n0 = blockIdx.x * BN;                    // W256 col tile base, in [0,128)
    const int m0 = blockIdx.y * BM;                    // scratch row base
    const int wm = (wid >> 2) * 64;
    const int wn = (wid & 3) * 16;

    // stage twiddle/bias tables: thread (j,q) handles direct k=c+256q, mirror k=(256-c)+256q
    float* TB = (float*)(sm + SM_TAB);
    {
        int j = tid >> 2, q4 = tid & 3;
        int c = n0 + j;
        int kd = c + 256 * q4;
        int km = (256 - c + 256 * q4) & 1023;
        int base = (j * 4 + q4) * 6;
        int k2 = (2 * kd) & 1023, k3 = (3 * kd) & 1023;
        TB[T_TWD + base + 0] = w_real[((size_t)kd << 10) + 1];
        TB[T_TWD + base + 1] = w_imag[((size_t)kd << 10) + 1];
        TB[T_TWD + base + 2] = w_real[((size_t)k2 << 10) + 1];
        TB[T_TWD + base + 3] = w_imag[((size_t)k2 << 10) + 1];
        TB[T_TWD + base + 4] = w_real[((size_t)k3 << 10) + 1];
        TB[T_TWD + base + 5] = w_imag[((size_t)k3 << 10) + 1];
        int m2 = (2 * km) & 1023, m3 = (3 * km) & 1023;
        TB[T_TWM + base + 0] = w_real[((size_t)km << 10) + 1];
        TB[T_TWM + base + 1] = w_imag[((size_t)km << 10) + 1];
        TB[T_TWM + base + 2] = w_real[((size_t)m2 << 10) + 1];
        TB[T_TWM + base + 3] = w_imag[((size_t)m2 << 10) + 1];
        TB[T_TWM + base + 4] = w_real[((size_t)m3 << 10) + 1];
        TB[T_TWM + base + 5] = w_imag[((size_t)m3 << 10) + 1];
        int bb = (j * 4 + q4) * 2;
        float a = b_real[kd], b = b_imag[kd];
        TB[T_BD + bb] = a - b; TB[T_BD + bb + 1] = a + b;
        a = b_real[km]; b = b_imag[km];
        TB[T_BM + bb] = a - b; TB[T_BM + bb + 1] = a + b;
    }

    // pipeline prologue
    load_chunk(sb + 0 * STAGE, m0, n0, 0, tid); cp_commit();
    load_chunk(sb + 1 * STAGE, m0, n0, 1, tid); cp_commit();
    load_chunk(sb + 2 * STAGE, m0, n0, 2, tid); cp_commit();

    float P1[4][2][4], P2[4][2][4], P3[4][2][4], P4[4][2][4];
#pragma unroll
    for (int a = 0; a < 4; ++a)
#pragma unroll
        for (int b = 0; b < 2; ++b)
#pragma unroll
            for (int c = 0; c < 4; ++c) {
                P1[a][b][c] = 0.f; P2[a][b][c] = 0.f;
                P3[a][b][c] = 0.f; P4[a][b][c] = 0.f;
            }

    const int lrow = lid & 15;
    const int lcb  = (lid >> 4) << 4;

    for (int i = 0; i < NCHUNK; ++i) {
        cp_wait<STAGES - 2>();
        __syncthreads();
        if (i + 3 < NCHUNK)
            load_chunk(sb + ((i + 3) & 3) * STAGE, m0, n0, i + 3, tid);
        cp_commit();

        const uint32_t st = sb + (i & 3) * STAGE;
#pragma unroll
        for (int kk = 0; kk < 4; ++kk) {
            const uint32_t colb = (uint32_t)(kk * 32 + lcb);
            uint32_t Axr[4][4], Axi[4][4];
#pragma unroll
            for (int mt = 0; mt < 4; ++mt) {
                uint32_t ro = (uint32_t)((wm + mt * 16 + lrow) << 7) + colb;
                ldsm4(Axr[mt], st + OFF_AR + swz(ro));
                ldsm4(Axi[mt], st + OFF_AI + swz(ro));
            }
            uint32_t Bwr[4], Bwi[4], t4[4];
            {
                uint32_t ro = (uint32_t)((wn + lrow) << 7) + colb;
                ldsm4(t4, st + OFF_BR + swz(ro));
                Bwr[0] = t4[0]; Bwr[1] = t4[2]; Bwr[2] = t4[1]; Bwr[3] = t4[3];
                ldsm4(t4, st + OFF_BI + swz(ro));
                Bwi[0] = t4[0]; Bwi[1] = t4[2]; Bwi[2] = t4[1]; Bwi[3] = t4[3];
            }
#pragma unroll
            for (int mt = 0; mt < 4; ++mt)
#pragma unroll
                for (int nt = 0; nt < 2; ++nt) {
                    const int ob = nt * 2;
                    mma16816(P1[mt][nt], Axr[mt], Bwr[ob], Bwr[ob + 1]);
                    mma16816(P2[mt][nt], Axi[mt], Bwi[ob], Bwi[ob + 1]);
                    mma16816(P3[mt][nt], Axr[mt], Bwi[ob], Bwi[ob + 1]);
                    mma16816(P4[mt][nt], Axi[mt], Bwr[ob], Bwr[ob + 1]);
                }
        }
    }

    // ---------------- fused 4-phase combine epilogue ----------------
    const int gr = lid >> 2, gc = lid & 3;
    const int q  = gr & 3;                             // lane's k-quarter AND phase
    const int lbase = lid & ~12;                       // quad base lane (phase 0)

#pragma unroll
    for (int mt = 0; mt < 4; ++mt)
#pragma unroll
        for (int nt = 0; nt < 2; ++nt) {
            const int jl = wn + nt * 8 + gc * 2;       // e0 col (even), e1 = jl+1
#pragma unroll
            for (int rg = 0; rg < 2; ++rg) {
                const int e0 = rg * 2, e1 = e0 + 1;
                size_t s = (size_t)(m0 >> 2) + (wm >> 2) + mt * 4 + rg * 2 + (gr >> 2);
                float* pr = out_real + (s << 10);
                float* pi = out_imag + (s << 10);
                // own-phase G values (direct col c and mirror 256-c), cols A=jl, B=jl+1
                float GdrA = P1[mt][nt][e0] - P2[mt][nt][e0];
                float GdiA = P3[mt][nt][e0] + P4[mt][nt][e0];
                float GmrA = P1[mt][nt][e0] + P2[mt][nt][e0];
                float GmiA = P4[mt][nt][e0] - P3[mt][nt][e0];
                float GdrB = P1[mt][nt][e1] - P2[mt][nt][e1];
                float GdiB = P3[mt][nt][e1] + P4[mt][nt][e1];
                float GmrB = P1[mt][nt][e1] + P2[mt][nt][e1];
                float GmiB = P4[mt][nt][e1] - P3[mt][nt][e1];
                // gather all 4 phases in absolute order
                float dAr[4], dAi[4], mAr[4], mAi[4];
                float dBr[4], dBi[4], mBr[4], mBi[4];
#pragma unroll
                for (int p = 0; p < 4; ++p) {
                    int src = lbase | (p << 2);
                    dAr[p] = __shfl_sync(0xFFFFFFFFu, GdrA, src);
                    dAi[p] = __shfl_sync(0xFFFFFFFFu, GdiA, src);
                    mAr[p] = __shfl_sync(0xFFFFFFFFu, GmrA, src);
                    mAi[p] = __shfl_sync(0xFFFFFFFFu, GmiA, src);
                    dBr[p] = __shfl_sync(0xFFFFFFFFu, GdrB, src);
                    dBi[p] = __shfl_sync(0xFFFFFFFFu, GdiB, src);
                    mBr[p] = __shfl_sync(0xFFFFFFFFu, GmrB, src);
                    mBi[p] = __shfl_sync(0xFFFFFFFFu, GmiB, src);
                }
                // direct: k = c + 256q for cols jl / jl+1
                {
                    const float* tA = TB + T_TWD + (jl * 4 + q) * 6;
                    const float* tB = TB + T_TWD + ((jl + 1) * 4 + q) * 6;
                    float XrA, XiA, XrB, XiB;
                    comb4(XrA, XiA, dAr, dAi, tA);
                    comb4(XrB, XiB, dBr, dBi, tB);
                    const float* bA = TB + T_BD + (jl * 4 + q) * 2;
                    const float* bB = TB + T_BD + ((jl + 1) * 4 + q) * 2;
                    int kd = (n0 + jl) + 256 * q;
                    float2 v;
                    v.x = XrA + bA[0]; v.y = XrB + bB[0];
                    *(float2*)(pr + kd) = v;
                    v.x = XiA + bA[1]; v.y = XiB + bB[1];
                    *(float2*)(pi + kd) = v;
                }
                // mirror: col A -> k = (256-c)+256q (skip if 1024), col B -> k-1
                {
                    const float* tA = TB + T_TWM + (jl * 4 + q) * 6;
                    const float* tB = TB + T_TWM + ((jl + 1) * 4 + q) * 6;
                    float XrA, XiA, XrB, XiB;
                    comb4(XrA, XiA, mAr, mAi, tA);
                    comb4(XrB, XiB, mBr, mBi, tB);
                    const float* bA = TB + T_BM + (jl * 4 + q) * 2;
                    const float* bB = TB + T_BM + ((jl + 1) * 4 + q) * 2;
                    int kmA = 256 - (n0 + jl) + 256 * q;
                    pr[kmA - 1] = XrB + bB[0];
                    pi[kmA - 1] = XiB + bB[1];
                    if (kmA < 1024) {
                        pr[kmA] = XrA + bA[0];
                        pi[kmA] = XiA + bA[1];
                    }
                }
            }
        }
}

// ---------------- launch ----------------
extern "C" void kernel_launch(void* const* d_in, const int* in_sizes, int n_in,
                              void* d_out, int out_size) {
    (void)in_sizes; (void)n_in; (void)out_size;
    const float4* xr = (const float4*)d_in[0];
    const float4* xi = (const float4*)d_in[1];
    const float4* wr = (const float4*)d_in[2];
    const float4* wi = (const float4*)d_in[3];
    const float*  br = (const float*)d_in[4];
    const float*  bi = (const float*)d_in[5];
    float* out_real = (float*)d_out;
    float* out_imag = out_real + (size_t)M_SIG * 1024;

    convert_x_kernel<<<8192, 256>>>(xr, xi);
    convert_w_kernel<<<16, 256>>>(wr, wi);
    col128_kernel<<<4096, 256>>>(br, bi, (const float*)d_in[2], (const float*)d_in[3],
                                 out_real, out_imag);

    cudaFuncSetAttribute(dft_gemm_kernel,
                         cudaFuncAttributeMaxDynamicSharedMemorySize, SMEM_TOTAL);
    dim3 grid(128 / BN, MR / BM);   // (2, 1024)
    dft_gemm_kernel<<<grid, THREADS, SMEM_TOTAL>>>(br, bi,
                                                   (const float*)d_in[2],
                                                   (const float*)d_in[3],
                                                   out_real, out_imag);
}

// round 8
// speedup vs baseline: 2.1926x; 1.0096x over previous
#include <cuda_runtime.h>
#include <cuda_fp16.h>
#include <cstdint>

#define DINL __device__ __forceinline__

// ---------------- problem sizes ----------------
static constexpr int M_SIG = 32768;        // independent signals
static constexpr int MR    = 131072;       // scratch rows: 4 phases per signal
static constexpr int KQ    = 256;          // GEMM K (quarter window)
static constexpr int BM = 64;              // scratch rows per CTA (16 signals)
static constexpr int BN = 64;              // direct W256 cols per CTA (of 128)
static constexpr int BK = 64;              // halfs per chunk (128B rows)
static constexpr int NCHUNK = KQ / BK;     // 4
static constexpr int STAGES = 3;
static constexpr int THREADS = 256;

// ---------------- smem layout ----------------
static constexpr uint32_t OFF_AR = 0;                 // xr tile 64x128B = 8KB
static constexpr uint32_t OFF_AI = 8192;
static constexpr uint32_t OFF_BR = 16384;             // wr tile 64x128B = 8KB
static constexpr uint32_t OFF_BI = 24576;
static constexpr uint32_t STAGE  = 32768;             // 32KB
static constexpr uint32_t SM_TAB = STAGES * STAGE;    // 98304: twiddle/bias tables
static constexpr uint32_t SMEM_TOTAL = SM_TAB + 16384;  // 114688 (x2 CTA = 229376)

// table float offsets inside TB
static constexpr int T_TWD = 0;      // [64][4][6]
static constexpr int T_TWM = 1536;   // [64][4][6]
static constexpr int T_BD  = 3072;   // [64][4][2]
static constexpr int T_BM  = 3584;   // [64][4][2]

// ---------------- fp16 scratch ----------------
// row 4s+p holds samples n == p (mod 4) of signal s: 256 halfs per row
__device__ __align__(128) __half g_xr_h[33554432];
__device__ __align__(128) __half g_xi_h[33554432];
// W256 rows 0..127 (k-major, 256 halfs per row): W256[k][t] = w1024[4k][t]
__device__ __align__(128) __half g_wr_h[32768];
__device__ __align__(128) __half g_wi_h[32768];

// ---------------- PTX helpers ----------------
DINL uint32_t swz(uint32_t o) { return o ^ ((o >> 3) & 0x70); }

DINL void cp16(uint32_t dst, const void* src) {
    asm volatile("cp.async.cg.shared.global [%0], [%1], 16;\n" :: "r"(dst), "l"(src));
}
DINL void cp_commit() { asm volatile("cp.async.commit_group;\n" ::: "memory"); }
template <int N> DINL void cp_wait() {
    asm volatile("cp.async.wait_group %0;\n" :: "n"(N) : "memory");
}

DINL void ldsm4(uint32_t* r, uint32_t a) {
    asm volatile("ldmatrix.sync.aligned.m8n8.x4.shared.b16 {%0,%1,%2,%3}, [%4];\n"
                 : "=r"(r[0]), "=r"(r[1]), "=r"(r[2]), "=r"(r[3]) : "r"(a));
}

DINL void mma16816(float* d, const uint32_t* a, uint32_t b0, uint32_t b1) {
    asm volatile(
        "mma.sync.aligned.m16n8k16.row.col.f32.f16.f16.f32 "
        "{%0,%1,%2,%3}, {%4,%5,%6,%7}, {%8,%9}, {%0,%1,%2,%3};\n"
        : "+f"(d[0]), "+f"(d[1]), "+f"(d[2]), "+f"(d[3])
        : "r"(a[0]), "r"(a[1]), "r"(a[2]), "r"(a[3]), "r"(b0), "r"(b1));
}

// ---------------- conversion ----------------
DINL uint32_t h2u(float a, float b) {
    __half2 h = __floats2half2_rn(a, b);
    return *(uint32_t*)&h;
}
DINL uint4 pack8(float4 a, float4 b) {
    uint4 u;
    u.x = h2u(a.x, a.y); u.y = h2u(a.z, a.w);
    u.z = h2u(b.x, b.y); u.w = h2u(b.z, b.w);
    return u;
}

// 4-phase deinterleave: thread handles 16 consecutive samples of one signal
__global__ void __launch_bounds__(256) convert_x_kernel(const float4* __restrict__ xr,
                                                        const float4* __restrict__ xi) {
    size_t gid = (size_t)blockIdx.x * 256 + threadIdx.x;   // 2M threads
    size_t m = gid >> 6;                                   // signal
    int j = (int)(gid & 63);                               // 16-sample group
    {
        const float4* p = xr + (m << 8) + (j << 2);
        float4 f0 = p[0], f1 = p[1], f2 = p[2], f3 = p[3];
        uint2 v;
        v.x = h2u(f0.x, f1.x); v.y = h2u(f2.x, f3.x);
        *(uint2*)(g_xr_h + ((m * 4 + 0) << 8) + (j << 2)) = v;
        v.x = h2u(f0.y, f1.y); v.y = h2u(f2.y, f3.y);
        *(uint2*)(g_xr_h + ((m * 4 + 1) << 8) + (j << 2)) = v;
        v.x = h2u(f0.z, f1.z); v.y = h2u(f2.z, f3.z);
        *(uint2*)(g_xr_h + ((m * 4 + 2) << 8) + (j << 2)) = v;
        v.x = h2u(f0.w, f1.w); v.y = h2u(f2.w, f3.w);
        *(uint2*)(g_xr_h + ((m * 4 + 3) << 8) + (j << 2)) = v;
    }
    {
        const float4* p = xi + (m << 8) + (j << 2);
        float4 f0 = p[0], f1 = p[1], f2 = p[2], f3 = p[3];
        uint2 v;
        v.x = h2u(f0.x, f1.x); v.y = h2u(f2.x, f3.x);
        *(uint2*)(g_xi_h + ((m * 4 + 0) << 8) + (j << 2)) = v;
        v.x = h2u(f0.y, f1.y); v.y = h2u(f2.y, f3.y);
        *(uint2*)(g_xi_h + ((m * 4 + 1) << 8) + (j << 2)) = v;
        v.x = h2u(f0.z, f1.z); v.y = h2u(f2.z, f3.z);
        *(uint2*)(g_xi_h + ((m * 4 + 2) << 8) + (j << 2)) = v;
        v.x = h2u(f0.w, f1.w); v.y = h2u(f2.w, f3.w);
        *(uint2*)(g_xi_h + ((m * 4 + 3) << 8) + (j << 2)) = v;
    }
}

// W256 rows 0..127: row k = first 256 cols of w1024 row 4k (float4 idx k<<10)
__global__ void __launch_bounds__(256) convert_w_kernel(const float4* __restrict__ wr,
                                                        const float4* __restrict__ wi) {
    size_t gid = (size_t)blockIdx.x * 256 + threadIdx.x;   // 4096 threads
    size_t k = gid >> 5;                                   // W256 row
    int j = (int)(gid & 31);                               // 8-half group
    size_t src = (k << 10) + (j << 1);
    float4 a = wr[src], b = wr[src + 1];
    *(uint4*)(g_wr_h + (k << 8) + (j << 3)) = pack8(a, b);
    float4 c = wi[src], d = wi[src + 1];
    *(uint4*)(g_wi_h + (k << 8) + (j << 3)) = pack8(c, d);
}

// ---------------- special cols: k in {128,384,640,896} ----------------
DINL float altsum(uint4 v) {
    const __half2* h = (const __half2*)&v;
    float s = 0.f;
#pragma unroll
    for (int j = 0; j < 4; ++j) { float2 f = __half22float2(h[j]); s += f.x - f.y; }
    return s;
}

__global__ void __launch_bounds__(256) col128_kernel(const float* __restrict__ b_real,
                                                     const float* __restrict__ b_imag,
                                                     const float* __restrict__ w_real,
                                                     const float* __restrict__ w_imag,
                                                     float* __restrict__ out_real,
                                                     float* __restrict__ out_imag) {
    int s = blockIdx.x * 8 + (threadIdx.x >> 5);       // one warp per signal
    int lane = threadIdx.x & 31;
    float g[8];
#pragma unroll
    for (int p = 0; p < 4; ++p) {
        const uint4* rr = (const uint4*)(g_xr_h + ((size_t)(4 * s + p) << 8));
        const uint4* ri = (const uint4*)(g_xi_h + ((size_t)(4 * s + p) << 8));
        g[2 * p]     = altsum(rr[lane]);
        g[2 * p + 1] = altsum(ri[lane]);
    }
#pragma unroll
    for (int sh = 16; sh > 0; sh >>= 1)
#pragma unroll
        for (int v = 0; v < 8; ++v) g[v] += __shfl_xor_sync(0xFFFFFFFFu, g[v], sh);
    if (lane == 0) {
        float twr[6], twi[6];
        const int rows[6] = {128, 256, 384, 640, 768, 896};
#pragma unroll
        for (int v = 0; v < 6; ++v) {
            twr[v] = w_real[((size_t)rows[v] << 10) + 1];
            twi[v] = w_imag[((size_t)rows[v] << 10) + 1];
        }
        size_t o = ((size_t)s << 10);
        const int ks[4] = {128, 384, 640, 896};
        const int ia[4] = {0, 2, 3, 5};
        const int ib[4] = {1, 4, 1, 4};
        const int ic[4] = {2, 0, 5, 3};
#pragma unroll
        for (int v = 0; v < 4; ++v) {
            float ar = twr[ia[v]], ai = twi[ia[v]];
            float br2 = twr[ib[v]], bi2 = twi[ib[v]];
            float cr = twr[ic[v]], ci = twi[ic[v]];
            float Xr = g[0] + ar * g[2] - ai * g[3] + br2 * g[4] - bi2 * g[5]
                            + cr * g[6] - ci * g[7];
            float Xi = g[1] + ar * g[3] + ai * g[2] + br2 * g[5] + bi2 * g[4]
                            + cr * g[7] + ci * g[6];
            int k = ks[v];
            float br = b_real[k], bi = b_imag[k];
            out_real[o + k] = Xr + (br - bi);
            out_imag[o + k] = Xi + (br + bi);
        }
    }
}

// ---------------- chunk loader: 8 cp.async of 16B per thread ----------------
DINL void load_chunk(uint32_t st, int m0, int n0, int kc, int tid) {
    const int c0 = kc * BK;
#pragma unroll
    for (int it = 0; it < 2; ++it) {                   // A: 64 rows x 8 x 16B
        int u = tid + it * 256;                        // 0..511
        int r = u >> 3, c = u & 7;
        uint32_t so = swz((uint32_t)((r << 7) + (c << 4)));
        size_t off = (((size_t)(m0 + r)) << 8) + c0 + (c << 3);
        cp16(st + OFF_AR + so, g_xr_h + off);
        cp16(st + OFF_AI + so, g_xi_h + off);
    }
#pragma unroll
    for (int it = 0; it < 2; ++it) {                   // B: 64 rows x 8 x 16B
        int u = tid + it * 256;
        int r = u >> 3, c = u & 7;
        uint32_t so = swz((uint32_t)((r << 7) + (c << 4)));
        size_t go = (((size_t)(n0 + r)) << 8) + c0 + (c << 3);
        cp16(st + OFF_BR + so, g_wr_h + go);
        cp16(st + OFF_BI + so, g_wi_h + go);
    }
}

// combine X = G0 + t1*G1 + t2*G2 + t3*G3
DINL void comb4(float& Xr, float& Xi, const float* gr_, const float* gi_, const float* t) {
    Xr = gr_[0] + t[0] * gr_[1] - t[1] * gi_[1]
                + t[2] * gr_[2] - t[3] * gi_[2]
                + t[4] * gr_[3] - t[5] * gi_[3];
    Xi = gi_[0] + t[0] * gi_[1] + t[1] * gr_[1]
                + t[2] * gi_[2] + t[3] * gr_[2]
                + t[4] * gi_[3] + t[5] * gr_[3];
}

// ---------------- main GEMM kernel (radix-4 fused, 2 CTA/SM) ----------------
__global__ void __launch_bounds__(THREADS, 2)
dft_gemm_kernel(const float* __restrict__ b_real, const float* __restrict__ b_imag,
                const float* __restrict__ w_real, const float* __restrict__ w_imag,
                float* __restrict__ out_real, float* __restrict__ out_imag) {
    extern __shared__ __align__(1024) char sm[];
    uint32_t sb = (uint32_t)__cvta_generic_to_shared(sm);
    const int tid = threadIdx.x, wid = tid >> 5, lid = tid & 31;
    const int n0 = blockIdx.x * BN;                    // W256 col tile base, in [0,128)
    const int m0 = blockIdx.y * BM;                    // scratch row base
    const int wm = (wid >> 2) * 32;                    // 2 m-warp groups of 32 rows
    const int wn = (wid & 3) * 16;                     // 4 n-warp groups

    // stage twiddle/bias tables
    float* TB = (float*)(sm + SM_TAB);
    {
        int j = tid >> 2, q4 = tid & 3;
        int c = n0 + j;
        int kd = c + 256 * q4;
        int km = (256 - c + 256 * q4) & 1023;
        int base = (j * 4 + q4) * 6;
        int k2 = (2 * kd) & 1023, k3 = (3 * kd) & 1023;
        TB[T_TWD + base + 0] = w_real[((size_t)kd << 10) + 1];
        TB[T_TWD + base + 1] = w_imag[((size_t)kd << 10) + 1];
        TB[T_TWD + base + 2] = w_real[((size_t)k2 << 10) + 1];
        TB[T_TWD + base + 3] = w_imag[((size_t)k2 << 10) + 1];
        TB[T_TWD + base + 4] = w_real[((size_t)k3 << 10) + 1];
        TB[T_TWD + base + 5] = w_imag[((size_t)k3 << 10) + 1];
        int m2 = (2 * km) & 1023, m3 = (3 * km) & 1023;
        TB[T_TWM + base + 0] = w_real[((size_t)km << 10) + 1];
        TB[T_TWM + base + 1] = w_imag[((size_t)km << 10) + 1];
        TB[T_TWM + base + 2] = w_real[((size_t)m2 << 10) + 1];
        TB[T_TWM + base + 3] = w_imag[((size_t)m2 << 10) + 1];
        TB[T_TWM + base + 4] = w_real[((size_t)m3 << 10) + 1];
        TB[T_TWM + base + 5] = w_imag[((size_t)m3 << 10) + 1];
        int bb = (j * 4 + q4) * 2;
        float a = b_real[kd], b = b_imag[kd];
        TB[T_BD + bb] = a - b; TB[T_BD + bb + 1] = a + b;
        a = b_real[km]; b = b_imag[km];
        TB[T_BM + bb] = a - b; TB[T_BM + bb + 1] = a + b;
    }

    // pipeline prologue: 2 stages in flight
    load_chunk(sb + 0 * STAGE, m0, n0, 0, tid); cp_commit();
    load_chunk(sb + 1 * STAGE, m0, n0, 1, tid); cp_commit();

    float P1[2][2][4], P2[2][2][4], P3[2][2][4], P4[2][2][4];
#pragma unroll
    for (int a = 0; a < 2; ++a)
#pragma unroll
        for (int b = 0; b < 2; ++b)
#pragma unroll
            for (int c = 0; c < 4; ++c) {
                P1[a][b][c] = 0.f; P2[a][b][c] = 0.f;
                P3[a][b][c] = 0.f; P4[a][b][c] = 0.f;
            }

    const int lrow = lid & 15;
    const int lcb  = (lid >> 4) << 4;

    for (int i = 0; i < NCHUNK; ++i) {
        cp_wait<STAGES - 2>();
        __syncthreads();
        if (i + 2 < NCHUNK)
            load_chunk(sb + ((i + 2) % STAGES) * STAGE, m0, n0, i + 2, tid);
        cp_commit();

        const uint32_t st = sb + (i % STAGES) * STAGE;
#pragma unroll
        for (int kk = 0; kk < 4; ++kk) {
            const uint32_t colb = (uint32_t)(kk * 32 + lcb);
            uint32_t Axr[2][4], Axi[2][4];
#pragma unroll
            for (int mt = 0; mt < 2; ++mt) {
                uint32_t ro = (uint32_t)((wm + mt * 16 + lrow) << 7) + colb;
                ldsm4(Axr[mt], st + OFF_AR + swz(ro));
                ldsm4(Axi[mt], st + OFF_AI + swz(ro));
            }
            uint32_t Bwr[4], Bwi[4], t4[4];
            {
                uint32_t ro = (uint32_t)((wn + lrow) << 7) + colb;
                ldsm4(t4, st + OFF_BR + swz(ro));
                Bwr[0] = t4[0]; Bwr[1] = t4[2]; Bwr[2] = t4[1]; Bwr[3] = t4[3];
                ldsm4(t4, st + OFF_BI + swz(ro));
                Bwi[0] = t4[0]; Bwi[1] = t4[2]; Bwi[2] = t4[1]; Bwi[3] = t4[3];
            }
#pragma unroll
            for (int mt = 0; mt < 2; ++mt)
#pragma unroll
                for (int nt = 0; nt < 2; ++nt) {
                    const int ob = nt * 2;
                    mma16816(P1[mt][nt], Axr[mt], Bwr[ob], Bwr[ob + 1]);
                    mma16816(P2[mt][nt], Axi[mt], Bwi[ob], Bwi[ob + 1]);
                    mma16816(P3[mt][nt], Axr[mt], Bwi[ob], Bwi[ob + 1]);
                    mma16816(P4[mt][nt], Axi[mt], Bwr[ob], Bwr[ob + 1]);
                }
        }
    }

    // ---------------- fused 4-phase combine epilogue ----------------
    const int gr = lid >> 2, gc = lid & 3;
    const int q  = gr & 3;                             // lane's k-quarter AND phase
    const int lbase = lid & ~12;                       // quad base lane (phase 0)

#pragma unroll
    for (int mt = 0; mt < 2; ++mt)
#pragma unroll
        for (int nt = 0; nt < 2; ++nt) {
            const int jl = wn + nt * 8 + gc * 2;       // e0 col (even), e1 = jl+1
#pragma unroll
            for (int rg = 0; rg < 2; ++rg) {
                const int e0 = rg * 2, e1 = e0 + 1;
                size_t s = (size_t)(m0 >> 2) + (wm >> 2) + mt * 4 + rg * 2 + (gr >> 2);
                float* pr = out_real + (s << 10);
                float* pi = out_imag + (s << 10);
                float GdrA = P1[mt][nt][e0] - P2[mt][nt][e0];
                float GdiA = P3[mt][nt][e0] + P4[mt][nt][e0];
                float GmrA = P1[mt][nt][e0] + P2[mt][nt][e0];
                float GmiA = P4[mt][nt][e0] - P3[mt][nt][e0];
                float GdrB = P1[mt][nt][e1] - P2[mt][nt][e1];
                float GdiB = P3[mt][nt][e1] + P4[mt][nt][e1];
                float GmrB = P1[mt][nt][e1] + P2[mt][nt][e1];
                float GmiB = P4[mt][nt][e1] - P3[mt][nt][e1];
                float dAr[4], dAi[4], mAr[4], mAi[4];
                float dBr[4], dBi[4], mBr[4], mBi[4];
#pragma unroll
                for (int p = 0; p < 4; ++p) {
                    int src = lbase | (p << 2);
                    dAr[p] = __shfl_sync(0xFFFFFFFFu, GdrA, src);
                    dAi[p] = __shfl_sync(0xFFFFFFFFu, GdiA, src);
                    mAr[p] = __shfl_sync(0xFFFFFFFFu, GmrA, src);
                    mAi[p] = __shfl_sync(0xFFFFFFFFu, GmiA, src);
                    dBr[p] = __shfl_sync(0xFFFFFFFFu, GdrB, src);
                    dBi[p] = __shfl_sync(0xFFFFFFFFu, GdiB, src);
                    mBr[p] = __shfl_sync(0xFFFFFFFFu, GmrB, src);
                    mBi[p] = __shfl_sync(0xFFFFFFFFu, GmiB, src);
                }
                // direct: k = c + 256q
                {
                    const float* tA = TB + T_TWD + (jl * 4 + q) * 6;
                    const float* tB = TB + T_TWD + ((jl + 1) * 4 + q) * 6;
                    float XrA, XiA, XrB, XiB;
                    comb4(XrA, XiA, dAr, dAi, tA);
                    comb4(XrB, XiB, dBr, dBi, tB);
                    const float* bA = TB + T_BD + (jl * 4 + q) * 2;
                    const float* bB = TB + T_BD + ((jl + 1) * 4 + q) * 2;
                    int kd = (n0 + jl) + 256 * q;
                    float2 v;
                    v.x = XrA + bA[0]; v.y = XrB + bB[0];
                    *(float2*)(pr + kd) = v;
                    v.x = XiA + bA[1]; v.y = XiB + bB[1];
                    *(float2*)(pi + kd) = v;
                }
                // mirror: col A -> k = (256-c)+256q (skip if 1024), col B -> k-1
                {
                    const float* tA = TB + T_TWM + (jl * 4 + q) * 6;
                    const float* tB = TB + T_TWM + ((jl + 1) * 4 + q) * 6;
                    float XrA, XiA, XrB, XiB;
                    comb4(XrA, XiA, mAr, mAi, tA);
                    comb4(XrB, XiB, mBr, mBi, tB);
                    const float* bA = TB + T_BM + (jl * 4 + q) * 2;
                    const float* bB = TB + T_BM + ((jl + 1) * 4 + q) * 2;
                    int kmA = 256 - (n0 + jl) + 256 * q;
                    pr[kmA - 1] = XrB + bB[0];
                    pi[kmA - 1] = XiB + bB[1];
                    if (kmA < 1024) {
                        pr[kmA] = XrA + bA[0];
                        pi[kmA] = XiA + bA[1];
                    }
                }
            }
        }
}

// ---------------- launch ----------------
extern "C" void kernel_launch(void* const* d_in, const int* in_sizes, int n_in,
                              void* d_out, int out_size) {
    (void)in_sizes; (void)n_in; (void)out_size;
    const float4* xr = (const float4*)d_in[0];
    const float4* xi = (const float4*)d_in[1];
    const float4* wr = (const float4*)d_in[2];
    const float4* wi = (const float4*)d_in[3];
    const float*  br = (const float*)d_in[4];
    const float*  bi = (const float*)d_in[5];
    float* out_real = (float*)d_out;
    float* out_imag = out_real + (size_t)M_SIG * 1024;

    convert_x_kernel<<<8192, 256>>>(xr, xi);
    convert_w_kernel<<<16, 256>>>(wr, wi);
    col128_kernel<<<4096, 256>>>(br, bi, (const float*)d_in[2], (const float*)d_in[3],
                                 out_real, out_imag);

    cudaFuncSetAttribute(dft_gemm_kernel,
                         cudaFuncAttributeMaxDynamicSharedMemorySize, SMEM_TOTAL);
    dim3 grid(128 / BN, MR / BM);   // (2, 2048)
    dft_gemm_kernel<<<grid, THREADS, SMEM_TOTAL>>>(br, bi,
                                                   (const float*)d_in[2],
                                                   (const float*)d_in[3],
                                                   out_real, out_imag);
}

// round 10
// speedup vs baseline: 2.6758x; 1.2204x over previous
#include <cuda_runtime.h>
#include <cuda_fp16.h>
#include <cstdint>

#define DINL __device__ __forceinline__

// ---------------- problem sizes ----------------
static constexpr int M_SIG = 32768;        // independent signals
static constexpr int MR    = 131072;       // scratch rows: 4 phases per signal
static constexpr int BM = 64;              // scratch rows per m-tile
static constexpr int BN = 64;              // direct W256 cols per CTA (of 128)
static constexpr int MITER = 2;            // m-tiles per CTA
static constexpr int NITER = 4 * MITER;    // 8 linear chunks
static constexpr int THREADS = 256;

// ---------------- smem layout (bytes) ----------------
static constexpr uint32_t OFF_B  = 0;       // 4 chunks x (wr 8KB + wi 8KB) = 64KB resident
static constexpr uint32_t OFF_A  = 65536;   // 2 stages x (xr 8KB + xi 8KB) = 32KB
static constexpr uint32_t SM_TAB = 98304;   // tables: 4096 floats = 16384B -> ends 114688
static constexpr uint32_t MB_B   = 114688;  // mbarriers (AFTER the full table region)
static constexpr uint32_t MB_A0  = 114696;
static constexpr uint32_t MB_A1  = 114704;
static constexpr uint32_t SMEM_TOTAL = 114816;   // x2 CTA = 229632 <= 232448

// table float offsets
static constexpr int T_TWD = 0;      // [64][4][6]   = 1536 floats
static constexpr int T_TWM = 1536;   // [64][4][6]   = 1536 floats
static constexpr int T_BD  = 3072;   // [64][4][2]   = 512 floats
static constexpr int T_BM  = 3584;   // [64][4][2]   = 512 floats (ends at 4096)

// ---------------- global scratch: PRE-SWIZZLED 8KB tiles ----------------
// A: tile index (mtile*4 + chunk), mtile = scratch_row/64, chunk = kcol/64.
// Inside a tile: 64 rows x 128B, SW128-swizzled.
__device__ __align__(128) __half g_xr_t[33554432];
__device__ __align__(128) __half g_xi_t[33554432];
// B: tile index (h*4 + chunk), h = W256row/64.
__device__ __align__(128) __half g_wr_t[32768];
__device__ __align__(128) __half g_wi_t[32768];
// twiddles: g_tw[k] = (w1024_real[k][1], w1024_imag[k][1])
__device__ __align__(16) float2 g_tw[1024];

// ---------------- PTX helpers ----------------
DINL uint32_t swz(uint32_t o) { return o ^ ((o >> 3) & 0x70); }

DINL void mbar_init(uint32_t a, uint32_t cnt) {
    asm volatile("mbarrier.init.shared.b64 [%0], %1;\n" :: "r"(a), "r"(cnt) : "memory");
}
DINL void mbar_expect(uint32_t a, uint32_t bytes) {
    asm volatile("mbarrier.arrive.expect_tx.shared.b64 _, [%0], %1;\n"
                 :: "r"(a), "r"(bytes) : "memory");
}
DINL void mbar_wait(uint32_t a, uint32_t parity) {
    asm volatile(
        "{\n\t.reg .pred P;\n"
        "WLP_%=:\n\t"
        "mbarrier.try_wait.parity.acquire.cta.shared::cta.b64 P, [%0], %1, 0x989680;\n\t"
        "@!P bra WLP_%=;\n\t"
        "}\n" :: "r"(a), "r"(parity) : "memory");
}
DINL void bulk_g2s(uint32_t dst, const void* src, uint32_t bytes, uint32_t mbar) {
    asm volatile(
        "cp.async.bulk.shared::cta.global.mbarrier::complete_tx::bytes [%0], [%1], %2, [%3];\n"
        :: "r"(dst), "l"(src), "r"(bytes), "r"(mbar) : "memory");
}

DINL void ldsm4(uint32_t* r, uint32_t a) {
    asm volatile("ldmatrix.sync.aligned.m8n8.x4.shared.b16 {%0,%1,%2,%3}, [%4];\n"
                 : "=r"(r[0]), "=r"(r[1]), "=r"(r[2]), "=r"(r[3]) : "r"(a));
}

DINL void mma16816(float* d, const uint32_t* a, uint32_t b0, uint32_t b1) {
    asm volatile(
        "mma.sync.aligned.m16n8k16.row.col.f32.f16.f16.f32 "
        "{%0,%1,%2,%3}, {%4,%5,%6,%7}, {%8,%9}, {%0,%1,%2,%3};\n"
        : "+f"(d[0]), "+f"(d[1]), "+f"(d[2]), "+f"(d[3])
        : "r"(a[0]), "r"(a[1]), "r"(a[2]), "r"(a[3]), "r"(b0), "r"(b1));
}

// ---------------- conversion ----------------
DINL uint32_t h2u(float a, float b) {
    __half2 h = __floats2half2_rn(a, b);
    return *(uint32_t*)&h;
}

// twiddle pre-gather: g_tw[k] = (wr[k][1], wi[k][1])
__global__ void __launch_bounds__(256) tw_gather_kernel(const float* __restrict__ wr,
                                                        const float* __restrict__ wi) {
    int k = blockIdx.x * 256 + threadIdx.x;   // 1024 threads
    g_tw[k] = make_float2(wr[((size_t)k << 10) + 1], wi[((size_t)k << 10) + 1]);
}

// 4-phase deinterleave -> pre-swizzled tiles.
__global__ void __launch_bounds__(256) convert_x_kernel(const float4* __restrict__ xr,
                                                        const float4* __restrict__ xi) {
    size_t gid = (size_t)blockIdx.x * 256 + threadIdx.x;   // 2M threads
    size_t m = gid >> 6;
    int j = (int)(gid & 63);
    const int c = j >> 4;                                  // k-chunk
    const uint32_t inb = (uint32_t)((j & 15) << 3);        // byte col in row
    char* bxr = (char*)g_xr_t + (((m >> 4) * 4 + c) << 13);
    char* bxi = (char*)g_xi_t + (((m >> 4) * 4 + c) << 13);
    const int rb = 4 * (int)(m & 15);
    {
        const float4* p = xr + (m << 8) + (j << 2);
        float4 f0 = p[0], f1 = p[1], f2 = p[2], f3 = p[3];
        uint2 v;
        v.x = h2u(f0.x, f1.x); v.y = h2u(f2.x, f3.x);
        *(uint2*)(bxr + swz(((rb + 0) << 7) | inb)) = v;
        v.x = h2u(f0.y, f1.y); v.y = h2u(f2.y, f3.y);
        *(uint2*)(bxr + swz(((rb + 1) << 7) | inb)) = v;
        v.x = h2u(f0.z, f1.z); v.y = h2u(f2.z, f3.z);
        *(uint2*)(bxr + swz(((rb + 2) << 7) | inb)) = v;
        v.x = h2u(f0.w, f1.w); v.y = h2u(f2.w, f3.w);
        *(uint2*)(bxr + swz(((rb + 3) << 7) | inb)) = v;
    }
    {
        const float4* p = xi + (m << 8) + (j << 2);
        float4 f0 = p[0], f1 = p[1], f2 = p[2], f3 = p[3];
        uint2 v;
        v.x = h2u(f0.x, f1.x); v.y = h2u(f2.x, f3.x);
        *(uint2*)(bxi + swz(((rb + 0) << 7) | inb)) = v;
        v.x = h2u(f0.y, f1.y); v.y = h2u(f2.y, f3.y);
        *(uint2*)(bxi + swz(((rb + 1) << 7) | inb)) = v;
        v.x = h2u(f0.z, f1.z); v.y = h2u(f2.z, f3.z);
        *(uint2*)(bxi + swz(((rb + 2) << 7) | inb)) = v;
        v.x = h2u(f0.w, f1.w); v.y = h2u(f2.w, f3.w);
        *(uint2*)(bxi + swz(((rb + 3) << 7) | inb)) = v;
    }
}

// W256 rows 0..127 (= w1024 rows 4k, first 256 cols) -> pre-swizzled tiles
__global__ void __launch_bounds__(256) convert_w_kernel(const float4* __restrict__ wr,
                                                        const float4* __restrict__ wi) {
    size_t gid = (size_t)blockIdx.x * 256 + threadIdx.x;   // 4096 threads
    size_t k = gid >> 5;                                   // W256 row 0..127
    int j = (int)(gid & 31);                               // 8-half group
    size_t src = (k << 10) + (j << 1);                     // float4 idx into w1024 row 4k
    const int h = (int)(k >> 6), r = (int)(k & 63), c = j >> 3;
    uint32_t off = swz((uint32_t)((r << 7) | ((j & 7) << 4)));
    char* bwr = (char*)g_wr_t + (((h * 4 + c)) << 13);
    char* bwi = (char*)g_wi_t + (((h * 4 + c)) << 13);
    float4 a = wr[src], b = wr[src + 1];
    uint4 u;
    u.x = h2u(a.x, a.y); u.y = h2u(a.z, a.w);
    u.z = h2u(b.x, b.y); u.w = h2u(b.z, b.w);
    *(uint4*)(bwr + off) = u;
    float4 cc = wi[src], d = wi[src + 1];
    u.x = h2u(cc.x, cc.y); u.y = h2u(cc.z, cc.w);
    u.z = h2u(d.x, d.y); u.w = h2u(d.z, d.w);
    *(uint4*)(bwi + off) = u;
}

// ---------------- special cols: k in {128,384,640,896} ----------------
DINL float altsum(uint4 v) {
    const __half2* h = (const __half2*)&v;
    float s = 0.f;
#pragma unroll
    for (int j = 0; j < 4; ++j) { float2 f = __half22float2(h[j]); s += f.x - f.y; }
    return s;
}

__global__ void __launch_bounds__(256) col128_kernel(const float* __restrict__ b_real,
                                                     const float* __restrict__ b_imag,
                                                     float* __restrict__ out_real,
                                                     float* __restrict__ out_imag) {
    int s = blockIdx.x * 8 + (threadIdx.x >> 5);       // one warp per signal
    int lane = threadIdx.x & 31;
    const int c = lane >> 3, u = lane & 7;             // chunk, 16B unit
    const size_t t = (size_t)(s >> 4);
    const int rb = 4 * (s & 15);
    float g[8];
#pragma unroll
    for (int p = 0; p < 4; ++p) {
        uint32_t off = swz((uint32_t)(((rb + p) << 7) | (u << 4)));
        size_t tb = ((t * 4 + c) << 13);
        g[2 * p]     = altsum(*(const uint4*)((const char*)g_xr_t + tb + off));
        g[2 * p + 1] = altsum(*(const uint4*)((const char*)g_xi_t + tb + off));
    }
#pragma unroll
    for (int sh = 16; sh > 0; sh >>= 1)
#pragma unroll
        for (int v = 0; v < 8; ++v) g[v] += __shfl_xor_sync(0xFFFFFFFFu, g[v], sh);
    if (lane == 0) {
        const int rows[6] = {128, 256, 384, 640, 768, 896};
        float twr[6], twi[6];
#pragma unroll
        for (int v = 0; v < 6; ++v) { float2 w = g_tw[rows[v]]; twr[v] = w.x; twi[v] = w.y; }
        size_t o = ((size_t)s << 10);
        const int ks[4] = {128, 384, 640, 896};
        const int ia[4] = {0, 2, 3, 5};
        const int ib[4] = {1, 4, 1, 4};
        const int ic[4] = {2, 0, 5, 3};
#pragma unroll
        for (int v = 0; v < 4; ++v) {
            float ar = twr[ia[v]], ai = twi[ia[v]];
            float br2 = twr[ib[v]], bi2 = twi[ib[v]];
            float cr = twr[ic[v]], ci = twi[ic[v]];
            float Xr = g[0] + ar * g[2] - ai * g[3] + br2 * g[4] - bi2 * g[5]
                            + cr * g[6] - ci * g[7];
            float Xi = g[1] + ar * g[3] + ai * g[2] + br2 * g[5] + bi2 * g[4]
                            + cr * g[7] + ci * g[6];
            int k = ks[v];
            float br = b_real[k], bi = b_imag[k];
            out_real[o + k] = Xr + (br - bi);
            out_imag[o + k] = Xi + (br + bi);
        }
    }
}

// combine X = G0 + t1*G1 + t2*G2 + t3*G3
DINL void comb4(float& Xr, float& Xi, const float* gr_, const float* gi_, const float* t) {
    Xr = gr_[0] + t[0] * gr_[1] - t[1] * gi_[1]
                + t[2] * gr_[2] - t[3] * gi_[2]
                + t[4] * gr_[3] - t[5] * gi_[3];
    Xi = gi_[0] + t[0] * gi_[1] + t[1] * gr_[1]
                + t[2] * gi_[2] + t[3] * gr_[2]
                + t[4] * gi_[3] + t[5] * gr_[3];
}

// ---------------- main GEMM kernel (bulk-copy, persistent, radix-4 fused) -----
__global__ void __launch_bounds__(THREADS, 2)
dft_gemm_kernel(const float* __restrict__ b_real, const float* __restrict__ b_imag,
                float* __restrict__ out_real, float* __restrict__ out_imag) {
    extern __shared__ __align__(1024) char sm[];
    uint32_t sb = (uint32_t)__cvta_generic_to_shared(sm);
    const int tid = threadIdx.x, wid = tid >> 5, lid = tid & 31;
    const int h = blockIdx.x;                          // n-half: n0 = 64h
    const int n0 = h * BN;
    const int tile0 = blockIdx.y * MITER;              // base m-tile
    const int wm = (wid >> 2) * 32;
    const int wn = (wid & 3) * 16;

    if (tid == 0) {
        mbar_init(sb + MB_B, 1);
        mbar_init(sb + MB_A0, 1);
        mbar_init(sb + MB_A1, 1);
    }
    __syncthreads();
    if (tid == 0) {
        mbar_expect(sb + MB_B, 65536);
#pragma unroll
        for (int c = 0; c < 4; ++c) {
            bulk_g2s(sb + OFF_B + c * 16384,
                     (const char*)g_wr_t + (((size_t)(h * 4 + c)) << 13), 8192, sb + MB_B);
            bulk_g2s(sb + OFF_B + c * 16384 + 8192,
                     (const char*)g_wi_t + (((size_t)(h * 4 + c)) << 13), 8192, sb + MB_B);
        }
        mbar_expect(sb + MB_A0, 16384);
        bulk_g2s(sb + OFF_A,
                 (const char*)g_xr_t + (((size_t)(tile0 * 4 + 0)) << 13), 8192, sb + MB_A0);
        bulk_g2s(sb + OFF_A + 8192,
                 (const char*)g_xi_t + (((size_t)(tile0 * 4 + 0)) << 13), 8192, sb + MB_A0);
        mbar_expect(sb + MB_A1, 16384);
        bulk_g2s(sb + OFF_A + 16384,
                 (const char*)g_xr_t + (((size_t)(tile0 * 4 + 1)) << 13), 8192, sb + MB_A1);
        bulk_g2s(sb + OFF_A + 16384 + 8192,
                 (const char*)g_xi_t + (((size_t)(tile0 * 4 + 1)) << 13), 8192, sb + MB_A1);
    }

    // stage twiddle/bias tables (coalesced; overlaps bulk loads)
    float* TB = (float*)(sm + SM_TAB);
    {
        int j = tid & 63, q4 = tid >> 6;
        int c = n0 + j;
        int kd = c + 256 * q4;
        int km = (256 - c + 256 * q4) & 1023;
        int base = (j * 4 + q4) * 6;
        float2 w1 = g_tw[kd], w2 = g_tw[(2 * kd) & 1023], w3 = g_tw[(3 * kd) & 1023];
        TB[T_TWD + base + 0] = w1.x; TB[T_TWD + base + 1] = w1.y;
        TB[T_TWD + base + 2] = w2.x; TB[T_TWD + base + 3] = w2.y;
        TB[T_TWD + base + 4] = w3.x; TB[T_TWD + base + 5] = w3.y;
        w1 = g_tw[km]; w2 = g_tw[(2 * km) & 1023]; w3 = g_tw[(3 * km) & 1023];
        TB[T_TWM + base + 0] = w1.x; TB[T_TWM + base + 1] = w1.y;
        TB[T_TWM + base + 2] = w2.x; TB[T_TWM + base + 3] = w2.y;
        TB[T_TWM + base + 4] = w3.x; TB[T_TWM + base + 5] = w3.y;
        int bb = (j * 4 + q4) * 2;
        float a = b_real[kd], b = b_imag[kd];
        TB[T_BD + bb] = a - b; TB[T_BD + bb + 1] = a + b;
        a = b_real[km]; b = b_imag[km];
        TB[T_BM + bb] = a - b; TB[T_BM + bb + 1] = a + b;
    }
    __syncthreads();
    mbar_wait(sb + MB_B, 0);

    float P1[2][2][4], P2[2][2][4], P3[2][2][4], P4[2][2][4];
#pragma unroll
    for (int a = 0; a < 2; ++a)
#pragma unroll
        for (int b = 0; b < 2; ++b)
#pragma unroll
            for (int c = 0; c < 4; ++c) {
                P1[a][b][c] = 0.f; P2[a][b][c] = 0.f;
                P3[a][b][c] = 0.f; P4[a][b][c] = 0.f;
            }

    const int lrow = lid & 15;
    const int lcb  = (lid >> 4) << 4;
    const int gr = lid >> 2, gc = lid & 3;
    const int q  = gr & 3;
    const int lbase = lid & ~12;

    for (int i = 0; i < NITER; ++i) {
        mbar_wait(sb + MB_A0 + (uint32_t)((i & 1) * 8), (uint32_t)((i >> 1) & 1));
        const uint32_t stA = sb + OFF_A + (i & 1) * 16384;
        const uint32_t stB = sb + OFF_B + (i & 3) * 16384;
#pragma unroll
        for (int kk = 0; kk < 4; ++kk) {
            const uint32_t colb = (uint32_t)(kk * 32 + lcb);
            uint32_t Axr[2][4], Axi[2][4];
#pragma unroll
            for (int mt = 0; mt < 2; ++mt) {
                uint32_t ro = (uint32_t)((wm + mt * 16 + lrow) << 7) + colb;
                ldsm4(Axr[mt], stA + swz(ro));
                ldsm4(Axi[mt], stA + 8192 + swz(ro));
            }
            uint32_t Bwr[4], Bwi[4], t4[4];
            {
                uint32_t ro = (uint32_t)((wn + lrow) << 7) + colb;
                ldsm4(t4, stB + swz(ro));
                Bwr[0] = t4[0]; Bwr[1] = t4[2]; Bwr[2] = t4[1]; Bwr[3] = t4[3];
                ldsm4(t4, stB + 8192 + swz(ro));
                Bwi[0] = t4[0]; Bwi[1] = t4[2]; Bwi[2] = t4[1]; Bwi[3] = t4[3];
            }
#pragma unroll
            for (int mt = 0; mt < 2; ++mt)
#pragma unroll
                for (int nt = 0; nt < 2; ++nt) {
                    const int ob = nt * 2;
                    mma16816(P1[mt][nt], Axr[mt], Bwr[ob], Bwr[ob + 1]);
                    mma16816(P2[mt][nt], Axi[mt], Bwi[ob], Bwi[ob + 1]);
                    mma16816(P3[mt][nt], Axr[mt], Bwi[ob], Bwi[ob + 1]);
                    mma16816(P4[mt][nt], Axi[mt], Bwr[ob], Bwr[ob + 1]);
                }
        }
        __syncthreads();                               // all warps done with stage i&1
        if (i + 2 < NITER && tid == 0) {
            int l = i + 2, mi2 = l >> 2, c2 = l & 3;
            uint32_t mb = sb + MB_A0 + (uint32_t)((i & 1) * 8);
            mbar_expect(mb, 16384);
            bulk_g2s(sb + OFF_A + (i & 1) * 16384,
                     (const char*)g_xr_t + (((size_t)((tile0 + mi2) * 4 + c2)) << 13), 8192, mb);
            bulk_g2s(sb + OFF_A + (i & 1) * 16384 + 8192,
                     (const char*)g_xi_t + (((size_t)((tile0 + mi2) * 4 + c2)) << 13), 8192, mb);
        }

        if ((i & 3) == 3) {
            // ------------- fused 4-phase combine epilogue for m-tile i>>2 -------------
            const int m0 = (tile0 + (i >> 2)) * BM;
#pragma unroll
            for (int mt = 0; mt < 2; ++mt)
#pragma unroll
                for (int nt = 0; nt < 2; ++nt) {
                    const int jl = wn + nt * 8 + gc * 2;
#pragma unroll
                    for (int rg = 0; rg < 2; ++rg) {
                        const int e0 = rg * 2, e1 = e0 + 1;
                        size_t s = (size_t)(m0 >> 2) + (wm >> 2) + mt * 4 + rg * 2 + (gr >> 2);
                        float* pr = out_real + (s << 10);
                        float* pi = out_imag + (s << 10);
                        float GdrA = P1[mt][nt][e0] - P2[mt][nt][e0];
                        float GdiA = P3[mt][nt][e0] + P4[mt][nt][e0];
                        float GmrA = P1[mt][nt][e0] + P2[mt][nt][e0];
                        float GmiA = P4[mt][nt][e0] - P3[mt][nt][e0];
                        float GdrB = P1[mt][nt][e1] - P2[mt][nt][e1];
                        float GdiB = P3[mt][nt][e1] + P4[mt][nt][e1];
                        float GmrB = P1[mt][nt][e1] + P2[mt][nt][e1];
                        float GmiB = P4[mt][nt][e1] - P3[mt][nt][e1];
                        float dAr[4], dAi[4], mAr[4], mAi[4];
                        float dBr[4], dBi[4], mBr[4], mBi[4];
#pragma unroll
                        for (int p = 0; p < 4; ++p) {
                            int src = lbase | (p << 2);
                            dAr[p] = __shfl_sync(0xFFFFFFFFu, GdrA, src);
                            dAi[p] = __shfl_sync(0xFFFFFFFFu, GdiA, src);
                            mAr[p] = __shfl_sync(0xFFFFFFFFu, GmrA, src);
                            mAi[p] = __shfl_sync(0xFFFFFFFFu, GmiA, src);
                            dBr[p] = __shfl_sync(0xFFFFFFFFu, GdrB, src);
                            dBi[p] = __shfl_sync(0xFFFFFFFFu, GdiB, src);
                            mBr[p] = __shfl_sync(0xFFFFFFFFu, GmrB, src);
                            mBi[p] = __shfl_sync(0xFFFFFFFFu, GmiB, src);
                        }
                        {
                            const float* tA = TB + T_TWD + (jl * 4 + q) * 6;
                            const float* tB2 = TB + T_TWD + ((jl + 1) * 4 + q) * 6;
                            float XrA, XiA, XrB, XiB;
                            comb4(XrA, XiA, dAr, dAi, tA);
                            comb4(XrB, XiB, dBr, dBi, tB2);
                            const float* bA = TB + T_BD + (jl * 4 + q) * 2;
                            const float* bB = TB + T_BD + ((jl + 1) * 4 + q) * 2;
                            int kd = (n0 + jl) + 256 * q;
                            float2 v;
                            v.x = XrA + bA[0]; v.y = XrB + bB[0];
                            *(float2*)(pr + kd) = v;
                            v.x = XiA + bA[1]; v.y = XiB + bB[1];
                            *(float2*)(pi + kd) = v;
                        }
                        {
                            const float* tA = TB + T_TWM + (jl * 4 + q) * 6;
                            const float* tB2 = TB + T_TWM + ((jl + 1) * 4 + q) * 6;
                            float XrA, XiA, XrB, XiB;
                            comb4(XrA, XiA, mAr, mAi, tA);
                            comb4(XrB, XiB, mBr, mBi, tB2);
                            const float* bA = TB + T_BM + (jl * 4 + q) * 2;
                            const float* bB = TB + T_BM + ((jl + 1) * 4 + q) * 2;
                            int kmA = 256 - (n0 + jl) + 256 * q;
                            pr[kmA - 1] = XrB + bB[0];
                            pi[kmA - 1] = XiB + bB[1];
                            if (kmA < 1024) {
                                pr[kmA] = XrA + bA[0];
                                pi[kmA] = XiA + bA[1];
                            }
                        }
                    }
                }
            // zero accumulators for next m-tile
#pragma unroll
            for (int a = 0; a < 2; ++a)
#pragma unroll
                for (int b = 0; b < 2; ++b)
#pragma unroll
                    for (int c = 0; c < 4; ++c) {
                        P1[a][b][c] = 0.f; P2[a][b][c] = 0.f;
                        P3[a][b][c] = 0.f; P4[a][b][c] = 0.f;
                    }
        }
    }
}

// ---------------- launch ----------------
extern "C" void kernel_launch(void* const* d_in, const int* in_sizes, int n_in,
                              void* d_out, int out_size) {
    (void)in_sizes; (void)n_in; (void)out_size;
    const float4* xr = (const float4*)d_in[0];
    const float4* xi = (const float4*)d_in[1];
    const float*  wr = (const float*)d_in[2];
    const float*  wi = (const float*)d_in[3];
    const float*  br = (const float*)d_in[4];
    const float*  bi = (const float*)d_in[5];
    float* out_real = (float*)d_out;
    float* out_imag = out_real + (size_t)M_SIG * 1024;

    tw_gather_kernel<<<4, 256>>>(wr, wi);
    convert_x_kernel<<<8192, 256>>>(xr, xi);
    convert_w_kernel<<<16, 256>>>((const float4*)wr, (const float4*)wi);
    col128_kernel<<<4096, 256>>>(br, bi, out_real, out_imag);

    cudaFuncSetAttribute(dft_gemm_kernel,
                         cudaFuncAttributeMaxDynamicSharedMemorySize, SMEM_TOTAL);
    dim3 grid(128 / BN, (MR / BM) / MITER);   // (2, 1024)
    dft_gemm_kernel<<<grid, THREADS, SMEM_TOTAL>>>(br, bi, out_real, out_imag);
}

// round 11
// speedup vs baseline: 2.9315x; 1.0955x over previous
#include <cuda_runtime.h>
#include <cuda_fp16.h>
#include <cstdint>

#define DINL __device__ __forceinline__

// ---------------- problem sizes ----------------
static constexpr int M_SIG = 32768;        // independent signals
static constexpr int MR    = 131072;       // scratch rows: 4 phases per signal
static constexpr int BM = 64;              // scratch rows per m-tile
static constexpr int BN = 64;              // direct W256 cols per CTA (of 128)
static constexpr int MITER = 2;            // m-tiles per CTA
static constexpr int NITER = 4 * MITER;    // 8 linear chunks
static constexpr int THREADS = 256;

// ---------------- smem layout (bytes) ----------------
static constexpr uint32_t OFF_B  = 0;       // 4 chunks x (wr 8KB + wi 8KB) = 64KB resident
static constexpr uint32_t OFF_A  = 65536;   // 2 stages x (xr 8KB + xi 8KB) = 32KB
static constexpr uint32_t SM_TAB = 98304;   // tables: 4096 floats = 16384B -> ends 114688
static constexpr uint32_t MB_B   = 114688;  // mbarriers (AFTER the full table region)
static constexpr uint32_t MB_A0  = 114696;
static constexpr uint32_t MB_A1  = 114704;
static constexpr uint32_t SMEM_TOTAL = 114816;   // x2 CTA = 229632 <= 232448

// table float offsets
static constexpr int T_TWD = 0;      // [64][4][6]   = 1536 floats
static constexpr int T_TWM = 1536;   // [64][4][6]   = 1536 floats
static constexpr int T_BD  = 3072;   // [64][4][2]   = 512 floats
static constexpr int T_BM  = 3584;   // [64][4][2]   = 512 floats (ends at 4096)

// ---------------- global scratch: PRE-SWIZZLED 8KB tiles ----------------
__device__ __align__(128) __half g_xr_t[33554432];
__device__ __align__(128) __half g_xi_t[33554432];
__device__ __align__(128) __half g_wr_t[32768];
__device__ __align__(128) __half g_wi_t[32768];
// twiddles: g_tw[k] = (w1024_real[k][1], w1024_imag[k][1])
__device__ __align__(16) float2 g_tw[1024];
// col128 partials: per signal 16 floats = [half0: pr0..3,pi0..3][half1: ...]
__device__ __align__(16) float g_part[524288];

// ---------------- PTX helpers ----------------
DINL uint32_t swz(uint32_t o) { return o ^ ((o >> 3) & 0x70); }

DINL void mbar_init(uint32_t a, uint32_t cnt) {
    asm volatile("mbarrier.init.shared.b64 [%0], %1;\n" :: "r"(a), "r"(cnt) : "memory");
}
DINL void mbar_expect(uint32_t a, uint32_t bytes) {
    asm volatile("mbarrier.arrive.expect_tx.shared.b64 _, [%0], %1;\n"
                 :: "r"(a), "r"(bytes) : "memory");
}
DINL void mbar_wait(uint32_t a, uint32_t parity) {
    asm volatile(
        "{\n\t.reg .pred P;\n"
        "WLP_%=:\n\t"
        "mbarrier.try_wait.parity.acquire.cta.shared::cta.b64 P, [%0], %1, 0x989680;\n\t"
        "@!P bra WLP_%=;\n\t"
        "}\n" :: "r"(a), "r"(parity) : "memory");
}
DINL void bulk_g2s(uint32_t dst, const void* src, uint32_t bytes, uint32_t mbar) {
    asm volatile(
        "cp.async.bulk.shared::cta.global.mbarrier::complete_tx::bytes [%0], [%1], %2, [%3];\n"
        :: "r"(dst), "l"(src), "r"(bytes), "r"(mbar) : "memory");
}

DINL void ldsm4(uint32_t* r, uint32_t a) {
    asm volatile("ldmatrix.sync.aligned.m8n8.x4.shared.b16 {%0,%1,%2,%3}, [%4];\n"
                 : "=r"(r[0]), "=r"(r[1]), "=r"(r[2]), "=r"(r[3]) : "r"(a));
}

DINL void mma16816(float* d, const uint32_t* a, uint32_t b0, uint32_t b1) {
    asm volatile(
        "mma.sync.aligned.m16n8k16.row.col.f32.f16.f16.f32 "
        "{%0,%1,%2,%3}, {%4,%5,%6,%7}, {%8,%9}, {%0,%1,%2,%3};\n"
        : "+f"(d[0]), "+f"(d[1]), "+f"(d[2]), "+f"(d[3])
        : "r"(a[0]), "r"(a[1]), "r"(a[2]), "r"(a[3]), "r"(b0), "r"(b1));
}

// ---------------- conversion ----------------
DINL uint32_t h2u(float a, float b) {
    __half2 h = __floats2half2_rn(a, b);
    return *(uint32_t*)&h;
}

// 4-phase deinterleave -> pre-swizzled tiles + fused col128 partial sums.
__global__ void __launch_bounds__(256) convert_x_kernel(const float4* __restrict__ xr,
                                                        const float4* __restrict__ xi) {
    size_t gid = (size_t)blockIdx.x * 256 + threadIdx.x;   // 2M threads
    size_t m = gid >> 6;
    int j = (int)(gid & 63);
    const int c = j >> 4;                                  // k-chunk
    const uint32_t inb = (uint32_t)((j & 15) << 3);        // byte col in row
    char* bxr = (char*)g_xr_t + (((m >> 4) * 4 + c) << 13);
    char* bxi = (char*)g_xi_t + (((m >> 4) * 4 + c) << 13);
    const int rb = 4 * (int)(m & 15);
    float pr[4], pq[4];                                    // col128 partials (re/im)
    {
        const float4* p = xr + (m << 8) + (j << 2);
        float4 f0 = p[0], f1 = p[1], f2 = p[2], f3 = p[3];
        uint2 v;
        v.x = h2u(f0.x, f1.x); v.y = h2u(f2.x, f3.x);
        *(uint2*)(bxr + swz(((rb + 0) << 7) | inb)) = v;
        v.x = h2u(f0.y, f1.y); v.y = h2u(f2.y, f3.y);
        *(uint2*)(bxr + swz(((rb + 1) << 7) | inb)) = v;
        v.x = h2u(f0.z, f1.z); v.y = h2u(f2.z, f3.z);
        *(uint2*)(bxr + swz(((rb + 2) << 7) | inb)) = v;
        v.x = h2u(f0.w, f1.w); v.y = h2u(f2.w, f3.w);
        *(uint2*)(bxr + swz(((rb + 3) << 7) | inb)) = v;
        pr[0] = f0.x - f1.x + f2.x - f3.x;
        pr[1] = f0.y - f1.y + f2.y - f3.y;
        pr[2] = f0.z - f1.z + f2.z - f3.z;
        pr[3] = f0.w - f1.w + f2.w - f3.w;
    }
    {
        const float4* p = xi + (m << 8) + (j << 2);
        float4 f0 = p[0], f1 = p[1], f2 = p[2], f3 = p[3];
        uint2 v;
        v.x = h2u(f0.x, f1.x); v.y = h2u(f2.x, f3.x);
        *(uint2*)(bxi + swz(((rb + 0) << 7) | inb)) = v;
        v.x = h2u(f0.y, f1.y); v.y = h2u(f2.y, f3.y);
        *(uint2*)(bxi + swz(((rb + 1) << 7) | inb)) = v;
        v.x = h2u(f0.z, f1.z); v.y = h2u(f2.z, f3.z);
        *(uint2*)(bxi + swz(((rb + 2) << 7) | inb)) = v;
        v.x = h2u(f0.w, f1.w); v.y = h2u(f2.w, f3.w);
        *(uint2*)(bxi + swz(((rb + 3) << 7) | inb)) = v;
        pq[0] = f0.x - f1.x + f2.x - f3.x;
        pq[1] = f0.y - f1.y + f2.y - f3.y;
        pq[2] = f0.z - f1.z + f2.z - f3.z;
        pq[3] = f0.w - f1.w + f2.w - f3.w;
    }
    // warp-level reduction: all 32 lanes of this warp belong to the same signal
#pragma unroll
    for (int sh = 16; sh > 0; sh >>= 1) {
#pragma unroll
        for (int v = 0; v < 4; ++v) {
            pr[v] += __shfl_xor_sync(0xFFFFFFFFu, pr[v], sh);
            pq[v] += __shfl_xor_sync(0xFFFFFFFFu, pq[v], sh);
        }
    }
    if ((threadIdx.x & 31) == 0) {
        size_t base = (m << 4) + (size_t)((j >> 5) << 3);
        *(float4*)(g_part + base)     = make_float4(pr[0], pr[1], pr[2], pr[3]);
        *(float4*)(g_part + base + 4) = make_float4(pq[0], pq[1], pq[2], pq[3]);
    }
}

// W256 rows -> pre-swizzled tiles; first 1024 threads also gather twiddles
__global__ void __launch_bounds__(256) convert_w_kernel(const float4* __restrict__ wr,
                                                        const float4* __restrict__ wi) {
    size_t gid = (size_t)blockIdx.x * 256 + threadIdx.x;   // 4096 threads
    if (gid < 1024) {
        g_tw[gid] = make_float2(((const float*)wr)[(gid << 10) + 1],
                                ((const float*)wi)[(gid << 10) + 1]);
    }
    size_t k = gid >> 5;                                   // W256 row 0..127
    int j = (int)(gid & 31);                               // 8-half group
    size_t src = (k << 10) + (j << 1);                     // float4 idx into w1024 row 4k
    const int h = (int)(k >> 6), r = (int)(k & 63), c = j >> 3;
    uint32_t off = swz((uint32_t)((r << 7) | ((j & 7) << 4)));
    char* bwr = (char*)g_wr_t + (((h * 4 + c)) << 13);
    char* bwi = (char*)g_wi_t + (((h * 4 + c)) << 13);
    float4 a = wr[src], b = wr[src + 1];
    uint4 u;
    u.x = h2u(a.x, a.y); u.y = h2u(a.z, a.w);
    u.z = h2u(b.x, b.y); u.w = h2u(b.z, b.w);
    *(uint4*)(bwr + off) = u;
    float4 cc = wi[src], d = wi[src + 1];
    u.x = h2u(cc.x, cc.y); u.y = h2u(cc.z, cc.w);
    u.z = h2u(d.x, d.y); u.w = h2u(d.z, d.w);
    *(uint4*)(bwi + off) = u;
}

// ---------------- special cols from partials: k in {128,384,640,896} ----------
__global__ void __launch_bounds__(256) col128_kernel(const float* __restrict__ b_real,
                                                     const float* __restrict__ b_imag,
                                                     float* __restrict__ out_real,
                                                     float* __restrict__ out_imag) {
    int s = blockIdx.x * 256 + threadIdx.x;            // one thread per signal
    float4 h0r = *(const float4*)(g_part + ((size_t)s << 4));
    float4 h0i = *(const float4*)(g_part + ((size_t)s << 4) + 4);
    float4 h1r = *(const float4*)(g_part + ((size_t)s << 4) + 8);
    float4 h1i = *(const float4*)(g_part + ((size_t)s << 4) + 12);
    float g[8];
    g[0] = h0r.x + h1r.x; g[1] = h0i.x + h1i.x;        // G0 re/im
    g[2] = h0r.y + h1r.y; g[3] = h0i.y + h1i.y;        // G1
    g[4] = h0r.z + h1r.z; g[5] = h0i.z + h1i.z;        // G2
    g[6] = h0r.w + h1r.w; g[7] = h0i.w + h1i.w;        // G3
    const int rows[6] = {128, 256, 384, 640, 768, 896};
    float twr[6], twi[6];
#pragma unroll
    for (int v = 0; v < 6; ++v) { float2 w = g_tw[rows[v]]; twr[v] = w.x; twi[v] = w.y; }
    size_t o = ((size_t)s << 10);
    const int ks[4] = {128, 384, 640, 896};
    const int ia[4] = {0, 2, 3, 5};
    const int ib[4] = {1, 4, 1, 4};
    const int ic[4] = {2, 0, 5, 3};
#pragma unroll
    for (int v = 0; v < 4; ++v) {
        float ar = twr[ia[v]], ai = twi[ia[v]];
        float br2 = twr[ib[v]], bi2 = twi[ib[v]];
        float cr = twr[ic[v]], ci = twi[ic[v]];
        float Xr = g[0] + ar * g[2] - ai * g[3] + br2 * g[4] - bi2 * g[5]
                        + cr * g[6] - ci * g[7];
        float Xi = g[1] + ar * g[3] + ai * g[2] + br2 * g[5] + bi2 * g[4]
                        + cr * g[7] + ci * g[6];
        int k = ks[v];
        float br = b_real[k], bi = b_imag[k];
        out_real[o + k] = Xr + (br - bi);
        out_imag[o + k] = Xi + (br + bi);
    }
}

// combine X = G0 + t1*G1 + t2*G2 + t3*G3
DINL void comb4(float& Xr, float& Xi, const float* gr_, const float* gi_, const float* t) {
    Xr = gr_[0] + t[0] * gr_[1] - t[1] * gi_[1]
                + t[2] * gr_[2] - t[3] * gi_[2]
                + t[4] * gr_[3] - t[5] * gi_[3];
    Xi = gi_[0] + t[0] * gi_[1] + t[1] * gr_[1]
                + t[2] * gi_[2] + t[3] * gr_[2]
                + t[4] * gi_[3] + t[5] * gr_[3];
}

// ---------------- main GEMM kernel (bulk-copy, persistent, radix-4 fused) -----
__global__ void __launch_bounds__(THREADS, 2)
dft_gemm_kernel(const float* __restrict__ b_real, const float* __restrict__ b_imag,
                float* __restrict__ out_real, float* __restrict__ out_imag) {
    extern __shared__ __align__(1024) char sm[];
    uint32_t sb = (uint32_t)__cvta_generic_to_shared(sm);
    const int tid = threadIdx.x, wid = tid >> 5, lid = tid & 31;
    const int h = blockIdx.x;                          // n-half: n0 = 64h
    const int n0 = h * BN;
    const int tile0 = blockIdx.y * MITER;              // base m-tile
    const int wm = (wid >> 2) * 32;
    const int wn = (wid & 3) * 16;

    if (tid == 0) {
        mbar_init(sb + MB_B, 1);
        mbar_init(sb + MB_A0, 1);
        mbar_init(sb + MB_A1, 1);
    }
    __syncthreads();
    if (tid == 0) {
        mbar_expect(sb + MB_B, 65536);
#pragma unroll
        for (int c = 0; c < 4; ++c) {
            bulk_g2s(sb + OFF_B + c * 16384,
                     (const char*)g_wr_t + (((size_t)(h * 4 + c)) << 13), 8192, sb + MB_B);
            bulk_g2s(sb + OFF_B + c * 16384 + 8192,
                     (const char*)g_wi_t + (((size_t)(h * 4 + c)) << 13), 8192, sb + MB_B);
        }
        mbar_expect(sb + MB_A0, 16384);
        bulk_g2s(sb + OFF_A,
                 (const char*)g_xr_t + (((size_t)(tile0 * 4 + 0)) << 13), 8192, sb + MB_A0);
        bulk_g2s(sb + OFF_A + 8192,
                 (const char*)g_xi_t + (((size_t)(tile0 * 4 + 0)) << 13), 8192, sb + MB_A0);
        mbar_expect(sb + MB_A1, 16384);
        bulk_g2s(sb + OFF_A + 16384,
                 (const char*)g_xr_t + (((size_t)(tile0 * 4 + 1)) << 13), 8192, sb + MB_A1);
        bulk_g2s(sb + OFF_A + 16384 + 8192,
                 (const char*)g_xi_t + (((size_t)(tile0 * 4 + 1)) << 13), 8192, sb + MB_A1);
    }

    // stage twiddle/bias tables (coalesced; overlaps bulk loads)
    float* TB = (float*)(sm + SM_TAB);
    {
        int j = tid & 63, q4 = tid >> 6;
        int c = n0 + j;
        int kd = c + 256 * q4;
        int km = (256 - c + 256 * q4) & 1023;
        int base = (j * 4 + q4) * 6;
        float2 w1 = g_tw[kd], w2 = g_tw[(2 * kd) & 1023], w3 = g_tw[(3 * kd) & 1023];
        TB[T_TWD + base + 0] = w1.x; TB[T_TWD + base + 1] = w1.y;
        TB[T_TWD + base + 2] = w2.x; TB[T_TWD + base + 3] = w2.y;
        TB[T_TWD + base + 4] = w3.x; TB[T_TWD + base + 5] = w3.y;
        w1 = g_tw[km]; w2 = g_tw[(2 * km) & 1023]; w3 = g_tw[(3 * km) & 1023];
        TB[T_TWM + base + 0] = w1.x; TB[T_TWM + base + 1] = w1.y;
        TB[T_TWM + base + 2] = w2.x; TB[T_TWM + base + 3] = w2.y;
        TB[T_TWM + base + 4] = w3.x; TB[T_TWM + base + 5] = w3.y;
        int bb = (j * 4 + q4) * 2;
        float a = b_real[kd], b = b_imag[kd];
        TB[T_BD + bb] = a - b; TB[T_BD + bb + 1] = a + b;
        a = b_real[km]; b = b_imag[km];
        TB[T_BM + bb] = a - b; TB[T_BM + bb + 1] = a + b;
    }
    __syncthreads();
    mbar_wait(sb + MB_B, 0);

    float P1[2][2][4], P2[2][2][4], P3[2][2][4], P4[2][2][4];
#pragma unroll
    for (int a = 0; a < 2; ++a)
#pragma unroll
        for (int b = 0; b < 2; ++b)
#pragma unroll
            for (int c = 0; c < 4; ++c) {
                P1[a][b][c] = 0.f; P2[a][b][c] = 0.f;
                P3[a][b][c] = 0.f; P4[a][b][c] = 0.f;
            }

    const int lrow = lid & 15;
    const int lcb  = (lid >> 4) << 4;
    const int gr = lid >> 2, gc = lid & 3;
    const int q  = gr & 3;
    const int lbase = lid & ~12;

    for (int i = 0; i < NITER; ++i) {
        mbar_wait(sb + MB_A0 + (uint32_t)((i & 1) * 8), (uint32_t)((i >> 1) & 1));
        const uint32_t stA = sb + OFF_A + (i & 1) * 16384;
        const uint32_t stB = sb + OFF_B + (i & 3) * 16384;
#pragma unroll
        for (int kk = 0; kk < 4; ++kk) {
            const uint32_t colb = (uint32_t)(kk * 32 + lcb);
            uint32_t Axr[2][4], Axi[2][4];
#pragma unroll
            for (int mt = 0; mt < 2; ++mt) {
                uint32_t ro = (uint32_t)((wm + mt * 16 + lrow) << 7) + colb;
                ldsm4(Axr[mt], stA + swz(ro));
                ldsm4(Axi[mt], stA + 8192 + swz(ro));
            }
            uint32_t Bwr[4], Bwi[4], t4[4];
            {
                uint32_t ro = (uint32_t)((wn + lrow) << 7) + colb;
                ldsm4(t4, stB + swz(ro));
                Bwr[0] = t4[0]; Bwr[1] = t4[2]; Bwr[2] = t4[1]; Bwr[3] = t4[3];
                ldsm4(t4, stB + 8192 + swz(ro));
                Bwi[0] = t4[0]; Bwi[1] = t4[2]; Bwi[2] = t4[1]; Bwi[3] = t4[3];
            }
#pragma unroll
            for (int mt = 0; mt < 2; ++mt)
#pragma unroll
                for (int nt = 0; nt < 2; ++nt) {
                    const int ob = nt * 2;
                    mma16816(P1[mt][nt], Axr[mt], Bwr[ob], Bwr[ob + 1]);
                    mma16816(P2[mt][nt], Axi[mt], Bwi[ob], Bwi[ob + 1]);
                    mma16816(P3[mt][nt], Axr[mt], Bwi[ob], Bwi[ob + 1]);
                    mma16816(P4[mt][nt], Axi[mt], Bwr[ob], Bwr[ob + 1]);
                }
        }
        __syncthreads();                               // all warps done with stage i&1
        if (i + 2 < NITER && tid == 0) {
            int l = i + 2, mi2 = l >> 2, c2 = l & 3;
            uint32_t mb = sb + MB_A0 + (uint32_t)((i & 1) * 8);
            mbar_expect(mb, 16384);
            bulk_g2s(sb + OFF_A + (i & 1) * 16384,
                     (const char*)g_xr_t + (((size_t)((tile0 + mi2) * 4 + c2)) << 13), 8192, mb);
            bulk_g2s(sb + OFF_A + (i & 1) * 16384 + 8192,
                     (const char*)g_xi_t + (((size_t)((tile0 + mi2) * 4 + c2)) << 13), 8192, mb);
        }

        if ((i & 3) == 3) {
            // ------------- fused 4-phase combine epilogue for m-tile i>>2 -------------
            const int m0 = (tile0 + (i >> 2)) * BM;
#pragma unroll
            for (int mt = 0; mt < 2; ++mt)
#pragma unroll
                for (int nt = 0; nt < 2; ++nt) {
                    const int jl = wn + nt * 8 + gc * 2;
#pragma unroll
                    for (int rg = 0; rg < 2; ++rg) {
                        const int e0 = rg * 2, e1 = e0 + 1;
                        size_t s = (size_t)(m0 >> 2) + (wm >> 2) + mt * 4 + rg * 2 + (gr >> 2);
                        float* pr = out_real + (s << 10);
                        float* pi = out_imag + (s << 10);
                        float GdrA = P1[mt][nt][e0] - P2[mt][nt][e0];
                        float GdiA = P3[mt][nt][e0] + P4[mt][nt][e0];
                        float GmrA = P1[mt][nt][e0] + P2[mt][nt][e0];
                        float GmiA = P4[mt][nt][e0] - P3[mt][nt][e0];
                        float GdrB = P1[mt][nt][e1] - P2[mt][nt][e1];
                        float GdiB = P3[mt][nt][e1] + P4[mt][nt][e1];
                        float GmrB = P1[mt][nt][e1] + P2[mt][nt][e1];
                        float GmiB = P4[mt][nt][e1] - P3[mt][nt][e1];
                        float dAr[4], dAi[4], mAr[4], mAi[4];
                        float dBr[4], dBi[4], mBr[4], mBi[4];
#pragma unroll
                        for (int p = 0; p < 4; ++p) {
                            int src = lbase | (p << 2);
                            dAr[p] = __shfl_sync(0xFFFFFFFFu, GdrA, src);
                            dAi[p] = __shfl_sync(0xFFFFFFFFu, GdiA, src);
                            mAr[p] = __shfl_sync(0xFFFFFFFFu, GmrA, src);
                            mAi[p] = __shfl_sync(0xFFFFFFFFu, GmiA, src);
                            dBr[p] = __shfl_sync(0xFFFFFFFFu, GdrB, src);
                            dBi[p] = __shfl_sync(0xFFFFFFFFu, GdiB, src);
                            mBr[p] = __shfl_sync(0xFFFFFFFFu, GmrB, src);
                            mBi[p] = __shfl_sync(0xFFFFFFFFu, GmiB, src);
                        }
                        {
                            const float* tA = TB + T_TWD + (jl * 4 + q) * 6;
                            const float* tB2 = TB + T_TWD + ((jl + 1) * 4 + q) * 6;
                            float XrA, XiA, XrB, XiB;
                            comb4(XrA, XiA, dAr, dAi, tA);
                            comb4(XrB, XiB, dBr, dBi, tB2);
                            const float* bA = TB + T_BD + (jl * 4 + q) * 2;
                            const float* bB = TB + T_BD + ((jl + 1) * 4 + q) * 2;
                            int kd = (n0 + jl) + 256 * q;
                            float2 v;
                            v.x = XrA + bA[0]; v.y = XrB + bB[0];
                            *(float2*)(pr + kd) = v;
                            v.x = XiA + bA[1]; v.y = XiB + bB[1];
                            *(float2*)(pi + kd) = v;
                        }
                        {
                            const float* tA = TB + T_TWM + (jl * 4 + q) * 6;
                            const float* tB2 = TB + T_TWM + ((jl + 1) * 4 + q) * 6;
                            float XrA, XiA, XrB, XiB;
                            comb4(XrA, XiA, mAr, mAi, tA);
                            comb4(XrB, XiB, mBr, mBi, tB2);
                            const float* bA = TB + T_BM + (jl * 4 + q) * 2;
                            const float* bB = TB + T_BM + ((jl + 1) * 4 + q) * 2;
                            int kmA = 256 - (n0 + jl) + 256 * q;
                            pr[kmA - 1] = XrB + bB[0];
                            pi[kmA - 1] = XiB + bB[1];
                            if (kmA < 1024) {
                                pr[kmA] = XrA + bA[0];
                                pi[kmA] = XiA + bA[1];
                            }
                        }
                    }
                }
            // zero accumulators for next m-tile
#pragma unroll
            for (int a = 0; a < 2; ++a)
#pragma unroll
                for (int b = 0; b < 2; ++b)
#pragma unroll
                    for (int c = 0; c < 4; ++c) {
                        P1[a][b][c] = 0.f; P2[a][b][c] = 0.f;
                        P3[a][b][c] = 0.f; P4[a][b][c] = 0.f;
                    }
        }
    }
}

// ---------------- launch ----------------
extern "C" void kernel_launch(void* const* d_in, const int* in_sizes, int n_in,
                              void* d_out, int out_size) {
    (void)in_sizes; (void)n_in; (void)out_size;
    const float4* xr = (const float4*)d_in[0];
    const float4* xi = (const float4*)d_in[1];
    const float*  wr = (const float*)d_in[2];
    const float*  wi = (const float*)d_in[3];
    const float*  br = (const float*)d_in[4];
    const float*  bi = (const float*)d_in[5];
    float* out_real = (float*)d_out;
    float* out_imag = out_real + (size_t)M_SIG * 1024;

    convert_w_kernel<<<16, 256>>>((const float4*)wr, (const float4*)wi);
    convert_x_kernel<<<8192, 256>>>(xr, xi);
    col128_kernel<<<128, 256>>>(br, bi, out_real, out_imag);

    cudaFuncSetAttribute(dft_gemm_kernel,
                         cudaFuncAttributeMaxDynamicSharedMemorySize, SMEM_TOTAL);
    dim3 grid(128 / BN, (MR / BM) / MITER);   // (2, 1024)
    dft_gemm_kernel<<<grid, THREADS, SMEM_TOTAL>>>(br, bi, out_real, out_imag);
}

// round 13
// speedup vs baseline: 2.9905x; 1.0201x over previous
#include <cuda_runtime.h>
#include <cuda_fp16.h>
#include <cstdint>

#define DINL __device__ __forceinline__

// ---------------- problem sizes ----------------
static constexpr int M_SIG = 32768;        // independent signals
static constexpr int MR    = 131072;       // scratch rows: 4 phases per signal
static constexpr int BM = 64;              // scratch rows per m-tile
static constexpr int BN = 64;              // direct W256 cols per CTA (of 128)
static constexpr int MITER = 4;            // m-tiles per CTA
static constexpr int NITER = 4 * MITER;    // 16 linear chunks
static constexpr int THREADS = 256;

// ---------------- smem layout (bytes) ----------------
static constexpr uint32_t OFF_B  = 0;       // 4 chunks x (wr 8KB + wi 8KB) = 64KB resident
static constexpr uint32_t OFF_A  = 65536;   // 2 stages x (xr 8KB + xi 8KB) = 32KB
static constexpr uint32_t SM_TAB = 98304;   // tables: 4096 floats = 16384B -> ends 114688
static constexpr uint32_t MB_B   = 114688;  // mbarriers (AFTER the full table region)
static constexpr uint32_t MB_A0  = 114696;
static constexpr uint32_t MB_A1  = 114704;
static constexpr uint32_t SMEM_TOTAL = 114816;   // x2 CTA = 229632 <= 232448

// table float offsets
static constexpr int T_TWD = 0;      // [64][4][6]   = 1536 floats
static constexpr int T_TWM = 1536;   // [64][4][6]   = 1536 floats
static constexpr int T_BD  = 3072;   // [64][4][2]   = 512 floats
static constexpr int T_BM  = 3584;   // [64][4][2]   = 512 floats (ends at 4096)

// ---------------- global scratch: PRE-SWIZZLED 8KB tiles ----------------
// A: tile index (mtile*4 + chunk), mtile = scratch_row/64, chunk = kcol/64.
// Inside a tile: 64 rows x 128B, SW128; row = 4*(signal&15) + phase.
__device__ __align__(128) __half g_xr_t[33554432];
__device__ __align__(128) __half g_xi_t[33554432];
// B: tile index (h*4 + chunk), h = W256row/64.
__device__ __align__(128) __half g_wr_t[32768];
__device__ __align__(128) __half g_wi_t[32768];
// twiddles: g_tw[k] = (w1024_real[k][1], w1024_imag[k][1])
__device__ __align__(16) float2 g_tw[1024];
// col128 partials: per signal 16 floats = [half0: pr0..3,pi0..3][half1: ...]
__device__ __align__(16) float g_part[524288];

// ---------------- PTX helpers ----------------
DINL uint32_t swz(uint32_t o) { return o ^ ((o >> 3) & 0x70); }

DINL void mbar_init(uint32_t a, uint32_t cnt) {
    asm volatile("mbarrier.init.shared.b64 [%0], %1;\n" :: "r"(a), "r"(cnt) : "memory");
}
DINL void mbar_expect(uint32_t a, uint32_t bytes) {
    asm volatile("mbarrier.arrive.expect_tx.shared.b64 _, [%0], %1;\n"
                 :: "r"(a), "r"(bytes) : "memory");
}
DINL void mbar_wait(uint32_t a, uint32_t parity) {
    asm volatile(
        "{\n\t.reg .pred P;\n"
        "WLP_%=:\n\t"
        "mbarrier.try_wait.parity.acquire.cta.shared::cta.b64 P, [%0], %1, 0x989680;\n\t"
        "@!P bra WLP_%=;\n\t"
        "}\n" :: "r"(a), "r"(parity) : "memory");
}
DINL void bulk_g2s(uint32_t dst, const void* src, uint32_t bytes, uint32_t mbar) {
    asm volatile(
        "cp.async.bulk.shared::cta.global.mbarrier::complete_tx::bytes [%0], [%1], %2, [%3];\n"
        :: "r"(dst), "l"(src), "r"(bytes), "r"(mbar) : "memory");
}

DINL void ldsm4(uint32_t* r, uint32_t a) {
    asm volatile("ldmatrix.sync.aligned.m8n8.x4.shared.b16 {%0,%1,%2,%3}, [%4];\n"
                 : "=r"(r[0]), "=r"(r[1]), "=r"(r[2]), "=r"(r[3]) : "r"(a));
}

DINL void mma16816(float* d, const uint32_t* a, uint32_t b0, uint32_t b1) {
    asm volatile(
        "mma.sync.aligned.m16n8k16.row.col.f32.f16.f16.f32 "
        "{%0,%1,%2,%3}, {%4,%5,%6,%7}, {%8,%9}, {%0,%1,%2,%3};\n"
        : "+f"(d[0]), "+f"(d[1]), "+f"(d[2]), "+f"(d[3])
        : "r"(a[0]), "r"(a[1]), "r"(a[2]), "r"(a[3]), "r"(b0), "r"(b1));
}

// ---------------- conversion ----------------
DINL uint32_t h2u(float a, float b) {
    __half2 h = __floats2half2_rn(a, b);
    return *(uint32_t*)&h;
}

// 4-phase deinterleave -> pre-swizzled tiles + fused col128 partial sums.
__global__ void __launch_bounds__(256) convert_x_kernel(const float4* __restrict__ xr,
                                                        const float4* __restrict__ xi) {
    size_t gid = (size_t)blockIdx.x * 256 + threadIdx.x;   // 2M threads
    size_t m = gid >> 6;
    int j = (int)(gid & 63);
    const int c = j >> 4;                                  // k-chunk
    const uint32_t inb = (uint32_t)((j & 15) << 3);        // byte col in row
    char* bxr = (char*)g_xr_t + (((m >> 4) * 4 + c) << 13);
    char* bxi = (char*)g_xi_t + (((m >> 4) * 4 + c) << 13);
    const int rb = 4 * (int)(m & 15);
    float pr[4], pq[4];                                    // col128 partials (re/im)
    {
        const float4* p = xr + (m << 8) + (j << 2);
        float4 f0 = p[0], f1 = p[1], f2 = p[2], f3 = p[3];
        uint2 v;
        v.x = h2u(f0.x, f1.x); v.y = h2u(f2.x, f3.x);
        *(uint2*)(bxr + swz(((rb + 0) << 7) | inb)) = v;
        v.x = h2u(f0.y, f1.y); v.y = h2u(f2.y, f3.y);
        *(uint2*)(bxr + swz(((rb + 1) << 7) | inb)) = v;
        v.x = h2u(f0.z, f1.z); v.y = h2u(f2.z, f3.z);
        *(uint2*)(bxr + swz(((rb + 2) << 7) | inb)) = v;
        v.x = h2u(f0.w, f1.w); v.y = h2u(f2.w, f3.w);
        *(uint2*)(bxr + swz(((rb + 3) << 7) | inb)) = v;
        pr[0] = f0.x - f1.x + f2.x - f3.x;
        pr[1] = f0.y - f1.y + f2.y - f3.y;
        pr[2] = f0.z - f1.z + f2.z - f3.z;
        pr[3] = f0.w - f1.w + f2.w - f3.w;
    }
    {
        const float4* p = xi + (m << 8) + (j << 2);
        float4 f0 = p[0], f1 = p[1], f2 = p[2], f3 = p[3];
        uint2 v;
        v.x = h2u(f0.x, f1.x); v.y = h2u(f2.x, f3.x);
        *(uint2*)(bxi + swz(((rb + 0) << 7) | inb)) = v;
        v.x = h2u(f0.y, f1.y); v.y = h2u(f2.y, f3.y);
        *(uint2*)(bxi + swz(((rb + 1) << 7) | inb)) = v;
        v.x = h2u(f0.z, f1.z); v.y = h2u(f2.z, f3.z);
        *(uint2*)(bxi + swz(((rb + 2) << 7) | inb)) = v;
        v.x = h2u(f0.w, f1.w); v.y = h2u(f2.w, f3.w);
        *(uint2*)(bxi + swz(((rb + 3) << 7) | inb)) = v;
        pq[0] = f0.x - f1.x + f2.x - f3.x;
        pq[1] = f0.y - f1.y + f2.y - f3.y;
        pq[2] = f0.z - f1.z + f2.z - f3.z;
        pq[3] = f0.w - f1.w + f2.w - f3.w;
    }
    // warp-level reduction: all 32 lanes of this warp belong to the same signal
#pragma unroll
    for (int sh = 16; sh > 0; sh >>= 1) {
#pragma unroll
        for (int v = 0; v < 4; ++v) {
            pr[v] += __shfl_xor_sync(0xFFFFFFFFu, pr[v], sh);
            pq[v] += __shfl_xor_sync(0xFFFFFFFFu, pq[v], sh);
        }
    }
    if ((threadIdx.x & 31) == 0) {
        size_t base = (m << 4) + (size_t)((j >> 5) << 3);
        *(float4*)(g_part + base)     = make_float4(pr[0], pr[1], pr[2], pr[3]);
        *(float4*)(g_part + base + 4) = make_float4(pq[0], pq[1], pq[2], pq[3]);
    }
}

// W256 rows -> pre-swizzled tiles; first 1024 threads also gather twiddles
__global__ void __launch_bounds__(256) convert_w_kernel(const float4* __restrict__ wr,
                                                        const float4* __restrict__ wi) {
    size_t gid = (size_t)blockIdx.x * 256 + threadIdx.x;   // 4096 threads
    if (gid < 1024) {
        g_tw[gid] = make_float2(((const float*)wr)[(gid << 10) + 1],
                                ((const float*)wi)[(gid << 10) + 1]);
    }
    size_t k = gid >> 5;                                   // W256 row 0..127
    int j = (int)(gid & 31);                               // 8-half group
    size_t src = (k << 10) + (j << 1);                     // float4 idx into w1024 row 4k
    const int h = (int)(k >> 6), r = (int)(k & 63), c = j >> 3;
    uint32_t off = swz((uint32_t)((r << 7) | ((j & 7) << 4)));
    char* bwr = (char*)g_wr_t + (((h * 4 + c)) << 13);
    char* bwi = (char*)g_wi_t + (((h * 4 + c)) << 13);
    float4 a = wr[src], b = wr[src + 1];
    uint4 u;
    u.x = h2u(a.x, a.y); u.y = h2u(a.z, a.w);
    u.z = h2u(b.x, b.y); u.w = h2u(b.z, b.w);
    *(uint4*)(bwr + off) = u;
    float4 cc = wi[src], d = wi[src + 1];
    u.x = h2u(cc.x, cc.y); u.y = h2u(cc.z, cc.w);
    u.z = h2u(d.x, d.y); u.w = h2u(d.z, d.w);
    *(uint4*)(bwi + off) = u;
}

// ---------------- special cols from partials: k in {128,384,640,896} ----------
__global__ void __launch_bounds__(256) col128_kernel(const float* __restrict__ b_real,
                                                     const float* __restrict__ b_imag,
                                                     float* __restrict__ out_real,
                                                     float* __restrict__ out_imag) {
    int s = blockIdx.x * 256 + threadIdx.x;            // one thread per signal
    float4 h0r = *(const float4*)(g_part + ((size_t)s << 4));
    float4 h0i = *(const float4*)(g_part + ((size_t)s << 4) + 4);
    float4 h1r = *(const float4*)(g_part + ((size_t)s << 4) + 8);
    float4 h1i = *(const float4*)(g_part + ((size_t)s << 4) + 12);
    float g[8];
    g[0] = h0r.x + h1r.x; g[1] = h0i.x + h1i.x;        // G0 re/im
    g[2] = h0r.y + h1r.y; g[3] = h0i.y + h1i.y;        // G1
    g[4] = h0r.z + h1r.z; g[5] = h0i.z + h1i.z;        // G2
    g[6] = h0r.w + h1r.w; g[7] = h0i.w + h1i.w;        // G3
    const int rows[6] = {128, 256, 384, 640, 768, 896};
    float twr[6], twi[6];
#pragma unroll
    for (int v = 0; v < 6; ++v) { float2 w = g_tw[rows[v]]; twr[v] = w.x; twi[v] = w.y; }
    size_t o = ((size_t)s << 10);
    const int ks[4] = {128, 384, 640, 896};
    const int ia[4] = {0, 2, 3, 5};
    const int ib[4] = {1, 4, 1, 4};
    const int ic[4] = {2, 0, 5, 3};
#pragma unroll
    for (int v = 0; v < 4; ++v) {
        float ar = twr[ia[v]], ai = twi[ia[v]];
        float br2 = twr[ib[v]], bi2 = twi[ib[v]];
        float cr = twr[ic[v]], ci = twi[ic[v]];
        float Xr = g[0] + ar * g[2] - ai * g[3] + br2 * g[4] - bi2 * g[5]
                        + cr * g[6] - ci * g[7];
        float Xi = g[1] + ar * g[3] + ai * g[2] + br2 * g[5] + bi2 * g[4]
                        + cr * g[7] + ci * g[6];
        int k = ks[v];
        float br = b_real[k], bi = b_imag[k];
        out_real[o + k] = Xr + (br - bi);
        out_imag[o + k] = Xi + (br + bi);
    }
}

// combine X = G0 + t1*G1 + t2*G2 + t3*G3
DINL void comb4(float& Xr, float& Xi, const float* gr_, const float* gi_, const float* t) {
    Xr = gr_[0] + t[0] * gr_[1] - t[1] * gi_[1]
                + t[2] * gr_[2] - t[3] * gi_[2]
                + t[4] * gr_[3] - t[5] * gi_[3];
    Xi = gi_[0] + t[0] * gi_[1] + t[1] * gr_[1]
                + t[2] * gi_[2] + t[3] * gr_[2]
                + t[4] * gi_[3] + t[5] * gr_[3];
}

// ---------------- main GEMM kernel (bulk-copy, persistent, radix-4 fused) -----
__global__ void __launch_bounds__(THREADS, 2)
dft_gemm_kernel(const float* __restrict__ b_real, const float* __restrict__ b_imag,
                float* __restrict__ out_real, float* __restrict__ out_imag) {
    extern __shared__ __align__(1024) char sm[];
    uint32_t sb = (uint32_t)__cvta_generic_to_shared(sm);
    const int tid = threadIdx.x, wid = tid >> 5, lid = tid & 31;
    const int h = blockIdx.x;                          // n-half: n0 = 64h
    const int n0 = h * BN;
    const int tile0 = blockIdx.y * MITER;              // base m-tile
    const int wm = (wid >> 2) * 32;
    const int wn = (wid & 3) * 16;

    if (tid == 0) {
        mbar_init(sb + MB_B, 1);
        mbar_init(sb + MB_A0, 1);
        mbar_init(sb + MB_A1, 1);
    }
    __syncthreads();
    if (tid == 0) {
        // A stages first (mainloop consumes A before B is touched heavily)
        mbar_expect(sb + MB_A0, 16384);
        bulk_g2s(sb + OFF_A,
                 (const char*)g_xr_t + (((size_t)(tile0 * 4 + 0)) << 13), 8192, sb + MB_A0);
        bulk_g2s(sb + OFF_A + 8192,
                 (const char*)g_xi_t + (((size_t)(tile0 * 4 + 0)) << 13), 8192, sb + MB_A0);
        mbar_expect(sb + MB_A1, 16384);
        bulk_g2s(sb + OFF_A + 16384,
                 (const char*)g_xr_t + (((size_t)(tile0 * 4 + 1)) << 13), 8192, sb + MB_A1);
        bulk_g2s(sb + OFF_A + 16384 + 8192,
                 (const char*)g_xi_t + (((size_t)(tile0 * 4 + 1)) << 13), 8192, sb + MB_A1);
        mbar_expect(sb + MB_B, 65536);
#pragma unroll
        for (int c = 0; c < 4; ++c) {
            bulk_g2s(sb + OFF_B + c * 16384,
                     (const char*)g_wr_t + (((size_t)(h * 4 + c)) << 13), 8192, sb + MB_B);
            bulk_g2s(sb + OFF_B + c * 16384 + 8192,
                     (const char*)g_wi_t + (((size_t)(h * 4 + c)) << 13), 8192, sb + MB_B);
        }
    }

    // stage twiddle/bias tables (coalesced; overlaps bulk loads)
    float* TB = (float*)(sm + SM_TAB);
    {
        int j = tid & 63, q4 = tid >> 6;
        int c = n0 + j;
        int kd = c + 256 * q4;
        int km = (256 - c + 256 * q4) & 1023;
        int base = (j * 4 + q4) * 6;
        float2 w1 = g_tw[kd], w2 = g_tw[(2 * kd) & 1023], w3 = g_tw[(3 * kd) & 1023];
        TB[T_TWD + base + 0] = w1.x; TB[T_TWD + base + 1] = w1.y;
        TB[T_TWD + base + 2] = w2.x; TB[T_TWD + base + 3] = w2.y;
        TB[T_TWD + base + 4] = w3.x; TB[T_TWD + base + 5] = w3.y;
        w1 = g_tw[km]; w2 = g_tw[(2 * km) & 1023]; w3 = g_tw[(3 * km) & 1023];
        TB[T_TWM + base + 0] = w1.x; TB[T_TWM + base + 1] = w1.y;
        TB[T_TWM + base + 2] = w2.x; TB[T_TWM + base + 3] = w2.y;
        TB[T_TWM + base + 4] = w3.x; TB[T_TWM + base + 5] = w3.y;
        int bb = (j * 4 + q4) * 2;
        float a = b_real[kd], b = b_imag[kd];
        TB[T_BD + bb] = a - b; TB[T_BD + bb + 1] = a + b;
        a = b_real[km]; b = b_imag[km];
        TB[T_BM + bb] = a - b; TB[T_BM + bb + 1] = a + b;
    }
    __syncthreads();
    mbar_wait(sb + MB_B, 0);

    float P1[2][2][4], P2[2][2][4], P3[2][2][4], P4[2][2][4];
#pragma unroll
    for (int a = 0; a < 2; ++a)
#pragma unroll
        for (int b = 0; b < 2; ++b)
#pragma unroll
            for (int c = 0; c < 4; ++c) {
                P1[a][b][c] = 0.f; P2[a][b][c] = 0.f;
                P3[a][b][c] = 0.f; P4[a][b][c] = 0.f;
            }

    const int lrow = lid & 15;
    const int lcb  = (lid >> 4) << 4;
    const int gr = lid >> 2, gc = lid & 3;
    const int q  = gr & 3;
    const int lbase = lid & ~12;

    for (int i = 0; i < NITER; ++i) {
        mbar_wait(sb + MB_A0 + (uint32_t)((i & 1) * 8), (uint32_t)((i >> 1) & 1));
        const uint32_t stA = sb + OFF_A + (i & 1) * 16384;
        const uint32_t stB = sb + OFF_B + (i & 3) * 16384;
#pragma unroll
        for (int kk = 0; kk < 4; ++kk) {
            const uint32_t colb = (uint32_t)(kk * 32 + lcb);
            uint32_t Axr[2][4], Axi[2][4];
#pragma unroll
            for (int mt = 0; mt < 2; ++mt) {
                uint32_t ro = (uint32_t)((wm + mt * 16 + lrow) << 7) + colb;
                ldsm4(Axr[mt], stA + swz(ro));
                ldsm4(Axi[mt], stA + 8192 + swz(ro));
            }
            uint32_t Bwr[4], Bwi[4], t4[4];
            {
                uint32_t ro = (uint32_t)((wn + lrow) << 7) + colb;
                ldsm4(t4, stB + swz(ro));
                Bwr[0] = t4[0]; Bwr[1] = t4[2]; Bwr[2] = t4[1]; Bwr[3] = t4[3];
                ldsm4(t4, stB + 8192 + swz(ro));
                Bwi[0] = t4[0]; Bwi[1] = t4[2]; Bwi[2] = t4[1]; Bwi[3] = t4[3];
            }
#pragma unroll
            for (int mt = 0; mt < 2; ++mt)
#pragma unroll
                for (int nt = 0; nt < 2; ++nt) {
                    const int ob = nt * 2;
                    mma16816(P1[mt][nt], Axr[mt], Bwr[ob], Bwr[ob + 1]);
                    mma16816(P2[mt][nt], Axi[mt], Bwi[ob], Bwi[ob + 1]);
                    mma16816(P3[mt][nt], Axr[mt], Bwi[ob], Bwi[ob + 1]);
                    mma16816(P4[mt][nt], Axi[mt], Bwr[ob], Bwr[ob + 1]);
                }
        }
        __syncthreads();                               // all warps done with stage i&1
        if (i + 2 < NITER && tid == 0) {
            int l = i + 2, mi2 = l >> 2, c2 = l & 3;
            uint32_t mb = sb + MB_A0 + (uint32_t)((i & 1) * 8);
            mbar_expect(mb, 16384);
            bulk_g2s(sb + OFF_A + (i & 1) * 16384,
                     (const char*)g_xr_t + (((size_t)((tile0 + mi2) * 4 + c2)) << 13), 8192, mb);
            bulk_g2s(sb + OFF_A + (i & 1) * 16384 + 8192,
                     (const char*)g_xi_t + (((size_t)((tile0 + mi2) * 4 + c2)) << 13), 8192, mb);
        }

        if ((i & 3) == 3) {
            // ------------- fused 4-phase combine epilogue for m-tile i>>2 -------------
            const int m0 = (tile0 + (i >> 2)) * BM;
#pragma unroll
            for (int mt = 0; mt < 2; ++mt)
#pragma unroll
                for (int nt = 0; nt < 2; ++nt) {
                    const int jl = wn + nt * 8 + gc * 2;
#pragma unroll
                    for (int rg = 0; rg < 2; ++rg) {
                        const int e0 = rg * 2, e1 = e0 + 1;
                        size_t s = (size_t)(m0 >> 2) + (wm >> 2) + mt * 4 + rg * 2 + (gr >> 2);
                        float* pr = out_real + (s << 10);
                        float* pi = out_imag + (s << 10);
                        float GdrA = P1[mt][nt][e0] - P2[mt][nt][e0];
                        float GdiA = P3[mt][nt][e0] + P4[mt][nt][e0];
                        float GmrA = P1[mt][nt][e0] + P2[mt][nt][e0];
                        float GmiA = P4[mt][nt][e0] - P3[mt][nt][e0];
                        float GdrB = P1[mt][nt][e1] - P2[mt][nt][e1];
                        float GdiB = P3[mt][nt][e1] + P4[mt][nt][e1];
                        float GmrB = P1[mt][nt][e1] + P2[mt][nt][e1];
                        float GmiB = P4[mt][nt][e1] - P3[mt][nt][e1];
                        float dAr[4], dAi[4], mAr[4], mAi[4];
                        float dBr[4], dBi[4], mBr[4], mBi[4];
#pragma unroll
                        for (int p = 0; p < 4; ++p) {
                            int src = lbase | (p << 2);
                            dAr[p] = __shfl_sync(0xFFFFFFFFu, GdrA, src);
                            dAi[p] = __shfl_sync(0xFFFFFFFFu, GdiA, src);
                            mAr[p] = __shfl_sync(0xFFFFFFFFu, GmrA, src);
                            mAi[p] = __shfl_sync(0xFFFFFFFFu, GmiA, src);
                            dBr[p] = __shfl_sync(0xFFFFFFFFu, GdrB, src);
                            dBi[p] = __shfl_sync(0xFFFFFFFFu, GdiB, src);
                            mBr[p] = __shfl_sync(0xFFFFFFFFu, GmrB, src);
                            mBi[p] = __shfl_sync(0xFFFFFFFFu, GmiB, src);
                        }
                        {
                            const float* tA = TB + T_TWD + (jl * 4 + q) * 6;
                            const float* tB2 = TB + T_TWD + ((jl + 1) * 4 + q) * 6;
                            float XrA, XiA, XrB, XiB;
                            comb4(XrA, XiA, dAr, dAi, tA);
                            comb4(XrB, XiB, dBr, dBi, tB2);
                            const float* bA = TB + T_BD + (jl * 4 + q) * 2;
                            const float* bB = TB + T_BD + ((jl + 1) * 4 + q) * 2;
                            int kd = (n0 + jl) + 256 * q;
                            float2 v;
                            v.x = XrA + bA[0]; v.y = XrB + bB[0];
                            *(float2*)(pr + kd) = v;
                            v.x = XiA + bA[1]; v.y = XiB + bB[1];
                            *(float2*)(pi + kd) = v;
                        }
                        {
                            const float* tA = TB + T_TWM + (jl * 4 + q) * 6;
                            const float* tB2 = TB + T_TWM + ((jl + 1) * 4 + q) * 6;
                            float XrA, XiA, XrB, XiB;
                            comb4(XrA, XiA, mAr, mAi, tA);
                            comb4(XrB, XiB, mBr, mBi, tB2);
                            const float* bA = TB + T_BM + (jl * 4 + q) * 2;
                            const float* bB = TB + T_BM + ((jl + 1) * 4 + q) * 2;
                            int kmA = 256 - (n0 + jl) + 256 * q;
                            pr[kmA - 1] = XrB + bB[0];
                            pi[kmA - 1] = XiB + bB[1];
                            if (kmA < 1024) {
                                pr[kmA] = XrA + bA[0];
                                pi[kmA] = XiA + bA[1];
                            }
                        }
                    }
                }
            // zero accumulators for next m-tile
#pragma unroll
            for (int a = 0; a < 2; ++a)
#pragma unroll
                for (int b = 0; b < 2; ++b)
#pragma unroll
                    for (int c = 0; c < 4; ++c) {
                        P1[a][b][c] = 0.f; P2[a][b][c] = 0.f;
                        P3[a][b][c] = 0.f; P4[a][b][c] = 0.f;
                    }
        }
    }
}

// ---------------- launch ----------------
extern "C" void kernel_launch(void* const* d_in, const int* in_sizes, int n_in,
                              void* d_out, int out_size) {
    (void)in_sizes; (void)n_in; (void)out_size;
    const float4* xr = (const float4*)d_in[0];
    const float4* xi = (const float4*)d_in[1];
    const float*  wr = (const float*)d_in[2];
    const float*  wi = (const float*)d_in[3];
    const float*  br = (const float*)d_in[4];
    const float*  bi = (const float*)d_in[5];
    float* out_real = (float*)d_out;
    float* out_imag = out_real + (size_t)M_SIG * 1024;

    convert_w_kernel<<<16, 256>>>((const float4*)wr, (const float4*)wi);
    convert_x_kernel<<<8192, 256>>>(xr, xi);
    col128_kernel<<<128, 256>>>(br, bi, out_real, out_imag);

    cudaFuncSetAttribute(dft_gemm_kernel,
                         cudaFuncAttributeMaxDynamicSharedMemorySize, SMEM_TOTAL);
    dim3 grid(128 / BN, (MR / BM) / MITER);   // (2, 512)
    dft_gemm_kernel<<<grid, THREADS, SMEM_TOTAL>>>(br, bi, out_real, out_imag);
}

// round 14
// speedup vs baseline: 3.0416x; 1.0171x over previous
#include <cuda_runtime.h>
#include <cuda_fp16.h>
#include <cstdint>

#define DINL __device__ __forceinline__

// ---------------- problem sizes ----------------
static constexpr int M_SIG = 32768;        // independent signals
static constexpr int MR    = 131072;       // scratch rows: 4 phases per signal
static constexpr int BM = 64;              // scratch rows per m-tile
static constexpr int BN = 64;              // direct W256 cols per CTA (of 128)
static constexpr int MITER = 4;            // m-tiles per CTA
static constexpr int NITER = 4 * MITER;    // 16 linear chunks
static constexpr int THREADS = 256;

// ---------------- smem layout (bytes) ----------------
static constexpr uint32_t OFF_B  = 0;       // 4 chunks x (wr 8KB + wi 8KB) = 64KB resident
static constexpr uint32_t OFF_A  = 65536;   // 2 stages x (xr 8KB + xi 8KB) = 32KB
static constexpr uint32_t SM_TAB = 98304;   // tables: 4096 floats = 16384B -> ends 114688
static constexpr uint32_t MB_B   = 114688;  // mbarriers (AFTER the full table region)
static constexpr uint32_t MB_A0  = 114696;
static constexpr uint32_t MB_A1  = 114704;
static constexpr uint32_t SMEM_TOTAL = 114816;   // x2 CTA = 229632 <= 232448

// table float offsets
static constexpr int T_TWD = 0;      // [64][4][6]   = 1536 floats
static constexpr int T_TWM = 1536;   // [64][4][6]   = 1536 floats
static constexpr int T_BD  = 3072;   // [64][4][2]   = 512 floats
static constexpr int T_BM  = 3584;   // [64][4][2]   = 512 floats (ends at 4096)

// ---------------- global scratch: PRE-SWIZZLED 8KB tiles ----------------
// A: tile index (mtile*4 + chunk), mtile = scratch_row/64, chunk = kcol/64.
// Inside a tile: 64 rows x 128B, SW128; row = 4*(signal&15) + phase.
__device__ __align__(128) __half g_xr_t[33554432];
__device__ __align__(128) __half g_xi_t[33554432];
// B: tile index (h*4 + chunk), h = W256row/64.
__device__ __align__(128) __half g_wr_t[32768];
__device__ __align__(128) __half g_wi_t[32768];
// twiddles: g_tw[k] = (w1024_real[k][1], w1024_imag[k][1])
__device__ __align__(16) float2 g_tw[1024];
// col128 partials: per signal 16 floats = [half0: pr0..3,pi0..3][half1: ...]
__device__ __align__(16) float g_part[524288];

// ---------------- PTX helpers ----------------
DINL uint32_t swz(uint32_t o) { return o ^ ((o >> 3) & 0x70); }

DINL void mbar_init(uint32_t a, uint32_t cnt) {
    asm volatile("mbarrier.init.shared.b64 [%0], %1;\n" :: "r"(a), "r"(cnt) : "memory");
}
DINL void mbar_expect(uint32_t a, uint32_t bytes) {
    asm volatile("mbarrier.arrive.expect_tx.shared.b64 _, [%0], %1;\n"
                 :: "r"(a), "r"(bytes) : "memory");
}
DINL void mbar_wait(uint32_t a, uint32_t parity) {
    asm volatile(
        "{\n\t.reg .pred P;\n"
        "WLP_%=:\n\t"
        "mbarrier.try_wait.parity.acquire.cta.shared::cta.b64 P, [%0], %1, 0x989680;\n\t"
        "@!P bra WLP_%=;\n\t"
        "}\n" :: "r"(a), "r"(parity) : "memory");
}
DINL void bulk_g2s(uint32_t dst, const void* src, uint32_t bytes, uint32_t mbar) {
    asm volatile(
        "cp.async.bulk.shared::cta.global.mbarrier::complete_tx::bytes [%0], [%1], %2, [%3];\n"
        :: "r"(dst), "l"(src), "r"(bytes), "r"(mbar) : "memory");
}

DINL void ldsm4(uint32_t* r, uint32_t a) {
    asm volatile("ldmatrix.sync.aligned.m8n8.x4.shared.b16 {%0,%1,%2,%3}, [%4];\n"
                 : "=r"(r[0]), "=r"(r[1]), "=r"(r[2]), "=r"(r[3]) : "r"(a));
}

DINL void mma16816(float* d, const uint32_t* a, uint32_t b0, uint32_t b1) {
    asm volatile(
        "mma.sync.aligned.m16n8k16.row.col.f32.f16.f16.f32 "
        "{%0,%1,%2,%3}, {%4,%5,%6,%7}, {%8,%9}, {%0,%1,%2,%3};\n"
        : "+f"(d[0]), "+f"(d[1]), "+f"(d[2]), "+f"(d[3])
        : "r"(a[0]), "r"(a[1]), "r"(a[2]), "r"(a[3]), "r"(b0), "r"(b1));
}

// ---------------- conversion ----------------
DINL uint32_t h2u(float a, float b) {
    __half2 h = __floats2half2_rn(a, b);
    return *(uint32_t*)&h;
}

// 4-phase deinterleave -> pre-swizzled tiles + fused col128 partial sums.
__global__ void __launch_bounds__(256) convert_x_kernel(const float4* __restrict__ xr,
                                                        const float4* __restrict__ xi) {
    size_t gid = (size_t)blockIdx.x * 256 + threadIdx.x;   // 2M threads
    size_t m = gid >> 6;
    int j = (int)(gid & 63);
    const int c = j >> 4;                                  // k-chunk
    const uint32_t inb = (uint32_t)((j & 15) << 3);        // byte col in row
    char* bxr = (char*)g_xr_t + (((m >> 4) * 4 + c) << 13);
    char* bxi = (char*)g_xi_t + (((m >> 4) * 4 + c) << 13);
    const int rb = 4 * (int)(m & 15);
    float pr[4], pq[4];                                    // col128 partials (re/im)
    {
        const float4* p = xr + (m << 8) + (j << 2);
        float4 f0 = p[0], f1 = p[1], f2 = p[2], f3 = p[3];
        uint2 v;
        v.x = h2u(f0.x, f1.x); v.y = h2u(f2.x, f3.x);
        *(uint2*)(bxr + swz(((rb + 0) << 7) | inb)) = v;
        v.x = h2u(f0.y, f1.y); v.y = h2u(f2.y, f3.y);
        *(uint2*)(bxr + swz(((rb + 1) << 7) | inb)) = v;
        v.x = h2u(f0.z, f1.z); v.y = h2u(f2.z, f3.z);
        *(uint2*)(bxr + swz(((rb + 2) << 7) | inb)) = v;
        v.x = h2u(f0.w, f1.w); v.y = h2u(f2.w, f3.w);
        *(uint2*)(bxr + swz(((rb + 3) << 7) | inb)) = v;
        pr[0] = f0.x - f1.x + f2.x - f3.x;
        pr[1] = f0.y - f1.y + f2.y - f3.y;
        pr[2] = f0.z - f1.z + f2.z - f3.z;
        pr[3] = f0.w - f1.w + f2.w - f3.w;
    }
    {
        const float4* p = xi + (m << 8) + (j << 2);
        float4 f0 = p[0], f1 = p[1], f2 = p[2], f3 = p[3];
        uint2 v;
        v.x = h2u(f0.x, f1.x); v.y = h2u(f2.x, f3.x);
        *(uint2*)(bxi + swz(((rb + 0) << 7) | inb)) = v;
        v.x = h2u(f0.y, f1.y); v.y = h2u(f2.y, f3.y);
        *(uint2*)(bxi + swz(((rb + 1) << 7) | inb)) = v;
        v.x = h2u(f0.z, f1.z); v.y = h2u(f2.z, f3.z);
        *(uint2*)(bxi + swz(((rb + 2) << 7) | inb)) = v;
        v.x = h2u(f0.w, f1.w); v.y = h2u(f2.w, f3.w);
        *(uint2*)(bxi + swz(((rb + 3) << 7) | inb)) = v;
        pq[0] = f0.x - f1.x + f2.x - f3.x;
        pq[1] = f0.y - f1.y + f2.y - f3.y;
        pq[2] = f0.z - f1.z + f2.z - f3.z;
        pq[3] = f0.w - f1.w + f2.w - f3.w;
    }
    // warp-level reduction: all 32 lanes of this warp belong to the same signal
#pragma unroll
    for (int sh = 16; sh > 0; sh >>= 1) {
#pragma unroll
        for (int v = 0; v < 4; ++v) {
            pr[v] += __shfl_xor_sync(0xFFFFFFFFu, pr[v], sh);
            pq[v] += __shfl_xor_sync(0xFFFFFFFFu, pq[v], sh);
        }
    }
    if ((threadIdx.x & 31) == 0) {
        size_t base = (m << 4) + (size_t)((j >> 5) << 3);
        *(float4*)(g_part + base)     = make_float4(pr[0], pr[1], pr[2], pr[3]);
        *(float4*)(g_part + base + 4) = make_float4(pq[0], pq[1], pq[2], pq[3]);
    }
}

// W256 rows -> pre-swizzled tiles; first 1024 threads also gather twiddles
__global__ void __launch_bounds__(256) convert_w_kernel(const float4* __restrict__ wr,
                                                        const float4* __restrict__ wi) {
    size_t gid = (size_t)blockIdx.x * 256 + threadIdx.x;   // 4096 threads
    if (gid < 1024) {
        g_tw[gid] = make_float2(((const float*)wr)[(gid << 10) + 1],
                                ((const float*)wi)[(gid << 10) + 1]);
    }
    size_t k = gid >> 5;                                   // W256 row 0..127
    int j = (int)(gid & 31);                               // 8-half group
    size_t src = (k << 10) + (j << 1);                     // float4 idx into w1024 row 4k
    const int h = (int)(k >> 6), r = (int)(k & 63), c = j >> 3;
    uint32_t off = swz((uint32_t)((r << 7) | ((j & 7) << 4)));
    char* bwr = (char*)g_wr_t + (((h * 4 + c)) << 13);
    char* bwi = (char*)g_wi_t + (((h * 4 + c)) << 13);
    float4 a = wr[src], b = wr[src + 1];
    uint4 u;
    u.x = h2u(a.x, a.y); u.y = h2u(a.z, a.w);
    u.z = h2u(b.x, b.y); u.w = h2u(b.z, b.w);
    *(uint4*)(bwr + off) = u;
    float4 cc = wi[src], d = wi[src + 1];
    u.x = h2u(cc.x, cc.y); u.y = h2u(cc.z, cc.w);
    u.z = h2u(d.x, d.y); u.w = h2u(d.z, d.w);
    *(uint4*)(bwi + off) = u;
}

// ---------------- special cols from partials: k in {128,384,640,896} ----------
__global__ void __launch_bounds__(256) col128_kernel(const float* __restrict__ b_real,
                                                     const float* __restrict__ b_imag,
                                                     float* __restrict__ out_real,
                                                     float* __restrict__ out_imag) {
    int s = blockIdx.x * 256 + threadIdx.x;            // one thread per signal
    float4 h0r = *(const float4*)(g_part + ((size_t)s << 4));
    float4 h0i = *(const float4*)(g_part + ((size_t)s << 4) + 4);
    float4 h1r = *(const float4*)(g_part + ((size_t)s << 4) + 8);
    float4 h1i = *(const float4*)(g_part + ((size_t)s << 4) + 12);
    float g[8];
    g[0] = h0r.x + h1r.x; g[1] = h0i.x + h1i.x;        // G0 re/im
    g[2] = h0r.y + h1r.y; g[3] = h0i.y + h1i.y;        // G1
    g[4] = h0r.z + h1r.z; g[5] = h0i.z + h1i.z;        // G2
    g[6] = h0r.w + h1r.w; g[7] = h0i.w + h1i.w;        // G3
    const int rows[6] = {128, 256, 384, 640, 768, 896};
    float twr[6], twi[6];
#pragma unroll
    for (int v = 0; v < 6; ++v) { float2 w = g_tw[rows[v]]; twr[v] = w.x; twi[v] = w.y; }
    size_t o = ((size_t)s << 10);
    const int ks[4] = {128, 384, 640, 896};
    const int ia[4] = {0, 2, 3, 5};
    const int ib[4] = {1, 4, 1, 4};
    const int ic[4] = {2, 0, 5, 3};
#pragma unroll
    for (int v = 0; v < 4; ++v) {
        float ar = twr[ia[v]], ai = twi[ia[v]];
        float br2 = twr[ib[v]], bi2 = twi[ib[v]];
        float cr = twr[ic[v]], ci = twi[ic[v]];
        float Xr = g[0] + ar * g[2] - ai * g[3] + br2 * g[4] - bi2 * g[5]
                        + cr * g[6] - ci * g[7];
        float Xi = g[1] + ar * g[3] + ai * g[2] + br2 * g[5] + bi2 * g[4]
                        + cr * g[7] + ci * g[6];
        int k = ks[v];
        float br = b_real[k], bi = b_imag[k];
        out_real[o + k] = Xr + (br - bi);
        out_imag[o + k] = Xi + (br + bi);
    }
}

// combine X = G0 + t1*G1 + t2*G2 + t3*G3
DINL void comb4(float& Xr, float& Xi, const float* gr_, const float* gi_, const float* t) {
    Xr = gr_[0] + t[0] * gr_[1] - t[1] * gi_[1]
                + t[2] * gr_[2] - t[3] * gi_[2]
                + t[4] * gr_[3] - t[5] * gi_[3];
    Xi = gi_[0] + t[0] * gi_[1] + t[1] * gr_[1]
                + t[2] * gi_[2] + t[3] * gr_[2]
                + t[4] * gi_[3] + t[5] * gr_[3];
}

// ---------------- main GEMM kernel (bulk-copy, persistent, radix-4 fused) -----
__global__ void __launch_bounds__(THREADS, 2)
dft_gemm_kernel(const float* __restrict__ b_real, const float* __restrict__ b_imag,
                float* __restrict__ out_real, float* __restrict__ out_imag) {
    extern __shared__ __align__(1024) char sm[];
    uint32_t sb = (uint32_t)__cvta_generic_to_shared(sm);
    const int tid = threadIdx.x, wid = tid >> 5, lid = tid & 31;
    const int h = blockIdx.x;                          // n-half: n0 = 64h
    const int n0 = h * BN;
    const int tile0 = blockIdx.y * MITER;              // base m-tile
    const int wm = (wid >> 2) * 32;
    const int wn = (wid & 3) * 16;

    if (tid == 0) {
        mbar_init(sb + MB_B, 1);
        mbar_init(sb + MB_A0, 1);
        mbar_init(sb + MB_A1, 1);
    }
    __syncthreads();
    if (tid == 0) {
        // A stages first (mainloop consumes A before B is touched heavily)
        mbar_expect(sb + MB_A0, 16384);
        bulk_g2s(sb + OFF_A,
                 (const char*)g_xr_t + (((size_t)(tile0 * 4 + 0)) << 13), 8192, sb + MB_A0);
        bulk_g2s(sb + OFF_A + 8192,
                 (const char*)g_xi_t + (((size_t)(tile0 * 4 + 0)) << 13), 8192, sb + MB_A0);
        mbar_expect(sb + MB_A1, 16384);
        bulk_g2s(sb + OFF_A + 16384,
                 (const char*)g_xr_t + (((size_t)(tile0 * 4 + 1)) << 13), 8192, sb + MB_A1);
        bulk_g2s(sb + OFF_A + 16384 + 8192,
                 (const char*)g_xi_t + (((size_t)(tile0 * 4 + 1)) << 13), 8192, sb + MB_A1);
        mbar_expect(sb + MB_B, 65536);
#pragma unroll
        for (int c = 0; c < 4; ++c) {
            bulk_g2s(sb + OFF_B + c * 16384,
                     (const char*)g_wr_t + (((size_t)(h * 4 + c)) << 13), 8192, sb + MB_B);
            bulk_g2s(sb + OFF_B + c * 16384 + 8192,
                     (const char*)g_wi_t + (((size_t)(h * 4 + c)) << 13), 8192, sb + MB_B);
        }
    }

    // stage twiddle/bias tables (coalesced; overlaps bulk loads)
    float* TB = (float*)(sm + SM_TAB);
    {
        int j = tid & 63, q4 = tid >> 6;
        int c = n0 + j;
        int kd = c + 256 * q4;
        int km = (256 - c + 256 * q4) & 1023;
        int base = (j * 4 + q4) * 6;
        float2 w1 = g_tw[kd], w2 = g_tw[(2 * kd) & 1023], w3 = g_tw[(3 * kd) & 1023];
        TB[T_TWD + base + 0] = w1.x; TB[T_TWD + base + 1] = w1.y;
        TB[T_TWD + base + 2] = w2.x; TB[T_TWD + base + 3] = w2.y;
        TB[T_TWD + base + 4] = w3.x; TB[T_TWD + base + 5] = w3.y;
        w1 = g_tw[km]; w2 = g_tw[(2 * km) & 1023]; w3 = g_tw[(3 * km) & 1023];
        TB[T_TWM + base + 0] = w1.x; TB[T_TWM + base + 1] = w1.y;
        TB[T_TWM + base + 2] = w2.x; TB[T_TWM + base + 3] = w2.y;
        TB[T_TWM + base + 4] = w3.x; TB[T_TWM + base + 5] = w3.y;
        int bb = (j * 4 + q4) * 2;
        float a = b_real[kd], b = b_imag[kd];
        TB[T_BD + bb] = a - b; TB[T_BD + bb + 1] = a + b;
        a = b_real[km]; b = b_imag[km];
        TB[T_BM + bb] = a - b; TB[T_BM + bb + 1] = a + b;
    }
    __syncthreads();
    mbar_wait(sb + MB_B, 0);

    float P1[2][2][4], P2[2][2][4], P3[2][2][4], P4[2][2][4];
#pragma unroll
    for (int a = 0; a < 2; ++a)
#pragma unroll
        for (int b = 0; b < 2; ++b)
#pragma unroll
            for (int c = 0; c < 4; ++c) {
                P1[a][b][c] = 0.f; P2[a][b][c] = 0.f;
                P3[a][b][c] = 0.f; P4[a][b][c] = 0.f;
            }

    const int lrow = lid & 15;
    const int lcb  = (lid >> 4) << 4;
    const int gr = lid >> 2, gc = lid & 3;
    const int q  = gr & 3;
    const int lbase = lid & ~12;

    for (int i = 0; i < NITER; ++i) {
        mbar_wait(sb + MB_A0 + (uint32_t)((i & 1) * 8), (uint32_t)((i >> 1) & 1));
        const uint32_t stA = sb + OFF_A + (i & 1) * 16384;
        const uint32_t stB = sb + OFF_B + (i & 3) * 16384;
#pragma unroll
        for (int kk = 0; kk < 4; ++kk) {
            const uint32_t colb = (uint32_t)(kk * 32 + lcb);
            uint32_t Axr[2][4], Axi[2][4];
#pragma unroll
            for (int mt = 0; mt < 2; ++mt) {
                uint32_t ro = (uint32_t)((wm + mt * 16 + lrow) << 7) + colb;
                ldsm4(Axr[mt], stA + swz(ro));
                ldsm4(Axi[mt], stA + 8192 + swz(ro));
            }
            uint32_t Bwr[4], Bwi[4], t4[4];
            {
                uint32_t ro = (uint32_t)((wn + lrow) << 7) + colb;
                ldsm4(t4, stB + swz(ro));
                Bwr[0] = t4[0]; Bwr[1] = t4[2]; Bwr[2] = t4[1]; Bwr[3] = t4[3];
                ldsm4(t4, stB + 8192 + swz(ro));
                Bwi[0] = t4[0]; Bwi[1] = t4[2]; Bwi[2] = t4[1]; Bwi[3] = t4[3];
            }
#pragma unroll
            for (int mt = 0; mt < 2; ++mt)
#pragma unroll
                for (int nt = 0; nt < 2; ++nt) {
                    const int ob = nt * 2;
                    mma16816(P1[mt][nt], Axr[mt], Bwr[ob], Bwr[ob + 1]);
                    mma16816(P2[mt][nt], Axi[mt], Bwi[ob], Bwi[ob + 1]);
                    mma16816(P3[mt][nt], Axr[mt], Bwi[ob], Bwi[ob + 1]);
                    mma16816(P4[mt][nt], Axi[mt], Bwr[ob], Bwr[ob + 1]);
                }
        }
        __syncthreads();                               // all warps done with stage i&1
        if (i + 2 < NITER && tid == 0) {
            int l = i + 2, mi2 = l >> 2, c2 = l & 3;
            uint32_t mb = sb + MB_A0 + (uint32_t)((i & 1) * 8);
            mbar_expect(mb, 16384);
            bulk_g2s(sb + OFF_A + (i & 1) * 16384,
                     (const char*)g_xr_t + (((size_t)((tile0 + mi2) * 4 + c2)) << 13), 8192, mb);
            bulk_g2s(sb + OFF_A + (i & 1) * 16384 + 8192,
                     (const char*)g_xi_t + (((size_t)((tile0 + mi2) * 4 + c2)) << 13), 8192, mb);
        }

        if ((i & 3) == 3) {
            // ------- fused 4-phase combine epilogue (tables hoisted per nt) -------
            const int m0 = (tile0 + (i >> 2)) * BM;
#pragma unroll
            for (int nt = 0; nt < 2; ++nt) {
                const int jl = wn + nt * 8 + gc * 2;
                const int iA = (jl * 4 + q), iB = ((jl + 1) * 4 + q);
                // hoisted twiddle/bias tables (invariant across mt, rg)
                float tdA[6], tdB[6], tmA[6], tmB[6];
#pragma unroll
                for (int v = 0; v < 6; ++v) {
                    tdA[v] = TB[T_TWD + iA * 6 + v];
                    tdB[v] = TB[T_TWD + iB * 6 + v];
                    tmA[v] = TB[T_TWM + iA * 6 + v];
                    tmB[v] = TB[T_TWM + iB * 6 + v];
                }
                const float bdA0 = TB[T_BD + iA * 2], bdA1 = TB[T_BD + iA * 2 + 1];
                const float bdB0 = TB[T_BD + iB * 2], bdB1 = TB[T_BD + iB * 2 + 1];
                const float bmA0 = TB[T_BM + iA * 2], bmA1 = TB[T_BM + iA * 2 + 1];
                const float bmB0 = TB[T_BM + iB * 2], bmB1 = TB[T_BM + iB * 2 + 1];
                const int kd  = (n0 + jl) + 256 * q;
                const int kmA = 256 - (n0 + jl) + 256 * q;
#pragma unroll
                for (int mt = 0; mt < 2; ++mt)
#pragma unroll
                    for (int rg = 0; rg < 2; ++rg) {
                        const int e0 = rg * 2, e1 = e0 + 1;
                        size_t s = (size_t)(m0 >> 2) + (wm >> 2) + mt * 4 + rg * 2 + (gr >> 2);
                        float* pr = out_real + (s << 10);
                        float* pi = out_imag + (s << 10);
                        float GdrA = P1[mt][nt][e0] - P2[mt][nt][e0];
                        float GdiA = P3[mt][nt][e0] + P4[mt][nt][e0];
                        float GmrA = P1[mt][nt][e0] + P2[mt][nt][e0];
                        float GmiA = P4[mt][nt][e0] - P3[mt][nt][e0];
                        float GdrB = P1[mt][nt][e1] - P2[mt][nt][e1];
                        float GdiB = P3[mt][nt][e1] + P4[mt][nt][e1];
                        float GmrB = P1[mt][nt][e1] + P2[mt][nt][e1];
                        float GmiB = P4[mt][nt][e1] - P3[mt][nt][e1];
                        float dAr[4], dAi[4], mAr[4], mAi[4];
                        float dBr[4], dBi[4], mBr[4], mBi[4];
#pragma unroll
                        for (int p = 0; p < 4; ++p) {
                            int src = lbase | (p << 2);
                            dAr[p] = __shfl_sync(0xFFFFFFFFu, GdrA, src);
                            dAi[p] = __shfl_sync(0xFFFFFFFFu, GdiA, src);
                            mAr[p] = __shfl_sync(0xFFFFFFFFu, GmrA, src);
                            mAi[p] = __shfl_sync(0xFFFFFFFFu, GmiA, src);
                            dBr[p] = __shfl_sync(0xFFFFFFFFu, GdrB, src);
                            dBi[p] = __shfl_sync(0xFFFFFFFFu, GdiB, src);
                            mBr[p] = __shfl_sync(0xFFFFFFFFu, GmrB, src);
                            mBi[p] = __shfl_sync(0xFFFFFFFFu, GmiB, src);
                        }
                        {
                            float XrA, XiA, XrB, XiB;
                            comb4(XrA, XiA, dAr, dAi, tdA);
                            comb4(XrB, XiB, dBr, dBi, tdB);
                            float2 v;
                            v.x = XrA + bdA0; v.y = XrB + bdB0;
                            *(float2*)(pr + kd) = v;
                            v.x = XiA + bdA1; v.y = XiB + bdB1;
                            *(float2*)(pi + kd) = v;
                        }
                        {
                            float XrA, XiA, XrB, XiB;
                            comb4(XrA, XiA, mAr, mAi, tmA);
                            comb4(XrB, XiB, mBr, mBi, tmB);
                            pr[kmA - 1] = XrB + bmB0;
                            pi[kmA - 1] = XiB + bmB1;
                            if (kmA < 1024) {
                                pr[kmA] = XrA + bmA0;
                                pi[kmA] = XiA + bmA1;
                            }
                        }
                    }
            }
            // zero accumulators for next m-tile
#pragma unroll
            for (int a = 0; a < 2; ++a)
#pragma unroll
                for (int b = 0; b < 2; ++b)
#pragma unroll
                    for (int c = 0; c < 4; ++c) {
                        P1[a][b][c] = 0.f; P2[a][b][c] = 0.f;
                        P3[a][b][c] = 0.f; P4[a][b][c] = 0.f;
                    }
        }
    }
}

// ---------------- launch ----------------
extern "C" void kernel_launch(void* const* d_in, const int* in_sizes, int n_in,
                              void* d_out, int out_size) {
    (void)in_sizes; (void)n_in; (void)out_size;
    const float4* xr = (const float4*)d_in[0];
    const float4* xi = (const float4*)d_in[1];
    const float*  wr = (const float*)d_in[2];
    const float*  wi = (const float*)d_in[3];
    const float*  br = (const float*)d_in[4];
    const float*  bi = (const float*)d_in[5];
    float* out_real = (float*)d_out;
    float* out_imag = out_real + (size_t)M_SIG * 1024;

    convert_w_kernel<<<16, 256>>>((const float4*)wr, (const float4*)wi);
    convert_x_kernel<<<8192, 256>>>(xr, xi);
    col128_kernel<<<128, 256>>>(br, bi, out_real, out_imag);

    cudaFuncSetAttribute(dft_gemm_kernel,
                         cudaFuncAttributeMaxDynamicSharedMemorySize, SMEM_TOTAL);
    dim3 grid(128 / BN, (MR / BM) / MITER);   // (2, 512)
    dft_gemm_kernel<<<grid, THREADS, SMEM_TOTAL>>>(br, bi, out_real, out_imag);
}

// round 15
// speedup vs baseline: 3.2359x; 1.0639x over previous
#include <cuda_runtime.h>
#include <cuda_fp16.h>
#include <cstdint>

#define DINL __device__ __forceinline__

// ---------------- problem sizes ----------------
static constexpr int M_SIG = 32768;        // independent signals
static constexpr int MR    = 131072;       // scratch rows: 4 phases per signal
static constexpr int BM = 64;              // scratch rows per m-tile
static constexpr int BN = 64;              // direct W256 cols per CTA (of 128)
static constexpr int MITER = 4;            // m-tiles per CTA
static constexpr int NITER = 4 * MITER;    // 16 linear chunks
static constexpr int THREADS = 256;

// ---------------- smem layout (bytes) ----------------
static constexpr uint32_t OFF_B  = 0;       // 4 chunks x (wr 8KB + wi 8KB) = 64KB resident
static constexpr uint32_t OFF_A  = 65536;   // 2 stages x (xr 8KB + xi 8KB) = 32KB
static constexpr uint32_t SM_TAB = 98304;   // tables: 2048 floats = 8192B
static constexpr uint32_t MB_B   = 114688;  // mbarriers (region reserved to here)
static constexpr uint32_t MB_A0  = 114696;
static constexpr uint32_t MB_A1  = 114704;
static constexpr uint32_t SMEM_TOTAL = 114816;   // x2 CTA = 229632 <= 232448

// table float offsets
static constexpr int T_PD = 0;      // [64][4][2] w^{c*p}        (phase twiddle, direct)
static constexpr int T_PM = 512;    // [64][4][2] w^{(256-c)*p}  (phase twiddle, mirror)
static constexpr int T_BD = 1024;   // [64][4][2] bias direct  (br-bi, br+bi) @ k=c+256q
static constexpr int T_BM = 1536;   // [64][4][2] bias mirror                 (ends 2048)

// ---------------- global scratch: PRE-SWIZZLED 8KB tiles ----------------
// A: tile index (mtile*4 + chunk), mtile = scratch_row/64, chunk = kcol/64.
// Inside a tile: 64 rows x 128B, SW128; row = 4*(signal&15) + phase.
__device__ __align__(128) __half g_xr_t[33554432];
__device__ __align__(128) __half g_xi_t[33554432];
// B: tile index (h*4 + chunk), h = W256row/64.
__device__ __align__(128) __half g_wr_t[32768];
__device__ __align__(128) __half g_wi_t[32768];
// twiddles: g_tw[k] = (w1024_real[k][1], w1024_imag[k][1])
__device__ __align__(16) float2 g_tw[1024];
// col128 partials: per signal 16 floats
__device__ __align__(16) float g_part[524288];

// ---------------- PTX helpers ----------------
DINL uint32_t swz(uint32_t o) { return o ^ ((o >> 3) & 0x70); }

DINL void mbar_init(uint32_t a, uint32_t cnt) {
    asm volatile("mbarrier.init.shared.b64 [%0], %1;\n" :: "r"(a), "r"(cnt) : "memory");
}
DINL void mbar_expect(uint32_t a, uint32_t bytes) {
    asm volatile("mbarrier.arrive.expect_tx.shared.b64 _, [%0], %1;\n"
                 :: "r"(a), "r"(bytes) : "memory");
}
DINL void mbar_wait(uint32_t a, uint32_t parity) {
    asm volatile(
        "{\n\t.reg .pred P;\n"
        "WLP_%=:\n\t"
        "mbarrier.try_wait.parity.acquire.cta.shared::cta.b64 P, [%0], %1, 0x989680;\n\t"
        "@!P bra WLP_%=;\n\t"
        "}\n" :: "r"(a), "r"(parity) : "memory");
}
DINL void bulk_g2s(uint32_t dst, const void* src, uint32_t bytes, uint32_t mbar) {
    asm volatile(
        "cp.async.bulk.shared::cta.global.mbarrier::complete_tx::bytes [%0], [%1], %2, [%3];\n"
        :: "r"(dst), "l"(src), "r"(bytes), "r"(mbar) : "memory");
}

DINL void ldsm4(uint32_t* r, uint32_t a) {
    asm volatile("ldmatrix.sync.aligned.m8n8.x4.shared.b16 {%0,%1,%2,%3}, [%4];\n"
                 : "=r"(r[0]), "=r"(r[1]), "=r"(r[2]), "=r"(r[3]) : "r"(a));
}

DINL void mma16816(float* d, const uint32_t* a, uint32_t b0, uint32_t b1) {
    asm volatile(
        "mma.sync.aligned.m16n8k16.row.col.f32.f16.f16.f32 "
        "{%0,%1,%2,%3}, {%4,%5,%6,%7}, {%8,%9}, {%0,%1,%2,%3};\n"
        : "+f"(d[0]), "+f"(d[1]), "+f"(d[2]), "+f"(d[3])
        : "r"(a[0]), "r"(a[1]), "r"(a[2]), "r"(a[3]), "r"(b0), "r"(b1));
}

// radix-4 lane butterfly: input G (this lane's phase p), twiddle t = w^{c*p}.
// Output: X[c + 256*qOut] where qOut = bitrev2(p). b0 = gr bit0 (xor4), b1 = gr bit1 (xor8).
DINL void bfly4(float& Xr, float& Xi, float Gr, float Gi, float tr, float ti,
                bool b0, bool b1) {
    float Hr = tr * Gr - ti * Gi;
    float Hi = tr * Gi + ti * Gr;
    float o1r = __shfl_xor_sync(0xFFFFFFFFu, Hr, 8);
    float o1i = __shfl_xor_sync(0xFFFFFFFFu, Hi, 8);
    float Cr = b1 ? (o1r - Hr) : (Hr + o1r);
    float Ci = b1 ? (o1i - Hi) : (Hi + o1i);
    float o2r = __shfl_xor_sync(0xFFFFFFFFu, Cr, 4);
    float o2i = __shfl_xor_sync(0xFFFFFFFFu, Ci, 4);
    // rot(z) = i^{-b1} z : b1=0 -> z ; b1=1 -> (z.im, -z.re)
    float rsr = b1 ? Ci : Cr, rsi = b1 ? -Cr : Ci;       // rot(self)
    float ror = b1 ? o2i : o2r, roi = b1 ? -o2r : o2i;   // rot(other)
    Xr = b0 ? (o2r - rsr) : (Cr + ror);
    Xi = b0 ? (o2i - rsi) : (Ci + roi);
}

// ---------------- conversion ----------------
DINL uint32_t h2u(float a, float b) {
    __half2 h = __floats2half2_rn(a, b);
    return *(uint32_t*)&h;
}

// 4-phase deinterleave -> pre-swizzled tiles + fused col128 partial sums.
__global__ void __launch_bounds__(256) convert_x_kernel(const float4* __restrict__ xr,
                                                        const float4* __restrict__ xi) {
    size_t gid = (size_t)blockIdx.x * 256 + threadIdx.x;   // 2M threads
    size_t m = gid >> 6;
    int j = (int)(gid & 63);
    const int c = j >> 4;                                  // k-chunk
    const uint32_t inb = (uint32_t)((j & 15) << 3);        // byte col in row
    char* bxr = (char*)g_xr_t + (((m >> 4) * 4 + c) << 13);
    char* bxi = (char*)g_xi_t + (((m >> 4) * 4 + c) << 13);
    const int rb = 4 * (int)(m & 15);
    float pr[4], pq[4];                                    // col128 partials (re/im)
    {
        const float4* p = xr + (m << 8) + (j << 2);
        float4 f0 = p[0], f1 = p[1], f2 = p[2], f3 = p[3];
        uint2 v;
        v.x = h2u(f0.x, f1.x); v.y = h2u(f2.x, f3.x);
        *(uint2*)(bxr + swz(((rb + 0) << 7) | inb)) = v;
        v.x = h2u(f0.y, f1.y); v.y = h2u(f2.y, f3.y);
        *(uint2*)(bxr + swz(((rb + 1) << 7) | inb)) = v;
        v.x = h2u(f0.z, f1.z); v.y = h2u(f2.z, f3.z);
        *(uint2*)(bxr + swz(((rb + 2) << 7) | inb)) = v;
        v.x = h2u(f0.w, f1.w); v.y = h2u(f2.w, f3.w);
        *(uint2*)(bxr + swz(((rb + 3) << 7) | inb)) = v;
        pr[0] = f0.x - f1.x + f2.x - f3.x;
        pr[1] = f0.y - f1.y + f2.y - f3.y;
        pr[2] = f0.z - f1.z + f2.z - f3.z;
        pr[3] = f0.w - f1.w + f2.w - f3.w;
    }
    {
        const float4* p = xi + (m << 8) + (j << 2);
        float4 f0 = p[0], f1 = p[1], f2 = p[2], f3 = p[3];
        uint2 v;
        v.x = h2u(f0.x, f1.x); v.y = h2u(f2.x, f3.x);
        *(uint2*)(bxi + swz(((rb + 0) << 7) | inb)) = v;
        v.x = h2u(f0.y, f1.y); v.y = h2u(f2.y, f3.y);
        *(uint2*)(bxi + swz(((rb + 1) << 7) | inb)) = v;
        v.x = h2u(f0.z, f1.z); v.y = h2u(f2.z, f3.z);
        *(uint2*)(bxi + swz(((rb + 2) << 7) | inb)) = v;
        v.x = h2u(f0.w, f1.w); v.y = h2u(f2.w, f3.w);
        *(uint2*)(bxi + swz(((rb + 3) << 7) | inb)) = v;
        pq[0] = f0.x - f1.x + f2.x - f3.x;
        pq[1] = f0.y - f1.y + f2.y - f3.y;
        pq[2] = f0.z - f1.z + f2.z - f3.z;
        pq[3] = f0.w - f1.w + f2.w - f3.w;
    }
#pragma unroll
    for (int sh = 16; sh > 0; sh >>= 1) {
#pragma unroll
        for (int v = 0; v < 4; ++v) {
            pr[v] += __shfl_xor_sync(0xFFFFFFFFu, pr[v], sh);
            pq[v] += __shfl_xor_sync(0xFFFFFFFFu, pq[v], sh);
        }
    }
    if ((threadIdx.x & 31) == 0) {
        size_t base = (m << 4) + (size_t)((j >> 5) << 3);
        *(float4*)(g_part + base)     = make_float4(pr[0], pr[1], pr[2], pr[3]);
        *(float4*)(g_part + base + 4) = make_float4(pq[0], pq[1], pq[2], pq[3]);
    }
}

// W256 rows -> pre-swizzled tiles; first 1024 threads also gather twiddles
__global__ void __launch_bounds__(256) convert_w_kernel(const float4* __restrict__ wr,
                                                        const float4* __restrict__ wi) {
    size_t gid = (size_t)blockIdx.x * 256 + threadIdx.x;   // 4096 threads
    if (gid < 1024) {
        g_tw[gid] = make_float2(((const float*)wr)[(gid << 10) + 1],
                                ((const float*)wi)[(gid << 10) + 1]);
    }
    size_t k = gid >> 5;                                   // W256 row 0..127
    int j = (int)(gid & 31);                               // 8-half group
    size_t src = (k << 10) + (j << 1);                     // float4 idx into w1024 row 4k
    const int h = (int)(k >> 6), r = (int)(k & 63), c = j >> 3;
    uint32_t off = swz((uint32_t)((r << 7) | ((j & 7) << 4)));
    char* bwr = (char*)g_wr_t + (((h * 4 + c)) << 13);
    char* bwi = (char*)g_wi_t + (((h * 4 + c)) << 13);
    float4 a = wr[src], b = wr[src + 1];
    uint4 u;
    u.x = h2u(a.x, a.y); u.y = h2u(a.z, a.w);
    u.z = h2u(b.x, b.y); u.w = h2u(b.z, b.w);
    *(uint4*)(bwr + off) = u;
    float4 cc = wi[src], d = wi[src + 1];
    u.x = h2u(cc.x, cc.y); u.y = h2u(cc.z, cc.w);
    u.z = h2u(d.x, d.y); u.w = h2u(d.z, d.w);
    *(uint4*)(bwi + off) = u;
}

// ---------------- special cols from partials: k in {128,384,640,896} ----------
__global__ void __launch_bounds__(256) col128_kernel(const float* __restrict__ b_real,
                                                     const float* __restrict__ b_imag,
                                                     float* __restrict__ out_real,
                                                     float* __restrict__ out_imag) {
    int s = blockIdx.x * 256 + threadIdx.x;            // one thread per signal
    float4 h0r = *(const float4*)(g_part + ((size_t)s << 4));
    float4 h0i = *(const float4*)(g_part + ((size_t)s << 4) + 4);
    float4 h1r = *(const float4*)(g_part + ((size_t)s << 4) + 8);
    float4 h1i = *(const float4*)(g_part + ((size_t)s << 4) + 12);
    float g[8];
    g[0] = h0r.x + h1r.x; g[1] = h0i.x + h1i.x;        // G0 re/im
    g[2] = h0r.y + h1r.y; g[3] = h0i.y + h1i.y;        // G1
    g[4] = h0r.z + h1r.z; g[5] = h0i.z + h1i.z;        // G2
    g[6] = h0r.w + h1r.w; g[7] = h0i.w + h1i.w;        // G3
    const int rows[6] = {128, 256, 384, 640, 768, 896};
    float twr[6], twi[6];
#pragma unroll
    for (int v = 0; v < 6; ++v) { float2 w = g_tw[rows[v]]; twr[v] = w.x; twi[v] = w.y; }
    size_t o = ((size_t)s << 10);
    const int ks[4] = {128, 384, 640, 896};
    const int ia[4] = {0, 2, 3, 5};
    const int ib[4] = {1, 4, 1, 4};
    const int ic[4] = {2, 0, 5, 3};
#pragma unroll
    for (int v = 0; v < 4; ++v) {
        float ar = twr[ia[v]], ai = twi[ia[v]];
        float br2 = twr[ib[v]], bi2 = twi[ib[v]];
        float cr = twr[ic[v]], ci = twi[ic[v]];
        float Xr = g[0] + ar * g[2] - ai * g[3] + br2 * g[4] - bi2 * g[5]
                        + cr * g[6] - ci * g[7];
        float Xi = g[1] + ar * g[3] + ai * g[2] + br2 * g[5] + bi2 * g[4]
                        + cr * g[7] + ci * g[6];
        int k = ks[v];
        float br = b_real[k], bi = b_imag[k];
        out_real[o + k] = Xr + (br - bi);
        out_imag[o + k] = Xi + (br + bi);
    }
}

// ---------------- main GEMM kernel (bulk-copy, persistent, butterfly epi) -----
__global__ void __launch_bounds__(THREADS, 2)
dft_gemm_kernel(const float* __restrict__ b_real, const float* __restrict__ b_imag,
                float* __restrict__ out_real, float* __restrict__ out_imag) {
    extern __shared__ __align__(1024) char sm[];
    uint32_t sb = (uint32_t)__cvta_generic_to_shared(sm);
    const int tid = threadIdx.x, wid = tid >> 5, lid = tid & 31;
    const int h = blockIdx.x;                          // n-half: n0 = 64h
    const int n0 = h * BN;
    const int tile0 = blockIdx.y * MITER;              // base m-tile
    const int wm = (wid >> 2) * 32;
    const int wn = (wid & 3) * 16;

    if (tid == 0) {
        mbar_init(sb + MB_B, 1);
        mbar_init(sb + MB_A0, 1);
        mbar_init(sb + MB_A1, 1);
    }
    __syncthreads();
    if (tid == 0) {
        mbar_expect(sb + MB_A0, 16384);
        bulk_g2s(sb + OFF_A,
                 (const char*)g_xr_t + (((size_t)(tile0 * 4 + 0)) << 13), 8192, sb + MB_A0);
        bulk_g2s(sb + OFF_A + 8192,
                 (const char*)g_xi_t + (((size_t)(tile0 * 4 + 0)) << 13), 8192, sb + MB_A0);
        mbar_expect(sb + MB_A1, 16384);
        bulk_g2s(sb + OFF_A + 16384,
                 (const char*)g_xr_t + (((size_t)(tile0 * 4 + 1)) << 13), 8192, sb + MB_A1);
        bulk_g2s(sb + OFF_A + 16384 + 8192,
                 (const char*)g_xi_t + (((size_t)(tile0 * 4 + 1)) << 13), 8192, sb + MB_A1);
        mbar_expect(sb + MB_B, 65536);
#pragma unroll
        for (int c = 0; c < 4; ++c) {
            bulk_g2s(sb + OFF_B + c * 16384,
                     (const char*)g_wr_t + (((size_t)(h * 4 + c)) << 13), 8192, sb + MB_B);
            bulk_g2s(sb + OFF_B + c * 16384 + 8192,
                     (const char*)g_wi_t + (((size_t)(h * 4 + c)) << 13), 8192, sb + MB_B);
        }
    }

    // stage phase-twiddle + bias tables (coalesced; overlaps bulk loads)
    float* TB = (float*)(sm + SM_TAB);
    {
        int j = tid & 63, p4 = tid >> 6;               // p4: phase / q index 0..3
        int c = n0 + j;
        int base = (j * 4 + p4) * 2;
        float2 w1 = g_tw[(c * p4) & 1023];             // w^{c*p}
        TB[T_PD + base] = w1.x; TB[T_PD + base + 1] = w1.y;
        w1 = g_tw[((256 - c) * p4) & 1023];            // w^{(256-c)*p}
        TB[T_PM + base] = w1.x; TB[T_PM + base + 1] = w1.y;
        int kd = c + 256 * p4;
        int km = (256 - c + 256 * p4) & 1023;
        float a = b_real[kd], b = b_imag[kd];
        TB[T_BD + base] = a - b; TB[T_BD + base + 1] = a + b;
        a = b_real[km]; b = b_imag[km];
        TB[T_BM + base] = a - b; TB[T_BM + base + 1] = a + b;
    }
    __syncthreads();
    mbar_wait(sb + MB_B, 0);

    float P1[2][2][4], P2[2][2][4], P3[2][2][4], P4[2][2][4];
#pragma unroll
    for (int a = 0; a < 2; ++a)
#pragma unroll
        for (int b = 0; b < 2; ++b)
#pragma unroll
            for (int c = 0; c < 4; ++c) {
                P1[a][b][c] = 0.f; P2[a][b][c] = 0.f;
                P3[a][b][c] = 0.f; P4[a][b][c] = 0.f;
            }

    const int lrow = lid & 15;
    const int lcb  = (lid >> 4) << 4;
    const int gr = lid >> 2, gc = lid & 3;
    const int p  = gr & 3;                             // lane's data phase
    const int qOut = ((p & 1) << 1) | (p >> 1);        // butterfly output quarter
    const bool b0 = (gr & 1) != 0, b1 = (gr & 2) != 0;

    for (int i = 0; i < NITER; ++i) {
        mbar_wait(sb + MB_A0 + (uint32_t)((i & 1) * 8), (uint32_t)((i >> 1) & 1));
        const uint32_t stA = sb + OFF_A + (i & 1) * 16384;
        const uint32_t stB = sb + OFF_B + (i & 3) * 16384;
#pragma unroll
        for (int kk = 0; kk < 4; ++kk) {
            const uint32_t colb = (uint32_t)(kk * 32 + lcb);
            uint32_t Axr[2][4], Axi[2][4];
#pragma unroll
            for (int mt = 0; mt < 2; ++mt) {
                uint32_t ro = (uint32_t)((wm + mt * 16 + lrow) << 7) + colb;
                ldsm4(Axr[mt], stA + swz(ro));
                ldsm4(Axi[mt], stA + 8192 + swz(ro));
            }
            uint32_t Bwr[4], Bwi[4], t4[4];
            {
                uint32_t ro = (uint32_t)((wn + lrow) << 7) + colb;
                ldsm4(t4, stB + swz(ro));
                Bwr[0] = t4[0]; Bwr[1] = t4[2]; Bwr[2] = t4[1]; Bwr[3] = t4[3];
                ldsm4(t4, stB + 8192 + swz(ro));
                Bwi[0] = t4[0]; Bwi[1] = t4[2]; Bwi[2] = t4[1]; Bwi[3] = t4[3];
            }
#pragma unroll
            for (int mt = 0; mt < 2; ++mt)
#pragma unroll
                for (int nt = 0; nt < 2; ++nt) {
                    const int ob = nt * 2;
                    mma16816(P1[mt][nt], Axr[mt], Bwr[ob], Bwr[ob + 1]);
                    mma16816(P2[mt][nt], Axi[mt], Bwi[ob], Bwi[ob + 1]);
                    mma16816(P3[mt][nt], Axr[mt], Bwi[ob], Bwi[ob + 1]);
                    mma16816(P4[mt][nt], Axi[mt], Bwr[ob], Bwr[ob + 1]);
                }
        }
        __syncthreads();                               // all warps done with stage i&1
        if (i + 2 < NITER && tid == 0) {
            int l = i + 2, mi2 = l >> 2, c2 = l & 3;
            uint32_t mb = sb + MB_A0 + (uint32_t)((i & 1) * 8);
            mbar_expect(mb, 16384);
            bulk_g2s(sb + OFF_A + (i & 1) * 16384,
                     (const char*)g_xr_t + (((size_t)((tile0 + mi2) * 4 + c2)) << 13), 8192, mb);
            bulk_g2s(sb + OFF_A + (i & 1) * 16384 + 8192,
                     (const char*)g_xi_t + (((size_t)((tile0 + mi2) * 4 + c2)) << 13), 8192, mb);
        }

        if ((i & 3) == 3) {
            // ---- butterfly combine epilogue for m-tile i>>2 ----
            const int m0 = (tile0 + (i >> 2)) * BM;
#pragma unroll
            for (int nt = 0; nt < 2; ++nt) {
                const int jl = wn + nt * 8 + gc * 2;
                const int iA = (jl * 4 + p) * 2, iB = ((jl + 1) * 4 + p) * 2;
                const int jA = (jl * 4 + qOut) * 2, jB = ((jl + 1) * 4 + qOut) * 2;
                const float pdAr = TB[T_PD + iA], pdAi = TB[T_PD + iA + 1];
                const float pdBr = TB[T_PD + iB], pdBi = TB[T_PD + iB + 1];
                const float pmAr = TB[T_PM + iA], pmAi = TB[T_PM + iA + 1];
                const float pmBr = TB[T_PM + iB], pmBi = TB[T_PM + iB + 1];
                const float bdA0 = TB[T_BD + jA], bdA1 = TB[T_BD + jA + 1];
                const float bdB0 = TB[T_BD + jB], bdB1 = TB[T_BD + jB + 1];
                const float bmA0 = TB[T_BM + jA], bmA1 = TB[T_BM + jA + 1];
                const float bmB0 = TB[T_BM + jB], bmB1 = TB[T_BM + jB + 1];
                const int kd  = (n0 + jl) + 256 * qOut;
                const int kmA = 256 - (n0 + jl) + 256 * qOut;
#pragma unroll
                for (int mt = 0; mt < 2; ++mt)
#pragma unroll
                    for (int rg = 0; rg < 2; ++rg) {
                        const int e0 = rg * 2, e1 = e0 + 1;
                        size_t s = (size_t)(m0 >> 2) + (wm >> 2) + mt * 4 + rg * 2 + (gr >> 2);
                        float* pr = out_real + (s << 10);
                        float* pi = out_imag + (s << 10);
                        float GdrA = P1[mt][nt][e0] - P2[mt][nt][e0];
                        float GdiA = P3[mt][nt][e0] + P4[mt][nt][e0];
                        float GmrA = P1[mt][nt][e0] + P2[mt][nt][e0];
                        float GmiA = P4[mt][nt][e0] - P3[mt][nt][e0];
                        float GdrB = P1[mt][nt][e1] - P2[mt][nt][e1];
                        float GdiB = P3[mt][nt][e1] + P4[mt][nt][e1];
                        float GmrB = P1[mt][nt][e1] + P2[mt][nt][e1];
                        float GmiB = P4[mt][nt][e1] - P3[mt][nt][e1];
                        float XrA, XiA, XrB, XiB;
                        bfly4(XrA, XiA, GdrA, GdiA, pdAr, pdAi, b0, b1);
                        bfly4(XrB, XiB, GdrB, GdiB, pdBr, pdBi, b0, b1);
                        float2 v;
                        v.x = XrA + bdA0; v.y = XrB + bdB0;
                        *(float2*)(pr + kd) = v;
                        v.x = XiA + bdA1; v.y = XiB + bdB1;
                        *(float2*)(pi + kd) = v;
                        bfly4(XrA, XiA, GmrA, GmiA, pmAr, pmAi, b0, b1);
                        bfly4(XrB, XiB, GmrB, GmiB, pmBr, pmBi, b0, b1);
                        pr[kmA - 1] = XrB + bmB0;
                        pi[kmA - 1] = XiB + bmB1;
                        if (kmA < 1024) {
                            pr[kmA] = XrA + bmA0;
                            pi[kmA] = XiA + bmA1;
                        }
                    }
            }
            // zero accumulators for next m-tile
#pragma unroll
            for (int a = 0; a < 2; ++a)
#pragma unroll
                for (int b = 0; b < 2; ++b)
#pragma unroll
                    for (int c = 0; c < 4; ++c) {
                        P1[a][b][c] = 0.f; P2[a][b][c] = 0.f;
                        P3[a][b][c] = 0.f; P4[a][b][c] = 0.f;
                    }
        }
    }
}

// ---------------- launch ----------------
extern "C" void kernel_launch(void* const* d_in, const int* in_sizes, int n_in,
                              void* d_out, int out_size) {
    (void)in_sizes; (void)n_in; (void)out_size;
    const float4* xr = (const float4*)d_in[0];
    const float4* xi = (const float4*)d_in[1];
    const float*  wr = (const float*)d_in[2];
    const float*  wi = (const float*)d_in[3];
    const float*  br = (const float*)d_in[4];
    const float*  bi = (const float*)d_in[5];
    float* out_real = (float*)d_out;
    float* out_imag = out_real + (size_t)M_SIG * 1024;

    convert_w_kernel<<<16, 256>>>((const float4*)wr, (const float4*)wi);
    convert_x_kernel<<<8192, 256>>>(xr, xi);
    col128_kernel<<<128, 256>>>(br, bi, out_real, out_imag);

    cudaFuncSetAttribute(dft_gemm_kernel,
                         cudaFuncAttributeMaxDynamicSharedMemorySize, SMEM_TOTAL);
    dim3 grid(128 / BN, (MR / BM) / MITER);   // (2, 512)
    dft_gemm_kernel<<<grid, THREADS, SMEM_TOTAL>>>(br, bi, out_real, out_imag);
}

// round 17
// speedup vs baseline: 3.3838x; 1.0457x over previous
#include <cuda_runtime.h>
#include <cuda_fp16.h>
#include <cstdint>

#define DINL __device__ __forceinline__

// ---------------- problem sizes ----------------
static constexpr int M_SIG = 32768;        // independent signals
static constexpr int MR    = 262144;       // scratch rows: 8 phases per signal
static constexpr int BM = 64;              // scratch rows per m-tile (8 signals)
static constexpr int MITER = 4;            // m-tiles per CTA
static constexpr int NITER = 2 * MITER;    // 8 linear chunks (2 K-chunks per tile)
static constexpr int THREADS = 256;

// ---------------- smem layout (bytes) ----------------
static constexpr uint32_t OFF_B  = 0;       // 2 chunks x (wr 8KB + wi 8KB) = 32KB
static constexpr uint32_t OFF_A  = 32768;   // 2 stages x (xr 8KB + xi 8KB) = 32KB
static constexpr uint32_t SM_TAB = 65536;   // tables: 4352 floats = 17408B
static constexpr uint32_t MB_B   = 82944;
static constexpr uint32_t MB_A0  = 82952;
static constexpr uint32_t MB_A1  = 82960;
static constexpr uint32_t SMEM_TOTAL = 83072;    // x2 CTA = 166144 <= 232448

// table float offsets
static constexpr int T_2D = 0;      // [64][8][2] stage-2 twiddle direct
static constexpr int T_2M = 1024;   // [64][8][2] stage-2 twiddle mirror
static constexpr int T_BD = 2048;   // [64][8][2] bias direct (br-bi, br+bi)
static constexpr int T_BM = 3072;   // [64][8][2] bias mirror
static constexpr int T_S1 = 4096;   // [64][4] stage-1: (w^{4c}, w^{4(128-c)})

// ---------------- global scratch: PRE-SWIZZLED 8KB tiles ----------------
// A: tile = (signal>>3)*2 + chunk; inside: 64 rows x 128B SW128,
// row = 8*(signal&7) + phase, cols = 64 halfs of K-chunk.
__device__ __align__(128) __half g_xr_t[33554432];
__device__ __align__(128) __half g_xi_t[33554432];
// B: W128 rows c=0..63 x 128 halfs -> 2 chunk tiles of 64x64 halfs.
__device__ __align__(128) __half g_wr_t[8192];
__device__ __align__(128) __half g_wi_t[8192];
// twiddles: g_tw[k] = (w1024_real[k][1], w1024_imag[k][1])
__device__ __align__(16) float2 g_tw[1024];
// col64 partials: 32 floats per signal
__device__ __align__(16) float g_part[1048576];

// ---------------- PTX helpers ----------------
DINL uint32_t swz(uint32_t o) { return o ^ ((o >> 3) & 0x70); }

DINL void mbar_init(uint32_t a, uint32_t cnt) {
    asm volatile("mbarrier.init.shared.b64 [%0], %1;\n" :: "r"(a), "r"(cnt) : "memory");
}
DINL void mbar_expect(uint32_t a, uint32_t bytes) {
    asm volatile("mbarrier.arrive.expect_tx.shared.b64 _, [%0], %1;\n"
                 :: "r"(a), "r"(bytes) : "memory");
}
DINL void mbar_wait(uint32_t a, uint32_t parity) {
    asm volatile(
        "{\n\t.reg .pred P;\n"
        "WLP_%=:\n\t"
        "mbarrier.try_wait.parity.acquire.cta.shared::cta.b64 P, [%0], %1, 0x989680;\n\t"
        "@!P bra WLP_%=;\n\t"
        "}\n" :: "r"(a), "r"(parity) : "memory");
}
DINL void bulk_g2s(uint32_t dst, const void* src, uint32_t bytes, uint32_t mbar) {
    asm volatile(
        "cp.async.bulk.shared::cta.global.mbarrier::complete_tx::bytes [%0], [%1], %2, [%3];\n"
        :: "r"(dst), "l"(src), "r"(bytes), "r"(mbar) : "memory");
}

DINL void ldsm4(uint32_t* r, uint32_t a) {
    asm volatile("ldmatrix.sync.aligned.m8n8.x4.shared.b16 {%0,%1,%2,%3}, [%4];\n"
                 : "=r"(r[0]), "=r"(r[1]), "=r"(r[2]), "=r"(r[3]) : "r"(a));
}

DINL void mma16816(float* d, const uint32_t* a, uint32_t b0, uint32_t b1) {
    asm volatile(
        "mma.sync.aligned.m16n8k16.row.col.f32.f16.f16.f32 "
        "{%0,%1,%2,%3}, {%4,%5,%6,%7}, {%8,%9}, {%0,%1,%2,%3};\n"
        : "+f"(d[0]), "+f"(d[1]), "+f"(d[2]), "+f"(d[3])
        : "r"(a[0]), "r"(a[1]), "r"(a[2]), "r"(a[3]), "r"(b0), "r"(b1));
}

// radix-4 lane butterfly (validated in HW round 15): lanes p' = gr&3.
DINL void bfly4(float& Xr, float& Xi, float Gr, float Gi, float tr, float ti,
                bool b0, bool b1) {
    float Hr = tr * Gr - ti * Gi;
    float Hi = tr * Gi + ti * Gr;
    float o1r = __shfl_xor_sync(0xFFFFFFFFu, Hr, 8);
    float o1i = __shfl_xor_sync(0xFFFFFFFFu, Hi, 8);
    float Cr = b1 ? (o1r - Hr) : (Hr + o1r);
    float Ci = b1 ? (o1i - Hi) : (Hi + o1i);
    float o2r = __shfl_xor_sync(0xFFFFFFFFu, Cr, 4);
    float o2i = __shfl_xor_sync(0xFFFFFFFFu, Ci, 4);
    float rsr = b1 ? Ci : Cr, rsi = b1 ? -Cr : Ci;
    float ror = b1 ? o2i : o2r, roi = b1 ? -o2r : o2i;
    Xr = b0 ? (o2r - rsr) : (Cr + ror);
    Xi = b0 ? (o2i - rsi) : (Ci + roi);
}

// radix-8 = radix-2 over bit2 (xor16, stage-1 twiddle w^{4c}) then bfly4.
DINL void bfly8(float& Xr, float& Xi, float Gr, float Gi,
                float s1r, float s1i, float t2r, float t2i,
                bool b0, bool b1, bool b2) {
    float Tr = b2 ? (s1r * Gr - s1i * Gi) : Gr;
    float Ti = b2 ? (s1r * Gi + s1i * Gr) : Gi;
    float or_ = __shfl_xor_sync(0xFFFFFFFFu, Tr, 16);
    float oi_ = __shfl_xor_sync(0xFFFFFFFFu, Ti, 16);
    float Ar = b2 ? (or_ - Tr) : (Tr + or_);
    float Ai = b2 ? (oi_ - Ti) : (Ti + oi_);
    bfly4(Xr, Xi, Ar, Ai, t2r, t2i, b0, b1);
}

// ---------------- conversion ----------------
DINL uint32_t h2u(float a, float b) {
    __half2 h = __floats2half2_rn(a, b);
    return *(uint32_t*)&h;
}

// 8-phase deinterleave -> pre-swizzled tiles + fused col64 partial sums.
// thread: signal m (gid>>6), group j (gid&63) = samples 16j..16j+15.
// sample n=8t+p: t=2j -> n=16j+p ; t=2j+1 -> n=16j+8+p.
__global__ void __launch_bounds__(256) convert_x_kernel(const float4* __restrict__ xr,
                                                        const float4* __restrict__ xi) {
    size_t gid = (size_t)blockIdx.x * 256 + threadIdx.x;   // 2M threads
    size_t m = gid >> 6;
    int j = (int)(gid & 63);
    const int chunk = j >> 5;                              // t=2j -> halfcol (2j)&63
    const uint32_t inb = (uint32_t)((j & 31) << 2);        // byte col in row
    char* bxr = (char*)g_xr_t + (((m >> 3) * 2 + chunk) << 13);
    char* bxi = (char*)g_xi_t + (((m >> 3) * 2 + chunk) << 13);
    const int rb = 8 * (int)(m & 7);                       // phase p at row rb+p
    float pr[8], pq[8];
    {
        const float4* p = xr + (m << 8) + (j << 2);
        float4 f0 = p[0], f1 = p[1], f2 = p[2], f3 = p[3];
        const float a0[8] = {f0.x, f0.y, f0.z, f0.w, f1.x, f1.y, f1.z, f1.w};
        const float a1[8] = {f2.x, f2.y, f2.z, f2.w, f3.x, f3.y, f3.z, f3.w};
#pragma unroll
        for (int p8 = 0; p8 < 8; ++p8) {
            *(uint32_t*)(bxr + swz(((rb + p8) << 7) | inb)) = h2u(a0[p8], a1[p8]);
            pr[p8] = a0[p8] - a1[p8];
        }
    }
    {
        const float4* p = xi + (m << 8) + (j << 2);
        float4 f0 = p[0], f1 = p[1], f2 = p[2], f3 = p[3];
        const float a0[8] = {f0.x, f0.y, f0.z, f0.w, f1.x, f1.y, f1.z, f1.w};
        const float a1[8] = {f2.x, f2.y, f2.z, f2.w, f3.x, f3.y, f3.z, f3.w};
#pragma unroll
        for (int p8 = 0; p8 < 8; ++p8) {
            *(uint32_t*)(bxi + swz(((rb + p8) << 7) | inb)) = h2u(a0[p8], a1[p8]);
            pq[p8] = a0[p8] - a1[p8];
        }
    }
#pragma unroll
    for (int sh = 16; sh > 0; sh >>= 1) {
#pragma unroll
        for (int v = 0; v < 8; ++v) {
            pr[v] += __shfl_xor_sync(0xFFFFFFFFu, pr[v], sh);
            pq[v] += __shfl_xor_sync(0xFFFFFFFFu, pq[v], sh);
        }
    }
    if ((threadIdx.x & 31) == 0) {
        size_t base = (m << 5) + (size_t)((j >> 5) << 4);
        *(float4*)(g_part + base)      = make_float4(pr[0], pr[1], pr[2], pr[3]);
        *(float4*)(g_part + base + 4)  = make_float4(pr[4], pr[5], pr[6], pr[7]);
        *(float4*)(g_part + base + 8)  = make_float4(pq[0], pq[1], pq[2], pq[3]);
        *(float4*)(g_part + base + 12) = make_float4(pq[4], pq[5], pq[6], pq[7]);
    }
}

// W128 rows c=0..63 (= w1024 rows 8c, first 128 cols) -> 2 chunk tiles; + g_tw
__global__ void __launch_bounds__(256) convert_w_kernel(const float4* __restrict__ wr,
                                                        const float4* __restrict__ wi) {
    size_t gid = (size_t)blockIdx.x * 256 + threadIdx.x;   // 1024 threads
    g_tw[gid] = make_float2(((const float*)wr)[(gid << 10) + 1],
                            ((const float*)wi)[(gid << 10) + 1]);
    size_t k = gid >> 4;                                   // W128 row 0..63
    int j = (int)(gid & 15);                               // 8-half group (128/8)
    size_t src = (k << 11) + (j << 1);                     // float4 idx into w1024 row 8k
    const int c = j >> 3;                                  // chunk
    uint32_t off = swz((uint32_t)((k << 7) | ((j & 7) << 4)));
    char* bwr = (char*)g_wr_t + ((size_t)c << 13);
    char* bwi = (char*)g_wi_t + ((size_t)c << 13);
    float4 a = wr[src], b = wr[src + 1];
    uint4 u;
    u.x = h2u(a.x, a.y); u.y = h2u(a.z, a.w);
    u.z = h2u(b.x, b.y); u.w = h2u(b.z, b.w);
    *(uint4*)(bwr + off) = u;
    float4 cc = wi[src], d = wi[src + 1];
    u.x = h2u(cc.x, cc.y); u.y = h2u(cc.z, cc.w);
    u.z = h2u(d.x, d.y); u.w = h2u(d.z, d.w);
    *(uint4*)(bwi + off) = u;
}

// ---------------- special cols: k = 64 + 128q ----------------
__global__ void __launch_bounds__(256) col64_kernel(const float* __restrict__ b_real,
                                                    const float* __restrict__ b_imag,
                                                    float* __restrict__ out_real,
                                                    float* __restrict__ out_imag) {
    int s = blockIdx.x * 256 + threadIdx.x;            // one thread per signal
    const float* P = g_part + ((size_t)s << 5);
    float Gr[8], Gi[8];
#pragma unroll
    for (int p = 0; p < 8; ++p) {
        Gr[p] = P[p] + P[16 + p];
        Gi[p] = P[8 + p] + P[24 + p];
    }
    size_t o = ((size_t)s << 10);
#pragma unroll
    for (int q = 0; q < 8; ++q) {
        int k = 64 + 128 * q;
        float Xr = Gr[0], Xi = Gi[0];
#pragma unroll
        for (int p = 1; p < 8; ++p) {
            float2 w = g_tw[(k * p) & 1023];
            Xr += w.x * Gr[p] - w.y * Gi[p];
            Xi += w.x * Gi[p] + w.y * Gr[p];
        }
        float br = b_real[k], bi = b_imag[k];
        out_real[o + k] = Xr + (br - bi);
        out_imag[o + k] = Xi + (br + bi);
    }
}

// ---------------- main GEMM kernel (radix-8, bulk-copy, persistent) -----------
__global__ void __launch_bounds__(THREADS, 2)
dft_gemm_kernel(const float* __restrict__ b_real, const float* __restrict__ b_imag,
                float* __restrict__ out_real, float* __restrict__ out_imag) {
    extern __shared__ __align__(1024) char sm[];
    uint32_t sb = (uint32_t)__cvta_generic_to_shared(sm);
    const int tid = threadIdx.x, wid = tid >> 5, lid = tid & 31;
    const int tile0 = blockIdx.x * MITER;              // base m-tile (grid.x only)
    const int wm = (wid >> 2) * 32;
    const int wn = (wid & 3) * 16;

    if (tid == 0) {
        mbar_init(sb + MB_B, 1);
        mbar_init(sb + MB_A0, 1);
        mbar_init(sb + MB_A1, 1);
    }
    __syncthreads();
    if (tid == 0) {
        mbar_expect(sb + MB_A0, 16384);
        bulk_g2s(sb + OFF_A,
                 (const char*)g_xr_t + (((size_t)(tile0 * 2 + 0)) << 13), 8192, sb + MB_A0);
        bulk_g2s(sb + OFF_A + 8192,
                 (const char*)g_xi_t + (((size_t)(tile0 * 2 + 0)) << 13), 8192, sb + MB_A0);
        mbar_expect(sb + MB_A1, 16384);
        bulk_g2s(sb + OFF_A + 16384,
                 (const char*)g_xr_t + (((size_t)(tile0 * 2 + 1)) << 13), 8192, sb + MB_A1);
        bulk_g2s(sb + OFF_A + 16384 + 8192,
                 (const char*)g_xi_t + (((size_t)(tile0 * 2 + 1)) << 13), 8192, sb + MB_A1);
        mbar_expect(sb + MB_B, 32768);
#pragma unroll
        for (int c = 0; c < 2; ++c) {
            bulk_g2s(sb + OFF_B + c * 16384,
                     (const char*)g_wr_t + ((size_t)c << 13), 8192, sb + MB_B);
            bulk_g2s(sb + OFF_B + c * 16384 + 8192,
                     (const char*)g_wi_t + ((size_t)c << 13), 8192, sb + MB_B);
        }
    }

    // stage tables (coalesced; overlaps bulk loads)
    float* TB = (float*)(sm + SM_TAB);
    {
        int j = tid & 63, z = tid >> 6;
#pragma unroll
        for (int u = 0; u < 2; ++u) {
            int g8 = z + 4 * u;                        // gr / q index 0..7
            int pp = g8 & 3, ss = g8 >> 2;
            int base = (j * 8 + g8) * 2;
            float2 w = g_tw[((j + 128 * ss) * pp) & 1023];
            TB[T_2D + base] = w.x; TB[T_2D + base + 1] = w.y;
            w = g_tw[(((128 - j) + 128 * ss) * pp) & 1023];
            TB[T_2M + base] = w.x; TB[T_2M + base + 1] = w.y;
            int kd = j + 128 * g8;
            float a = b_real[kd], b = b_imag[kd];
            TB[T_BD + base] = a - b; TB[T_BD + base + 1] = a + b;
            int km = (128 - j + 128 * g8) & 1023;
            a = b_real[km]; b = b_imag[km];
            TB[T_BM + base] = a - b; TB[T_BM + base + 1] = a + b;
        }
        if (z == 0) {
            float2 w = g_tw[(4 * j) & 1023];
            TB[T_S1 + j * 4]     = w.x; TB[T_S1 + j * 4 + 1] = w.y;
            w = g_tw[(512 - 4 * j) & 1023];
            TB[T_S1 + j * 4 + 2] = w.x; TB[T_S1 + j * 4 + 3] = w.y;
        }
    }
    __syncthreads();
    mbar_wait(sb + MB_B, 0);

    float P1[2][2][4], P2[2][2][4], P3[2][2][4], P4[2][2][4];
#pragma unroll
    for (int a = 0; a < 2; ++a)
#pragma unroll
        for (int b = 0; b < 2; ++b)
#pragma unroll
            for (int c = 0; c < 4; ++c) {
                P1[a][b][c] = 0.f; P2[a][b][c] = 0.f;
                P3[a][b][c] = 0.f; P4[a][b][c] = 0.f;
            }

    const int lrow = lid & 15;
    const int lcb  = (lid >> 4) << 4;
    const int gr = lid >> 2, gc = lid & 3;
    const int pq = gr & 3;
    const int qOut = ((pq & 1) << 1) | (pq >> 1);
    const int qLane = (gr >> 2) + 2 * qOut;            // output q of this lane
    const bool b0 = (gr & 1) != 0, b1 = (gr & 2) != 0, b2 = (gr & 4) != 0;

    for (int i = 0; i < NITER; ++i) {
        mbar_wait(sb + MB_A0 + (uint32_t)((i & 1) * 8), (uint32_t)((i >> 1) & 1));
        const uint32_t stA = sb + OFF_A + (i & 1) * 16384;
        const uint32_t stB = sb + OFF_B + (i & 1) * 16384;
#pragma unroll
        for (int kk = 0; kk < 4; ++kk) {
            const uint32_t colb = (uint32_t)(kk * 32 + lcb);
            uint32_t Axr[2][4], Axi[2][4];
#pragma unroll
            for (int mt = 0; mt < 2; ++mt) {
                uint32_t ro = (uint32_t)((wm + mt * 16 + lrow) << 7) + colb;
                ldsm4(Axr[mt], stA + swz(ro));
                ldsm4(Axi[mt], stA + 8192 + swz(ro));
            }
            uint32_t Bwr[4], Bwi[4], t4[4];
            {
                uint32_t ro = (uint32_t)((wn + lrow) << 7) + colb;
                ldsm4(t4, stB + swz(ro));
                Bwr[0] = t4[0]; Bwr[1] = t4[2]; Bwr[2] = t4[1]; Bwr[3] = t4[3];
                ldsm4(t4, stB + 8192 + swz(ro));
                Bwi[0] = t4[0]; Bwi[1] = t4[2]; Bwi[2] = t4[1]; Bwi[3] = t4[3];
            }
#pragma unroll
            for (int mt = 0; mt < 2; ++mt)
#pragma unroll
                for (int nt = 0; nt < 2; ++nt) {
                    const int ob = nt * 2;
                    mma16816(P1[mt][nt], Axr[mt], Bwr[ob], Bwr[ob + 1]);
                    mma16816(P2[mt][nt], Axi[mt], Bwi[ob], Bwi[ob + 1]);
                    mma16816(P3[mt][nt], Axr[mt], Bwi[ob], Bwi[ob + 1]);
                    mma16816(P4[mt][nt], Axi[mt], Bwr[ob], Bwr[ob + 1]);
                }
        }
        __syncthreads();                               // all warps done with stage i&1
        if (i + 2 < NITER && tid == 0) {
            int l = i + 2, tm2 = tile0 + (l >> 1), c2 = l & 1;
            uint32_t mb = sb + MB_A0 + (uint32_t)((i & 1) * 8);
            mbar_expect(mb, 16384);
            bulk_g2s(sb + OFF_A + (i & 1) * 16384,
                     (const char*)g_xr_t + (((size_t)(tm2 * 2 + c2)) << 13), 8192, mb);
            bulk_g2s(sb + OFF_A + (i & 1) * 16384 + 8192,
                     (const char*)g_xi_t + (((size_t)(tm2 * 2 + c2)) << 13), 8192, mb);
        }

        if ((i & 1) == 1) {
            // ---- radix-8 butterfly epilogue for m-tile i>>1 ----
            const int sbase = 8 * (tile0 + (i >> 1)) + (wm >> 3);
#pragma unroll
            for (int nt = 0; nt < 2; ++nt) {
                const int jl = wn + nt * 8 + gc * 2;
                const int iA = (jl * 8 + gr) * 2, iB = ((jl + 1) * 8 + gr) * 2;
                const int jA = (jl * 8 + qLane) * 2, jB = ((jl + 1) * 8 + qLane) * 2;
                const float t2dAr = TB[T_2D + iA], t2dAi = TB[T_2D + iA + 1];
                const float t2dBr = TB[T_2D + iB], t2dBi = TB[T_2D + iB + 1];
                const float t2mAr = TB[T_2M + iA], t2mAi = TB[T_2M + iA + 1];
                const float t2mBr = TB[T_2M + iB], t2mBi = TB[T_2M + iB + 1];
                const float s1dAr = TB[T_S1 + jl * 4],     s1dAi = TB[T_S1 + jl * 4 + 1];
                const float s1mAr = TB[T_S1 + jl * 4 + 2], s1mAi = TB[T_S1 + jl * 4 + 3];
                const float s1dBr = TB[T_S1 + (jl + 1) * 4],     s1dBi = TB[T_S1 + (jl + 1) * 4 + 1];
                const float s1mBr = TB[T_S1 + (jl + 1) * 4 + 2], s1mBi = TB[T_S1 + (jl + 1) * 4 + 3];
                const float bdA0 = TB[T_BD + jA], bdA1 = TB[T_BD + jA + 1];
                const float bdB0 = TB[T_BD + jB], bdB1 = TB[T_BD + jB + 1];
                const float bmA0 = TB[T_BM + jA], bmA1 = TB[T_BM + jA + 1];
                const float bmB0 = TB[T_BM + jB], bmB1 = TB[T_BM + jB + 1];
                const int kd  = jl + 128 * qLane;
                const int kmA = 128 - jl + 128 * qLane;
#pragma unroll
                for (int mt = 0; mt < 2; ++mt)
#pragma unroll
                    for (int rg = 0; rg < 2; ++rg) {
                        const int e0 = rg * 2, e1 = e0 + 1;
                        size_t s = (size_t)(sbase + mt * 2 + rg);
                        float* pr = out_real + (s << 10);
                        float* pi = out_imag + (s << 10);
                        float GdrA = P1[mt][nt][e0] - P2[mt][nt][e0];
                        float GdiA = P3[mt][nt][e0] + P4[mt][nt][e0];
                        float GmrA = P1[mt][nt][e0] + P2[mt][nt][e0];
                        float GmiA = P4[mt][nt][e0] - P3[mt][nt][e0];
                        float GdrB = P1[mt][nt][e1] - P2[mt][nt][e1];
                        float GdiB = P3[mt][nt][e1] + P4[mt][nt][e1];
                        float GmrB = P1[mt][nt][e1] + P2[mt][nt][e1];
                        float GmiB = P4[mt][nt][e1] - P3[mt][nt][e1];
                        float XrA, XiA, XrB, XiB;
                        bfly8(XrA, XiA, GdrA, GdiA, s1dAr, s1dAi, t2dAr, t2dAi, b0, b1, b2);
                        bfly8(XrB, XiB, GdrB, GdiB, s1dBr, s1dBi, t2dBr, t2dBi, b0, b1, b2);
                        float2 v;
                        v.x = XrA + bdA0; v.y = XrB + bdB0;
                        *(float2*)(pr + kd) = v;
                        v.x = XiA + bdA1; v.y = XiB + bdB1;
                        *(float2*)(pi + kd) = v;
                        bfly8(XrA, XiA, GmrA, GmiA, s1mAr, s1mAi, t2mAr, t2mAi, b0, b1, b2);
                        bfly8(XrB, XiB, GmrB, GmiB, s1mBr, s1mBi, t2mBr, t2mBi, b0, b1, b2);
                        pr[kmA - 1] = XrB + bmB0;
                        pi[kmA - 1] = XiB + bmB1;
                        if (jl != 0) {                 // c=0 mirror duplicates direct: skip
                            pr[kmA] = XrA + bmA0;
                            pi[kmA] = XiA + bmA1;
                        }
                    }
            }
            // zero accumulators for next m-tile
#pragma unroll
            for (int a = 0; a < 2; ++a)
#pragma unroll
                for (int b = 0; b < 2; ++b)
#pragma unroll
                    for (int c = 0; c < 4; ++c) {
                        P1[a][b][c] = 0.f; P2[a][b][c] = 0.f;
                        P3[a][b][c] = 0.f; P4[a][b][c] = 0.f;
                    }
        }
    }
}

// ---------------- launch ----------------
extern "C" void kernel_launch(void* const* d_in, const int* in_sizes, int n_in,
                              void* d_out, int out_size) {
    (void)in_sizes; (void)n_in; (void)out_size;
    const float4* xr = (const float4*)d_in[0];
    const float4* xi = (const float4*)d_in[1];
    const float*  wr = (const float*)d_in[2];
    const float*  wi = (const float*)d_in[3];
    const float*  br = (const float*)d_in[4];
    const float*  bi = (const float*)d_in[5];
    float* out_real = (float*)d_out;
    float* out_imag = out_real + (size_t)M_SIG * 1024;

    convert_w_kernel<<<4, 256>>>((const float4*)wr, (const float4*)wi);
    convert_x_kernel<<<8192, 256>>>(xr, xi);
    col64_kernel<<<128, 256>>>(br, bi, out_real, out_imag);

    cudaFuncSetAttribute(dft_gemm_kernel,
                         cudaFuncAttributeMaxDynamicSharedMemorySize, SMEM_TOTAL);
    dim3 grid((MR / BM) / MITER, 1);   // (1024, 1)
    dft_gemm_kernel<<<grid, THREADS, SMEM_TOTAL>>>(br, bi, out_real, out_imag);
}